// round 1
// baseline (speedup 1.0000x reference)
#include <cuda_runtime.h>
#include <math.h>

// Problem constants
#define B_DIM  64
#define T_DIM  256
#define D_DIM  768
#define NH_DIM 12
#define DH_DIM 64
#define C_DIM  7
#define M_ROWS (B_DIM * T_DIM)   // 16384

// ---------------------------------------------------------------------------
// Scratch (device globals; no runtime allocation allowed)
// ---------------------------------------------------------------------------
__device__ float g_Q[(size_t)M_ROWS * D_DIM];    // Q, later reused for c = ctx@Wo
__device__ float g_K[(size_t)M_ROWS * D_DIM];
__device__ float g_V[(size_t)M_ROWS * D_DIM];
__device__ float g_CTX[(size_t)M_ROWS * D_DIM];  // attention output (pre-Wo)

// ---------------------------------------------------------------------------
// Tiled FP32 GEMM:  C[M,N] = A[M,K] @ W[K,N] + bias[N]
// BM=BN=128, BK=8, 256 threads, 8x8 per-thread micro-tile.
// zero_period: if >0, rows with (row % zero_period == 0) are written as 0
//              (used to implement the t==0 "exact zeros" rule after Wo).
// ---------------------------------------------------------------------------
__global__ __launch_bounds__(256)
void sgemm_bias_kernel(const float* __restrict__ A,
                       const float* __restrict__ W,
                       const float* __restrict__ bias,
                       float* __restrict__ C,
                       int M, int N, int K, int zero_period)
{
    const int BM = 128, BN = 128, BK = 8, TM = 8, TN = 8;
    __shared__ float As[BK][BM];
    __shared__ float Bs[BK][BN];

    const int tid = threadIdx.x;                 // 0..255
    const int block_row = blockIdx.y * BM;
    const int block_col = blockIdx.x * BN;
    const int tr = (tid / 16) * TM;              // 0..120
    const int tc = (tid % 16) * TN;              // 0..120

    float acc[TM][TN];
    #pragma unroll
    for (int i = 0; i < TM; i++)
        #pragma unroll
        for (int j = 0; j < TN; j++)
            acc[i][j] = 0.0f;

    // Loader indices
    const int a_r  = tid >> 1;                   // 0..127 (row within A tile)
    const int a_k  = (tid & 1) * 4;              // 0 or 4
    const int b_k  = tid >> 5;                   // 0..7
    const int b_n  = (tid & 31) * 4;             // 0..124

    for (int k0 = 0; k0 < K; k0 += BK) {
        // Load A tile (transposed into smem: As[k][m])
        {
            float4 a4 = *(const float4*)&A[(size_t)(block_row + a_r) * K + (k0 + a_k)];
            As[a_k + 0][a_r] = a4.x;
            As[a_k + 1][a_r] = a4.y;
            As[a_k + 2][a_r] = a4.z;
            As[a_k + 3][a_r] = a4.w;
        }
        // Load W tile (Bs[k][n])
        {
            float4 b4 = *(const float4*)&W[(size_t)(k0 + b_k) * N + (block_col + b_n)];
            *(float4*)&Bs[b_k][b_n] = b4;
        }
        __syncthreads();

        #pragma unroll
        for (int kk = 0; kk < BK; kk++) {
            float areg[TM], breg[TN];
            #pragma unroll
            for (int i = 0; i < TM; i++) areg[i] = As[kk][tr + i];
            #pragma unroll
            for (int j = 0; j < TN; j++) breg[j] = Bs[kk][tc + j];
            #pragma unroll
            for (int i = 0; i < TM; i++)
                #pragma unroll
                for (int j = 0; j < TN; j++)
                    acc[i][j] += areg[i] * breg[j];
        }
        __syncthreads();
    }

    #pragma unroll
    for (int i = 0; i < TM; i++) {
        const int row = block_row + tr + i;
        const bool zero_row = (zero_period > 0) && ((row % zero_period) == 0);
        #pragma unroll
        for (int j = 0; j < TN; j++) {
            const int col = block_col + tc + j;
            float v = acc[i][j] + bias[col];
            if (zero_row) v = 0.0f;
            C[(size_t)row * N + col] = v;
        }
    }
}

// ---------------------------------------------------------------------------
// Attention: one block per (b, h); 256 threads = one query each.
// K/V for (b,h) staged in 128 KB dynamic smem; online softmax per thread.
// Masking: key k valid iff k < min(q, num_turns[b]); q==0 row -> zeros.
// ---------------------------------------------------------------------------
__global__ __launch_bounds__(256)
void attention_kernel(const float* __restrict__ Q,
                      const float* __restrict__ K,
                      const float* __restrict__ V,
                      const int*   __restrict__ num_turns,
                      float*       __restrict__ CTX)
{
    const int b = blockIdx.x / NH_DIM;
    const int h = blockIdx.x % NH_DIM;

    extern __shared__ float smem[];
    float* Ksm = smem;                       // [T][DH]
    float* Vsm = smem + T_DIM * DH_DIM;      // [T][DH]

    // Base offset for (b, t=0, h, 0) in [B,T,NH,DH] layout
    const size_t base = ((size_t)b * T_DIM * NH_DIM + h) * DH_DIM;
    const int row_stride = NH_DIM * DH_DIM;  // 768 floats between consecutive t

    // Cooperative load of K and V (float4 granularity)
    for (int idx = threadIdx.x; idx < T_DIM * (DH_DIM / 4); idx += blockDim.x) {
        const int t  = idx >> 4;             // /16
        const int d4 = idx & 15;
        const size_t g = base + (size_t)t * row_stride + d4 * 4;
        ((float4*)Ksm)[idx] = *(const float4*)&K[g];
        ((float4*)Vsm)[idx] = *(const float4*)&V[g];
    }
    __syncthreads();

    const int q   = threadIdx.x;             // query index (T == blockDim.x)
    const int lim = min(q, num_turns[b]);

    float* out = &CTX[base + (size_t)q * row_stride];

    if (lim <= 0) {
        #pragma unroll
        for (int d = 0; d < DH_DIM; d++) out[d] = 0.0f;
        return;
    }

    // Load & pre-scale query
    const float* qp = &Q[base + (size_t)q * row_stride];
    float qreg[DH_DIM];
    #pragma unroll
    for (int d = 0; d < DH_DIM; d++) qreg[d] = qp[d] * 0.125f;  // 1/sqrt(64)

    float m = -1e30f, l = 0.0f;
    float ctx[DH_DIM];
    #pragma unroll
    for (int d = 0; d < DH_DIM; d++) ctx[d] = 0.0f;

    for (int k = 0; k < lim; k++) {
        const float* kp = &Ksm[k * DH_DIM];
        float s = 0.0f;
        #pragma unroll
        for (int d = 0; d < DH_DIM; d++) s += qreg[d] * kp[d];

        if (s > m) {
            const float corr = __expf(m - s);
            l *= corr;
            #pragma unroll
            for (int d = 0; d < DH_DIM; d++) ctx[d] *= corr;
            m = s;
        }
        const float p = __expf(s - m);
        l += p;
        const float* vp = &Vsm[k * DH_DIM];
        #pragma unroll
        for (int d = 0; d < DH_DIM; d++) ctx[d] += p * vp[d];
    }

    const float inv = 1.0f / l;
    #pragma unroll
    for (int d = 0; d < DH_DIM; d++) out[d] = ctx[d] * inv;
}

// ---------------------------------------------------------------------------
// Classifier: all_logits[b,t,:] = concat(H[b,t], c[b,t]) @ Wc + bc
// One block per b, thread t handles one row; Wc cached in smem (43 KB).
// ---------------------------------------------------------------------------
__global__ __launch_bounds__(256)
void classifier_kernel(const float* __restrict__ H,
                       const float* __restrict__ Cc,    // c (t==0 rows already 0)
                       const float* __restrict__ Wc,    // [2D, C]
                       const float* __restrict__ bc,
                       float* __restrict__ out_all)     // [B,T,C]
{
    __shared__ float Wcs[2 * D_DIM * C_DIM];             // 10752 floats = 43008 B
    const int b = blockIdx.x;

    for (int i = threadIdx.x; i < 2 * D_DIM * C_DIM; i += blockDim.x)
        Wcs[i] = Wc[i];
    __syncthreads();

    const int t = threadIdx.x;
    const float* hrow = &H [((size_t)b * T_DIM + t) * D_DIM];
    const float* crow = &Cc[((size_t)b * T_DIM + t) * D_DIM];

    float acc[C_DIM];
    #pragma unroll
    for (int c = 0; c < C_DIM; c++) acc[c] = bc[c];

    for (int i = 0; i < D_DIM; i += 4) {
        float4 h4 = *(const float4*)&hrow[i];
        const float hv[4] = {h4.x, h4.y, h4.z, h4.w};
        #pragma unroll
        for (int e = 0; e < 4; e++)
            #pragma unroll
            for (int c = 0; c < C_DIM; c++)
                acc[c] += hv[e] * Wcs[(i + e) * C_DIM + c];
    }
    for (int i = 0; i < D_DIM; i += 4) {
        float4 c4 = *(const float4*)&crow[i];
        const float cv[4] = {c4.x, c4.y, c4.z, c4.w};
        #pragma unroll
        for (int e = 0; e < 4; e++)
            #pragma unroll
            for (int c = 0; c < C_DIM; c++)
                acc[c] += cv[e] * Wcs[(D_DIM + i + e) * C_DIM + c];
    }

    float* o = &out_all[((size_t)b * T_DIM + t) * C_DIM];
    #pragma unroll
    for (int c = 0; c < C_DIM; c++) o[c] = acc[c];
}

// ---------------------------------------------------------------------------
// Gather final_logits[b,:] = all_logits[b, num_turns[b]-1, :]
// ---------------------------------------------------------------------------
__global__ void gather_final_kernel(const float* __restrict__ all_logits,
                                    const int*   __restrict__ num_turns,
                                    float*       __restrict__ out_final)
{
    const int b = blockIdx.x;
    const int c = threadIdx.x;   // 0..6
    const int t = num_turns[b] - 1;
    out_final[(size_t)b * C_DIM + c] =
        all_logits[((size_t)b * T_DIM + t) * C_DIM + c];
}

// ---------------------------------------------------------------------------
// Launch
// ---------------------------------------------------------------------------
extern "C" void kernel_launch(void* const* d_in, const int* in_sizes, int n_in,
                              void* d_out, int out_size)
{
    const float* H  = (const float*)d_in[0];
    const float* Wq = (const float*)d_in[1];
    const float* bq = (const float*)d_in[2];
    const float* Wk = (const float*)d_in[3];
    const float* bk = (const float*)d_in[4];
    const float* Wv = (const float*)d_in[5];
    const float* bv = (const float*)d_in[6];
    const float* Wo = (const float*)d_in[7];
    const float* bo = (const float*)d_in[8];
    const float* Wc = (const float*)d_in[9];
    const float* bc = (const float*)d_in[10];
    const int*   nt = (const int*)  d_in[11];

    float* out_all   = (float*)d_out;                          // [B,T,C]
    float* out_final = (float*)d_out + (size_t)B_DIM * T_DIM * C_DIM;

    float *Qb, *Kb, *Vb, *CTXb;
    cudaGetSymbolAddress((void**)&Qb,   g_Q);
    cudaGetSymbolAddress((void**)&Kb,   g_K);
    cudaGetSymbolAddress((void**)&Vb,   g_V);
    cudaGetSymbolAddress((void**)&CTXb, g_CTX);

    const int M = M_ROWS, N = D_DIM, Kd = D_DIM;
    dim3 gemm_grid(N / 128, M / 128);   // (6, 128)
    dim3 gemm_block(256);

    // QKV projections
    sgemm_bias_kernel<<<gemm_grid, gemm_block>>>(H, Wq, bq, Qb, M, N, Kd, 0);
    sgemm_bias_kernel<<<gemm_grid, gemm_block>>>(H, Wk, bk, Kb, M, N, Kd, 0);
    sgemm_bias_kernel<<<gemm_grid, gemm_block>>>(H, Wv, bv, Vb, M, N, Kd, 0);

    // Attention
    const int attn_smem = 2 * T_DIM * DH_DIM * (int)sizeof(float);  // 131072
    cudaFuncSetAttribute(attention_kernel,
                         cudaFuncAttributeMaxDynamicSharedMemorySize, attn_smem);
    attention_kernel<<<B_DIM * NH_DIM, T_DIM, attn_smem>>>(Qb, Kb, Vb, nt, CTXb);

    // Output projection c = ctx @ Wo + bo, with t==0 rows forced to exact 0.
    // Writes into g_Q (Q no longer needed).
    sgemm_bias_kernel<<<gemm_grid, gemm_block>>>(CTXb, Wo, bo, Qb, M, N, Kd, T_DIM);

    // Classifier + gather
    classifier_kernel<<<B_DIM, T_DIM>>>(H, Qb, Wc, bc, out_all);
    gather_final_kernel<<<B_DIM, C_DIM>>>(out_all, nt, out_final);
}

// round 2
// speedup vs baseline: 2.2898x; 2.2898x over previous
#include <cuda_runtime.h>
#include <math.h>
#include <stdint.h>

// Problem constants
#define B_DIM  64
#define T_DIM  256
#define D_DIM  768
#define NH_DIM 12
#define DH_DIM 64
#define C_DIM  7
#define M_ROWS (B_DIM * T_DIM)   // 16384

// ---------------------------------------------------------------------------
// Scratch (device globals; no runtime allocation allowed)
// ---------------------------------------------------------------------------
__device__ float g_Q[(size_t)M_ROWS * D_DIM];    // Q, later reused for c = ctx@Wo
__device__ float g_K[(size_t)M_ROWS * D_DIM];
__device__ float g_V[(size_t)M_ROWS * D_DIM];
__device__ float g_CTX[(size_t)M_ROWS * D_DIM];  // attention output (pre-Wo)

// ---------------------------------------------------------------------------
// TF32 tensor-core GEMM:  C[M,N] = A[M,K] @ W[K,N] + bias[N]
// BM=BN=128, BK=32, 256 threads (8 warps, 4x2), warp tile 32x64,
// mma.sync.m16n8k8.tf32, cp.async double buffering.
// zero_period: rows with (row % zero_period == 0) forced to exact 0.
// ---------------------------------------------------------------------------
#define BM 128
#define BN 128
#define BK 32
#define ASTRIDE 36    // 32 + 4 pad (floats)
#define BSTRIDE 136   // 128 + 8 pad (floats)
#define A_STAGE (BM * ASTRIDE)   // 4608 floats
#define B_STAGE (BK * BSTRIDE)   // 4352 floats
#define GEMM_SMEM_BYTES ((2 * A_STAGE + 2 * B_STAGE) * 4)  // 71680

__device__ __forceinline__ uint32_t f2tf32(float f) {
    uint32_t u;
    asm volatile("cvt.rna.tf32.f32 %0, %1;" : "=r"(u) : "f"(f));
    return u;
}

__device__ __forceinline__ void cp_async16(uint32_t smem_addr, const void* gptr) {
    asm volatile("cp.async.cg.shared.global [%0], [%1], 16;\n"
                 :: "r"(smem_addr), "l"(gptr));
}

__global__ __launch_bounds__(256)
void tf32_gemm_kernel(const float* __restrict__ A,
                      const float* __restrict__ W,
                      const float* __restrict__ bias,
                      float* __restrict__ C,
                      int M, int N, int K, int zero_period)
{
    extern __shared__ float smem[];
    float* As = smem;                    // [2][BM][ASTRIDE]
    float* Bs = smem + 2 * A_STAGE;      // [2][BK][BSTRIDE]

    const int tid  = threadIdx.x;
    const int lane = tid & 31;
    const int warp = tid >> 5;
    const int gid  = lane >> 2;          // 0..7
    const int tig  = lane & 3;           // 0..3
    const int warp_m = (warp & 3) * 32;  // 0,32,64,96
    const int warp_n = (warp >> 2) * 64; // 0,64

    const int block_row = blockIdx.y * BM;
    const int block_col = blockIdx.x * BN;

    const uint32_t smem_base = (uint32_t)__cvta_generic_to_shared(smem);
    const uint32_t As_addr = smem_base;
    const uint32_t Bs_addr = smem_base + 2 * A_STAGE * 4;

    // Loader coordinates (float4 chunks)
    const int a_m  = tid >> 1;              // chunk row for first of 4; pattern below
    // A tile: 128 rows x 8 chunks -> chunk c: m=c/8, k4=c%8
    // B tile: 32 rows x 32 chunks -> chunk c: k=c/32, n4=c%32

    float d[2][8][4];
    #pragma unroll
    for (int mi = 0; mi < 2; mi++)
        #pragma unroll
        for (int ni = 0; ni < 8; ni++)
            #pragma unroll
            for (int e = 0; e < 4; e++)
                d[mi][ni][e] = 0.0f;

    const int NITER = K / BK;   // 24

    // ---- stage-0 prefetch
    {
        const int k0 = 0;
        #pragma unroll
        for (int s = 0; s < 4; s++) {
            int c  = tid + s * 256;
            int m  = c >> 3, k4 = c & 7;
            cp_async16(As_addr + (m * ASTRIDE + k4 * 4) * 4,
                       &A[(size_t)(block_row + m) * K + k0 + k4 * 4]);
        }
        #pragma unroll
        for (int s = 0; s < 4; s++) {
            int c  = tid + s * 256;
            int k  = c >> 5, n4 = c & 31;
            cp_async16(Bs_addr + (k * BSTRIDE + n4 * 4) * 4,
                       &W[(size_t)(k0 + k) * N + block_col + n4 * 4]);
        }
        asm volatile("cp.async.commit_group;\n");
    }

    int buf = 0;
    for (int it = 0; it < NITER; it++) {
        // prefetch next stage
        if (it + 1 < NITER) {
            const int k0 = (it + 1) * BK;
            const int nb = buf ^ 1;
            #pragma unroll
            for (int s = 0; s < 4; s++) {
                int c  = tid + s * 256;
                int m  = c >> 3, k4 = c & 7;
                cp_async16(As_addr + (nb * A_STAGE + m * ASTRIDE + k4 * 4) * 4,
                           &A[(size_t)(block_row + m) * K + k0 + k4 * 4]);
            }
            #pragma unroll
            for (int s = 0; s < 4; s++) {
                int c  = tid + s * 256;
                int k  = c >> 5, n4 = c & 31;
                cp_async16(Bs_addr + (nb * B_STAGE + k * BSTRIDE + n4 * 4) * 4,
                           &W[(size_t)(k0 + k) * N + block_col + n4 * 4]);
            }
            asm volatile("cp.async.commit_group;\n");
            asm volatile("cp.async.wait_group 1;\n");
        } else {
            asm volatile("cp.async.wait_group 0;\n");
        }
        __syncthreads();

        const float* Ab = As + buf * A_STAGE;
        const float* Bb = Bs + buf * B_STAGE;

        #pragma unroll
        for (int ks = 0; ks < 4; ks++) {
            const int k0s = ks * 8;
            uint32_t afr[2][4];
            uint32_t bfr[8][2];
            #pragma unroll
            for (int mi = 0; mi < 2; mi++) {
                const int am = warp_m + mi * 16;
                afr[mi][0] = f2tf32(Ab[(am + gid)     * ASTRIDE + k0s + tig]);
                afr[mi][1] = f2tf32(Ab[(am + gid + 8) * ASTRIDE + k0s + tig]);
                afr[mi][2] = f2tf32(Ab[(am + gid)     * ASTRIDE + k0s + tig + 4]);
                afr[mi][3] = f2tf32(Ab[(am + gid + 8) * ASTRIDE + k0s + tig + 4]);
            }
            #pragma unroll
            for (int ni = 0; ni < 8; ni++) {
                const int bn = warp_n + ni * 8 + gid;
                bfr[ni][0] = f2tf32(Bb[(k0s + tig)     * BSTRIDE + bn]);
                bfr[ni][1] = f2tf32(Bb[(k0s + tig + 4) * BSTRIDE + bn]);
            }
            #pragma unroll
            for (int mi = 0; mi < 2; mi++)
                #pragma unroll
                for (int ni = 0; ni < 8; ni++) {
                    asm volatile(
                        "mma.sync.aligned.m16n8k8.row.col.f32.tf32.tf32.f32 "
                        "{%0,%1,%2,%3}, {%4,%5,%6,%7}, {%8,%9}, {%0,%1,%2,%3};\n"
                        : "+f"(d[mi][ni][0]), "+f"(d[mi][ni][1]),
                          "+f"(d[mi][ni][2]), "+f"(d[mi][ni][3])
                        : "r"(afr[mi][0]), "r"(afr[mi][1]),
                          "r"(afr[mi][2]), "r"(afr[mi][3]),
                          "r"(bfr[ni][0]), "r"(bfr[ni][1]));
                }
        }
        __syncthreads();
        buf ^= 1;
    }

    // ---- epilogue: bias + zero rows + store
    #pragma unroll
    for (int mi = 0; mi < 2; mi++) {
        const int r0 = block_row + warp_m + mi * 16 + gid;
        const int r1 = r0 + 8;
        const bool z0 = (zero_period > 0) && ((r0 % zero_period) == 0);
        const bool z1 = (zero_period > 0) && ((r1 % zero_period) == 0);
        #pragma unroll
        for (int ni = 0; ni < 8; ni++) {
            const int c0 = block_col + warp_n + ni * 8 + 2 * tig;
            const float b0 = bias[c0], b1 = bias[c0 + 1];
            float v00 = d[mi][ni][0] + b0, v01 = d[mi][ni][1] + b1;
            float v10 = d[mi][ni][2] + b0, v11 = d[mi][ni][3] + b1;
            if (z0) { v00 = 0.0f; v01 = 0.0f; }
            if (z1) { v10 = 0.0f; v11 = 0.0f; }
            C[(size_t)r0 * N + c0]     = v00;
            C[(size_t)r0 * N + c0 + 1] = v01;
            C[(size_t)r1 * N + c0]     = v10;
            C[(size_t)r1 * N + c0 + 1] = v11;
        }
    }
}

// ---------------------------------------------------------------------------
// Attention: one block per (b, h); 256 threads = one query each.
// ---------------------------------------------------------------------------
__global__ __launch_bounds__(256)
void attention_kernel(const float* __restrict__ Q,
                      const float* __restrict__ K,
                      const float* __restrict__ V,
                      const int*   __restrict__ num_turns,
                      float*       __restrict__ CTX)
{
    const int b = blockIdx.x / NH_DIM;
    const int h = blockIdx.x % NH_DIM;

    extern __shared__ float smem[];
    float* Ksm = smem;                       // [T][DH]
    float* Vsm = smem + T_DIM * DH_DIM;      // [T][DH]

    const size_t base = ((size_t)b * T_DIM * NH_DIM + h) * DH_DIM;
    const int row_stride = NH_DIM * DH_DIM;  // 768 floats

    for (int idx = threadIdx.x; idx < T_DIM * (DH_DIM / 4); idx += blockDim.x) {
        const int t  = idx >> 4;
        const int d4 = idx & 15;
        const size_t g = base + (size_t)t * row_stride + d4 * 4;
        ((float4*)Ksm)[idx] = *(const float4*)&K[g];
        ((float4*)Vsm)[idx] = *(const float4*)&V[g];
    }
    __syncthreads();

    const int q   = threadIdx.x;
    const int lim = min(q, num_turns[b]);

    float* out = &CTX[base + (size_t)q * row_stride];

    if (lim <= 0) {
        #pragma unroll
        for (int d = 0; d < DH_DIM; d++) out[d] = 0.0f;
        return;
    }

    const float* qp = &Q[base + (size_t)q * row_stride];
    float qreg[DH_DIM];
    #pragma unroll
    for (int d = 0; d < DH_DIM; d++) qreg[d] = qp[d] * 0.125f;

    float m = -1e30f, l = 0.0f;
    float ctx[DH_DIM];
    #pragma unroll
    for (int d = 0; d < DH_DIM; d++) ctx[d] = 0.0f;

    for (int k = 0; k < lim; k++) {
        const float* kp = &Ksm[k * DH_DIM];
        float s = 0.0f;
        #pragma unroll
        for (int d = 0; d < DH_DIM; d++) s += qreg[d] * kp[d];

        if (s > m) {
            const float corr = __expf(m - s);
            l *= corr;
            #pragma unroll
            for (int d = 0; d < DH_DIM; d++) ctx[d] *= corr;
            m = s;
        }
        const float p = __expf(s - m);
        l += p;
        const float* vp = &Vsm[k * DH_DIM];
        #pragma unroll
        for (int d = 0; d < DH_DIM; d++) ctx[d] += p * vp[d];
    }

    const float inv = 1.0f / l;
    #pragma unroll
    for (int d = 0; d < DH_DIM; d++) out[d] = ctx[d] * inv;
}

// ---------------------------------------------------------------------------
// Classifier
// ---------------------------------------------------------------------------
__global__ __launch_bounds__(256)
void classifier_kernel(const float* __restrict__ H,
                       const float* __restrict__ Cc,
                       const float* __restrict__ Wc,
                       const float* __restrict__ bc,
                       float* __restrict__ out_all)
{
    __shared__ float Wcs[2 * D_DIM * C_DIM];
    const int b = blockIdx.x;

    for (int i = threadIdx.x; i < 2 * D_DIM * C_DIM; i += blockDim.x)
        Wcs[i] = Wc[i];
    __syncthreads();

    const int t = threadIdx.x;
    const float* hrow = &H [((size_t)b * T_DIM + t) * D_DIM];
    const float* crow = &Cc[((size_t)b * T_DIM + t) * D_DIM];

    float acc[C_DIM];
    #pragma unroll
    for (int c = 0; c < C_DIM; c++) acc[c] = bc[c];

    for (int i = 0; i < D_DIM; i += 4) {
        float4 h4 = *(const float4*)&hrow[i];
        const float hv[4] = {h4.x, h4.y, h4.z, h4.w};
        #pragma unroll
        for (int e = 0; e < 4; e++)
            #pragma unroll
            for (int c = 0; c < C_DIM; c++)
                acc[c] += hv[e] * Wcs[(i + e) * C_DIM + c];
    }
    for (int i = 0; i < D_DIM; i += 4) {
        float4 c4 = *(const float4*)&crow[i];
        const float cv[4] = {c4.x, c4.y, c4.z, c4.w};
        #pragma unroll
        for (int e = 0; e < 4; e++)
            #pragma unroll
            for (int c = 0; c < C_DIM; c++)
                acc[c] += cv[e] * Wcs[(D_DIM + i + e) * C_DIM + c];
    }

    float* o = &out_all[((size_t)b * T_DIM + t) * C_DIM];
    #pragma unroll
    for (int c = 0; c < C_DIM; c++) o[c] = acc[c];
}

// ---------------------------------------------------------------------------
// Gather final_logits
// ---------------------------------------------------------------------------
__global__ void gather_final_kernel(const float* __restrict__ all_logits,
                                    const int*   __restrict__ num_turns,
                                    float*       __restrict__ out_final)
{
    const int b = blockIdx.x;
    const int c = threadIdx.x;
    const int t = num_turns[b] - 1;
    out_final[(size_t)b * C_DIM + c] =
        all_logits[((size_t)b * T_DIM + t) * C_DIM + c];
}

// ---------------------------------------------------------------------------
// Launch
// ---------------------------------------------------------------------------
extern "C" void kernel_launch(void* const* d_in, const int* in_sizes, int n_in,
                              void* d_out, int out_size)
{
    const float* H  = (const float*)d_in[0];
    const float* Wq = (const float*)d_in[1];
    const float* bq = (const float*)d_in[2];
    const float* Wk = (const float*)d_in[3];
    const float* bk = (const float*)d_in[4];
    const float* Wv = (const float*)d_in[5];
    const float* bv = (const float*)d_in[6];
    const float* Wo = (const float*)d_in[7];
    const float* bo = (const float*)d_in[8];
    const float* Wc = (const float*)d_in[9];
    const float* bc = (const float*)d_in[10];
    const int*   nt = (const int*)  d_in[11];

    float* out_all   = (float*)d_out;
    float* out_final = (float*)d_out + (size_t)B_DIM * T_DIM * C_DIM;

    float *Qb, *Kb, *Vb, *CTXb;
    cudaGetSymbolAddress((void**)&Qb,   g_Q);
    cudaGetSymbolAddress((void**)&Kb,   g_K);
    cudaGetSymbolAddress((void**)&Vb,   g_V);
    cudaGetSymbolAddress((void**)&CTXb, g_CTX);

    const int M = M_ROWS, N = D_DIM, Kd = D_DIM;
    dim3 gemm_grid(N / BN, M / BM);   // (6, 128)
    dim3 gemm_block(256);

    cudaFuncSetAttribute(tf32_gemm_kernel,
                         cudaFuncAttributeMaxDynamicSharedMemorySize, GEMM_SMEM_BYTES);

    // QKV projections (tensor cores, tf32)
    tf32_gemm_kernel<<<gemm_grid, gemm_block, GEMM_SMEM_BYTES>>>(H, Wq, bq, Qb, M, N, Kd, 0);
    tf32_gemm_kernel<<<gemm_grid, gemm_block, GEMM_SMEM_BYTES>>>(H, Wk, bk, Kb, M, N, Kd, 0);
    tf32_gemm_kernel<<<gemm_grid, gemm_block, GEMM_SMEM_BYTES>>>(H, Wv, bv, Vb, M, N, Kd, 0);

    // Attention
    const int attn_smem = 2 * T_DIM * DH_DIM * (int)sizeof(float);  // 131072
    cudaFuncSetAttribute(attention_kernel,
                         cudaFuncAttributeMaxDynamicSharedMemorySize, attn_smem);
    attention_kernel<<<B_DIM * NH_DIM, T_DIM, attn_smem>>>(Qb, Kb, Vb, nt, CTXb);

    // Output projection (t==0 rows zeroed), writes into g_Q
    tf32_gemm_kernel<<<gemm_grid, gemm_block, GEMM_SMEM_BYTES>>>(CTXb, Wo, bo, Qb, M, N, Kd, T_DIM);

    // Classifier + gather
    classifier_kernel<<<B_DIM, T_DIM>>>(H, Qb, Wc, bc, out_all);
    gather_final_kernel<<<B_DIM, C_DIM>>>(out_all, nt, out_final);
}

// round 4
// speedup vs baseline: 2.3379x; 1.0210x over previous
#include <cuda_runtime.h>
#include <math.h>
#include <stdint.h>

// Problem constants
#define B_DIM  64
#define T_DIM  256
#define D_DIM  768
#define NH_DIM 12
#define DH_DIM 64
#define C_DIM  7
#define M_ROWS (B_DIM * T_DIM)   // 16384
#define NQKV   (3 * D_DIM)       // 2304

// ---------------------------------------------------------------------------
// Scratch (device globals; no runtime allocation allowed)
// ---------------------------------------------------------------------------
__device__ float g_Q[(size_t)M_ROWS * D_DIM];    // Q, later reused for c = ctx@Wo
__device__ float g_K[(size_t)M_ROWS * D_DIM];
__device__ float g_V[(size_t)M_ROWS * D_DIM];
__device__ float g_CTX[(size_t)M_ROWS * D_DIM];  // attention output (pre-Wo)
// Two separately-strided regions:
//   [0, D*NQKV)           : Wqkv, row-major [768][2304]   (tf32-rounded)
//   [D*NQKV, D*NQKV+D*D)  : Wo,   row-major [768][768]    (tf32-rounded)
__device__ float g_Wpack[(size_t)D_DIM * (NQKV + D_DIM)];
__device__ float g_bpack[NQKV];                  // bq|bk|bv (raw fp32)

// ---------------------------------------------------------------------------
// Weight pack: round to tf32 (rna) once; pack biases.
// ---------------------------------------------------------------------------
__device__ __forceinline__ float tf32_round(float f) {
    uint32_t u;
    asm volatile("cvt.rna.tf32.f32 %0, %1;" : "=r"(u) : "f"(f));
    return __uint_as_float(u);
}

__global__ __launch_bounds__(256)
void pack_weights_kernel(const float* __restrict__ Wq, const float* __restrict__ Wk,
                         const float* __restrict__ Wv, const float* __restrict__ Wo,
                         const float* __restrict__ bq, const float* __restrict__ bk,
                         const float* __restrict__ bv,
                         float* __restrict__ Wp, float* __restrict__ bp)
{
    const int total_qkv = D_DIM * NQKV;          // stride-2304 region
    const int total_o   = D_DIM * D_DIM;         // stride-768 region
    for (int idx = blockIdx.x * blockDim.x + threadIdx.x;
         idx < total_qkv + total_o; idx += gridDim.x * blockDim.x) {
        if (idx < total_qkv) {
            const int k = idx / NQKV;
            const int j = idx % NQKV;
            float v;
            if (j < D_DIM)          v = Wq[k * D_DIM + j];
            else if (j < 2 * D_DIM) v = Wk[k * D_DIM + (j - D_DIM)];
            else                    v = Wv[k * D_DIM + (j - 2 * D_DIM)];
            Wp[idx] = tf32_round(v);
        } else {
            const int o = idx - total_qkv;
            Wp[idx] = tf32_round(Wo[o]);
        }
        if (idx < NQKV) {
            float bv_;
            if (idx < D_DIM)            bv_ = bq[idx];
            else if (idx < 2 * D_DIM)   bv_ = bk[idx - D_DIM];
            else                        bv_ = bv[idx - 2 * D_DIM];
            bp[idx] = bv_;
        }
    }
}

// ---------------------------------------------------------------------------
// TF32 tensor-core GEMM:  [M,K] @ W[K,N] + bias[N]
// Output routed by column segment of width 768: seg0->C0, seg1->C1, seg2->C2,
// each stored with row stride 768 (BN=128 never straddles a segment).
// B (weights) are pre-rounded to tf32; only A fragments are cvt'd.
// zero_period: rows with (row % zero_period == 0) forced to exact 0.
// ---------------------------------------------------------------------------
#define BM 128
#define BN 128
#define BK 32
#define ASTRIDE 36    // 32 + 4 pad (floats)
#define BSTRIDE 136   // 128 + 8 pad (floats)
#define A_STAGE (BM * ASTRIDE)   // 4608 floats
#define B_STAGE (BK * BSTRIDE)   // 4352 floats
#define GEMM_SMEM_BYTES ((2 * A_STAGE + 2 * B_STAGE) * 4)  // 71680

__device__ __forceinline__ uint32_t f2tf32(float f) {
    uint32_t u;
    asm volatile("cvt.rna.tf32.f32 %0, %1;" : "=r"(u) : "f"(f));
    return u;
}

__device__ __forceinline__ void cp_async16(uint32_t smem_addr, const void* gptr) {
    asm volatile("cp.async.cg.shared.global [%0], [%1], 16;\n"
                 :: "r"(smem_addr), "l"(gptr));
}

__global__ __launch_bounds__(256)
void tf32_gemm_kernel(const float* __restrict__ A,
                      const float* __restrict__ W,
                      const float* __restrict__ bias,
                      float* __restrict__ C0, float* __restrict__ C1,
                      float* __restrict__ C2,
                      int M, int N, int K, int zero_period)
{
    extern __shared__ float smem[];
    float* As = smem;                    // [2][BM][ASTRIDE]
    float* Bs = smem + 2 * A_STAGE;      // [2][BK][BSTRIDE]

    const int tid  = threadIdx.x;
    const int lane = tid & 31;
    const int warp = tid >> 5;
    const int gid  = lane >> 2;          // 0..7
    const int tig  = lane & 3;           // 0..3
    const int warp_m = (warp & 3) * 32;  // 0,32,64,96
    const int warp_n = (warp >> 2) * 64; // 0,64

    const int block_row = blockIdx.y * BM;
    const int block_col = blockIdx.x * BN;

    // Output segment routing
    const int seg = block_col / D_DIM;
    float* Cout = (seg == 0) ? C0 : (seg == 1 ? C1 : C2);
    const int out_col_base = block_col - seg * D_DIM;

    const uint32_t smem_base = (uint32_t)__cvta_generic_to_shared(smem);
    const uint32_t As_addr = smem_base;
    const uint32_t Bs_addr = smem_base + 2 * A_STAGE * 4;

    float d[2][8][4];
    #pragma unroll
    for (int mi = 0; mi < 2; mi++)
        #pragma unroll
        for (int ni = 0; ni < 8; ni++)
            #pragma unroll
            for (int e = 0; e < 4; e++)
                d[mi][ni][e] = 0.0f;

    const int NITER = K / BK;   // 24

    // ---- stage-0 prefetch
    {
        #pragma unroll
        for (int s = 0; s < 4; s++) {
            int c  = tid + s * 256;
            int m  = c >> 3, k4 = c & 7;
            cp_async16(As_addr + (m * ASTRIDE + k4 * 4) * 4,
                       &A[(size_t)(block_row + m) * K + k4 * 4]);
        }
        #pragma unroll
        for (int s = 0; s < 4; s++) {
            int c  = tid + s * 256;
            int k  = c >> 5, n4 = c & 31;
            cp_async16(Bs_addr + (k * BSTRIDE + n4 * 4) * 4,
                       &W[(size_t)k * N + block_col + n4 * 4]);
        }
        asm volatile("cp.async.commit_group;\n");
    }

    int buf = 0;
    for (int it = 0; it < NITER; it++) {
        if (it + 1 < NITER) {
            const int k0 = (it + 1) * BK;
            const int nb = buf ^ 1;
            #pragma unroll
            for (int s = 0; s < 4; s++) {
                int c  = tid + s * 256;
                int m  = c >> 3, k4 = c & 7;
                cp_async16(As_addr + (nb * A_STAGE + m * ASTRIDE + k4 * 4) * 4,
                           &A[(size_t)(block_row + m) * K + k0 + k4 * 4]);
            }
            #pragma unroll
            for (int s = 0; s < 4; s++) {
                int c  = tid + s * 256;
                int k  = c >> 5, n4 = c & 31;
                cp_async16(Bs_addr + (nb * B_STAGE + k * BSTRIDE + n4 * 4) * 4,
                           &W[(size_t)(k0 + k) * N + block_col + n4 * 4]);
            }
            asm volatile("cp.async.commit_group;\n");
            asm volatile("cp.async.wait_group 1;\n");
        } else {
            asm volatile("cp.async.wait_group 0;\n");
        }
        __syncthreads();

        const float* Ab = As + buf * A_STAGE;
        const float* Bb = Bs + buf * B_STAGE;

        #pragma unroll
        for (int ks = 0; ks < 4; ks++) {
            const int k0s = ks * 8;
            uint32_t afr[2][4];
            uint32_t bfr[8][2];
            #pragma unroll
            for (int mi = 0; mi < 2; mi++) {
                const int am = warp_m + mi * 16;
                afr[mi][0] = f2tf32(Ab[(am + gid)     * ASTRIDE + k0s + tig]);
                afr[mi][1] = f2tf32(Ab[(am + gid + 8) * ASTRIDE + k0s + tig]);
                afr[mi][2] = f2tf32(Ab[(am + gid)     * ASTRIDE + k0s + tig + 4]);
                afr[mi][3] = f2tf32(Ab[(am + gid + 8) * ASTRIDE + k0s + tig + 4]);
            }
            #pragma unroll
            for (int ni = 0; ni < 8; ni++) {
                const int bn = warp_n + ni * 8 + gid;
                bfr[ni][0] = __float_as_uint(Bb[(k0s + tig)     * BSTRIDE + bn]);
                bfr[ni][1] = __float_as_uint(Bb[(k0s + tig + 4) * BSTRIDE + bn]);
            }
            #pragma unroll
            for (int mi = 0; mi < 2; mi++)
                #pragma unroll
                for (int ni = 0; ni < 8; ni++) {
                    asm volatile(
                        "mma.sync.aligned.m16n8k8.row.col.f32.tf32.tf32.f32 "
                        "{%0,%1,%2,%3}, {%4,%5,%6,%7}, {%8,%9}, {%0,%1,%2,%3};\n"
                        : "+f"(d[mi][ni][0]), "+f"(d[mi][ni][1]),
                          "+f"(d[mi][ni][2]), "+f"(d[mi][ni][3])
                        : "r"(afr[mi][0]), "r"(afr[mi][1]),
                          "r"(afr[mi][2]), "r"(afr[mi][3]),
                          "r"(bfr[ni][0]), "r"(bfr[ni][1]));
                }
        }
        __syncthreads();
        buf ^= 1;
    }

    // ---- epilogue: bias + zero rows + store (row stride 768)
    #pragma unroll
    for (int mi = 0; mi < 2; mi++) {
        const int r0 = block_row + warp_m + mi * 16 + gid;
        const int r1 = r0 + 8;
        const bool z0 = (zero_period > 0) && ((r0 % zero_period) == 0);
        const bool z1 = (zero_period > 0) && ((r1 % zero_period) == 0);
        #pragma unroll
        for (int ni = 0; ni < 8; ni++) {
            const int cg = block_col + warp_n + ni * 8 + 2 * tig;    // bias index
            const int cl = out_col_base + warp_n + ni * 8 + 2 * tig; // local col
            const float b0 = bias[cg], b1 = bias[cg + 1];
            float v00 = d[mi][ni][0] + b0, v01 = d[mi][ni][1] + b1;
            float v10 = d[mi][ni][2] + b0, v11 = d[mi][ni][3] + b1;
            if (z0) { v00 = 0.0f; v01 = 0.0f; }
            if (z1) { v10 = 0.0f; v11 = 0.0f; }
            Cout[(size_t)r0 * D_DIM + cl]     = v00;
            Cout[(size_t)r0 * D_DIM + cl + 1] = v01;
            Cout[(size_t)r1 * D_DIM + cl]     = v10;
            Cout[(size_t)r1 * D_DIM + cl + 1] = v11;
        }
    }
}

// ---------------------------------------------------------------------------
// Attention, DH-split-2: 512 threads per (b,h) block.
// Thread pair (q, half): each owns 32 of the 64 head dims.
// Partial q.k dot combined via shfl_xor over the PAIR mask only (both lanes
// of a pair share q and thus lim -> they always converge).
// ---------------------------------------------------------------------------
__global__ __launch_bounds__(512)
void attention_kernel(const float* __restrict__ Q,
                      const float* __restrict__ K,
                      const float* __restrict__ V,
                      const int*   __restrict__ num_turns,
                      float*       __restrict__ CTX)
{
    const int b = blockIdx.x / NH_DIM;
    const int h = blockIdx.x % NH_DIM;

    extern __shared__ float smem[];
    float* Ksm = smem;                       // [T][DH]
    float* Vsm = smem + T_DIM * DH_DIM;      // [T][DH]

    const size_t base = ((size_t)b * T_DIM * NH_DIM + h) * DH_DIM;
    const int row_stride = NH_DIM * DH_DIM;  // 768 floats

    for (int idx = threadIdx.x; idx < T_DIM * (DH_DIM / 4); idx += blockDim.x) {
        const int t  = idx >> 4;
        const int d4 = idx & 15;
        const size_t g = base + (size_t)t * row_stride + d4 * 4;
        ((float4*)Ksm)[idx] = *(const float4*)&K[g];
        ((float4*)Vsm)[idx] = *(const float4*)&V[g];
    }
    __syncthreads();

    const int q    = threadIdx.x >> 1;
    const int half = threadIdx.x & 1;
    const int hoff = half * 32;
    const int lim  = min(q, num_turns[b]);

    const int lane = threadIdx.x & 31;
    const unsigned pmask = 0x3u << (lane & ~1);   // 2-lane pair mask

    float* out = &CTX[base + (size_t)q * row_stride + hoff];

    if (lim <= 0) {
        #pragma unroll
        for (int d = 0; d < 32; d++) out[d] = 0.0f;
        return;
    }

    const float* qp = &Q[base + (size_t)q * row_stride + hoff];
    float qreg[32];
    #pragma unroll
    for (int d = 0; d < 32; d++) qreg[d] = qp[d] * 0.125f;   // 1/sqrt(64)

    float m = -1e30f, l = 0.0f;
    float ctx[32];
    #pragma unroll
    for (int d = 0; d < 32; d++) ctx[d] = 0.0f;

    for (int k = 0; k < lim; k++) {
        const float4* kp4 = (const float4*)&Ksm[k * DH_DIM + hoff];
        float s = 0.0f;
        #pragma unroll
        for (int i = 0; i < 8; i++) {
            float4 k4 = kp4[i];
            s += qreg[4*i+0] * k4.x + qreg[4*i+1] * k4.y
               + qreg[4*i+2] * k4.z + qreg[4*i+3] * k4.w;
        }
        s += __shfl_xor_sync(pmask, s, 1);

        if (s > m) {
            const float corr = __expf(m - s);
            l *= corr;
            #pragma unroll
            for (int d = 0; d < 32; d++) ctx[d] *= corr;
            m = s;
        }
        const float p = __expf(s - m);
        l += p;
        const float4* vp4 = (const float4*)&Vsm[k * DH_DIM + hoff];
        #pragma unroll
        for (int i = 0; i < 8; i++) {
            float4 v4 = vp4[i];
            ctx[4*i+0] += p * v4.x; ctx[4*i+1] += p * v4.y;
            ctx[4*i+2] += p * v4.z; ctx[4*i+3] += p * v4.w;
        }
    }

    const float inv = 1.0f / l;
    #pragma unroll
    for (int d = 0; d < 32; d++) out[d] = ctx[d] * inv;
}

// ---------------------------------------------------------------------------
// Classifier
// ---------------------------------------------------------------------------
__global__ __launch_bounds__(256)
void classifier_kernel(const float* __restrict__ H,
                       const float* __restrict__ Cc,
                       const float* __restrict__ Wc,
                       const float* __restrict__ bc,
                       float* __restrict__ out_all)
{
    __shared__ float Wcs[2 * D_DIM * C_DIM];
    const int b = blockIdx.x;

    for (int i = threadIdx.x; i < 2 * D_DIM * C_DIM; i += blockDim.x)
        Wcs[i] = Wc[i];
    __syncthreads();

    const int t = threadIdx.x;
    const float* hrow = &H [((size_t)b * T_DIM + t) * D_DIM];
    const float* crow = &Cc[((size_t)b * T_DIM + t) * D_DIM];

    float acc[C_DIM];
    #pragma unroll
    for (int c = 0; c < C_DIM; c++) acc[c] = bc[c];

    for (int i = 0; i < D_DIM; i += 4) {
        float4 h4 = *(const float4*)&hrow[i];
        const float hv[4] = {h4.x, h4.y, h4.z, h4.w};
        #pragma unroll
        for (int e = 0; e < 4; e++)
            #pragma unroll
            for (int c = 0; c < C_DIM; c++)
                acc[c] += hv[e] * Wcs[(i + e) * C_DIM + c];
    }
    for (int i = 0; i < D_DIM; i += 4) {
        float4 c4 = *(const float4*)&crow[i];
        const float cv[4] = {c4.x, c4.y, c4.z, c4.w};
        #pragma unroll
        for (int e = 0; e < 4; e++)
            #pragma unroll
            for (int c = 0; c < C_DIM; c++)
                acc[c] += cv[e] * Wcs[(D_DIM + i + e) * C_DIM + c];
    }

    float* o = &out_all[((size_t)b * T_DIM + t) * C_DIM];
    #pragma unroll
    for (int c = 0; c < C_DIM; c++) o[c] = acc[c];
}

// ---------------------------------------------------------------------------
// Gather final_logits
// ---------------------------------------------------------------------------
__global__ void gather_final_kernel(const float* __restrict__ all_logits,
                                    const int*   __restrict__ num_turns,
                                    float*       __restrict__ out_final)
{
    const int b = blockIdx.x;
    const int c = threadIdx.x;
    const int t = num_turns[b] - 1;
    out_final[(size_t)b * C_DIM + c] =
        all_logits[((size_t)b * T_DIM + t) * C_DIM + c];
}

// ---------------------------------------------------------------------------
// Launch
// ---------------------------------------------------------------------------
extern "C" void kernel_launch(void* const* d_in, const int* in_sizes, int n_in,
                              void* d_out, int out_size)
{
    const float* H  = (const float*)d_in[0];
    const float* Wq = (const float*)d_in[1];
    const float* bq = (const float*)d_in[2];
    const float* Wk = (const float*)d_in[3];
    const float* bk = (const float*)d_in[4];
    const float* Wv = (const float*)d_in[5];
    const float* bv = (const float*)d_in[6];
    const float* Wo = (const float*)d_in[7];
    const float* bo = (const float*)d_in[8];
    const float* Wc = (const float*)d_in[9];
    const float* bc = (const float*)d_in[10];
    const int*   nt = (const int*)  d_in[11];

    float* out_all   = (float*)d_out;
    float* out_final = (float*)d_out + (size_t)B_DIM * T_DIM * C_DIM;

    float *Qb, *Kb, *Vb, *CTXb, *Wp, *bp;
    cudaGetSymbolAddress((void**)&Qb,   g_Q);
    cudaGetSymbolAddress((void**)&Kb,   g_K);
    cudaGetSymbolAddress((void**)&Vb,   g_V);
    cudaGetSymbolAddress((void**)&CTXb, g_CTX);
    cudaGetSymbolAddress((void**)&Wp,   g_Wpack);
    cudaGetSymbolAddress((void**)&bp,   g_bpack);

    // 1) pack + tf32-round weights
    pack_weights_kernel<<<2304, 256>>>(Wq, Wk, Wv, Wo, bq, bk, bv, Wp, bp);

    cudaFuncSetAttribute(tf32_gemm_kernel,
                         cudaFuncAttributeMaxDynamicSharedMemorySize, GEMM_SMEM_BYTES);

    // 2) fused QKV projection: [16384,768] @ Wqkv[768,2304] (stride 2304)
    {
        dim3 grid(NQKV / BN, M_ROWS / BM);   // (18, 128)
        tf32_gemm_kernel<<<grid, 256, GEMM_SMEM_BYTES>>>(
            H, Wp, bp, Qb, Kb, Vb, M_ROWS, NQKV, D_DIM, 0);
    }

    // 3) attention
    const int attn_smem = 2 * T_DIM * DH_DIM * (int)sizeof(float);  // 131072
    cudaFuncSetAttribute(attention_kernel,
                         cudaFuncAttributeMaxDynamicSharedMemorySize, attn_smem);
    attention_kernel<<<B_DIM * NH_DIM, 512, attn_smem>>>(Qb, Kb, Vb, nt, CTXb);

    // 4) output projection c = ctx @ Wo[768,768] (stride 768), t==0 rows zeroed
    {
        dim3 grid(D_DIM / BN, M_ROWS / BM);  // (6, 128)
        tf32_gemm_kernel<<<grid, 256, GEMM_SMEM_BYTES>>>(
            CTXb, Wp + (size_t)D_DIM * NQKV, bo, Qb, Qb, Qb,
            M_ROWS, D_DIM, D_DIM, T_DIM);
    }

    // 5) classifier + gather
    classifier_kernel<<<B_DIM, T_DIM>>>(H, Qb, Wc, bc, out_all);
    gather_final_kernel<<<B_DIM, C_DIM>>>(out_all, nt, out_final);
}

// round 5
// speedup vs baseline: 3.1666x; 1.3544x over previous
#include <cuda_runtime.h>
#include <math.h>
#include <stdint.h>

// Problem constants
#define B_DIM  64
#define T_DIM  256
#define D_DIM  768
#define NH_DIM 12
#define DH_DIM 64
#define C_DIM  7
#define M_ROWS (B_DIM * T_DIM)   // 16384
#define NQKV   (3 * D_DIM)       // 2304

// ---------------------------------------------------------------------------
// Scratch (device globals; no runtime allocation allowed)
// ---------------------------------------------------------------------------
__device__ float g_Q[(size_t)M_ROWS * D_DIM];    // Q, later reused for c = ctx@Wo
__device__ float g_K[(size_t)M_ROWS * D_DIM];
__device__ float g_V[(size_t)M_ROWS * D_DIM];
__device__ float g_CTX[(size_t)M_ROWS * D_DIM];  // attention output (pre-Wo)
// Two separately-strided regions:
//   [0, D*NQKV)           : Wqkv, row-major [768][2304]   (tf32-rounded)
//   [D*NQKV, D*NQKV+D*D)  : Wo,   row-major [768][768]    (tf32-rounded)
__device__ float g_Wpack[(size_t)D_DIM * (NQKV + D_DIM)];
__device__ float g_bpack[NQKV];                  // bq|bk|bv (raw fp32)

// ---------------------------------------------------------------------------
__device__ __forceinline__ float tf32_round(float f) {
    uint32_t u;
    asm volatile("cvt.rna.tf32.f32 %0, %1;" : "=r"(u) : "f"(f));
    return __uint_as_float(u);
}

__global__ __launch_bounds__(256)
void pack_weights_kernel(const float* __restrict__ Wq, const float* __restrict__ Wk,
                         const float* __restrict__ Wv, const float* __restrict__ Wo,
                         const float* __restrict__ bq, const float* __restrict__ bk,
                         const float* __restrict__ bv,
                         float* __restrict__ Wp, float* __restrict__ bp)
{
    const int total_qkv = D_DIM * NQKV;
    const int total_o   = D_DIM * D_DIM;
    for (int idx = blockIdx.x * blockDim.x + threadIdx.x;
         idx < total_qkv + total_o; idx += gridDim.x * blockDim.x) {
        if (idx < total_qkv) {
            const int k = idx / NQKV;
            const int j = idx % NQKV;
            float v;
            if (j < D_DIM)          v = Wq[k * D_DIM + j];
            else if (j < 2 * D_DIM) v = Wk[k * D_DIM + (j - D_DIM)];
            else                    v = Wv[k * D_DIM + (j - 2 * D_DIM)];
            Wp[idx] = tf32_round(v);
        } else {
            const int o = idx - total_qkv;
            Wp[idx] = tf32_round(Wo[o]);
        }
        if (idx < NQKV) {
            float bv_;
            if (idx < D_DIM)            bv_ = bq[idx];
            else if (idx < 2 * D_DIM)   bv_ = bk[idx - D_DIM];
            else                        bv_ = bv[idx - 2 * D_DIM];
            bp[idx] = bv_;
        }
    }
}

// ---------------------------------------------------------------------------
// TF32 tensor-core GEMM (proven in round 4) — unchanged.
// ---------------------------------------------------------------------------
#define BM 128
#define BN 128
#define BK 32
#define ASTRIDE 36
#define BSTRIDE 136
#define A_STAGE (BM * ASTRIDE)
#define B_STAGE (BK * BSTRIDE)
#define GEMM_SMEM_BYTES ((2 * A_STAGE + 2 * B_STAGE) * 4)  // 71680

__device__ __forceinline__ uint32_t f2tf32(float f) {
    uint32_t u;
    asm volatile("cvt.rna.tf32.f32 %0, %1;" : "=r"(u) : "f"(f));
    return u;
}

__device__ __forceinline__ void cp_async16(uint32_t smem_addr, const void* gptr) {
    asm volatile("cp.async.cg.shared.global [%0], [%1], 16;\n"
                 :: "r"(smem_addr), "l"(gptr));
}

__device__ __forceinline__ void mma_tf32(float* d, uint32_t a0, uint32_t a1,
                                         uint32_t a2, uint32_t a3,
                                         uint32_t b0, uint32_t b1)
{
    asm volatile(
        "mma.sync.aligned.m16n8k8.row.col.f32.tf32.tf32.f32 "
        "{%0,%1,%2,%3}, {%4,%5,%6,%7}, {%8,%9}, {%0,%1,%2,%3};\n"
        : "+f"(d[0]), "+f"(d[1]), "+f"(d[2]), "+f"(d[3])
        : "r"(a0), "r"(a1), "r"(a2), "r"(a3), "r"(b0), "r"(b1));
}

__global__ __launch_bounds__(256)
void tf32_gemm_kernel(const float* __restrict__ A,
                      const float* __restrict__ W,
                      const float* __restrict__ bias,
                      float* __restrict__ C0, float* __restrict__ C1,
                      float* __restrict__ C2,
                      int M, int N, int K, int zero_period)
{
    extern __shared__ float smem[];
    float* As = smem;
    float* Bs = smem + 2 * A_STAGE;

    const int tid  = threadIdx.x;
    const int lane = tid & 31;
    const int warp = tid >> 5;
    const int gid  = lane >> 2;
    const int tig  = lane & 3;
    const int warp_m = (warp & 3) * 32;
    const int warp_n = (warp >> 2) * 64;

    const int block_row = blockIdx.y * BM;
    const int block_col = blockIdx.x * BN;

    const int seg = block_col / D_DIM;
    float* Cout = (seg == 0) ? C0 : (seg == 1 ? C1 : C2);
    const int out_col_base = block_col - seg * D_DIM;

    const uint32_t smem_base = (uint32_t)__cvta_generic_to_shared(smem);
    const uint32_t As_addr = smem_base;
    const uint32_t Bs_addr = smem_base + 2 * A_STAGE * 4;

    float d[2][8][4];
    #pragma unroll
    for (int mi = 0; mi < 2; mi++)
        #pragma unroll
        for (int ni = 0; ni < 8; ni++)
            #pragma unroll
            for (int e = 0; e < 4; e++)
                d[mi][ni][e] = 0.0f;

    const int NITER = K / BK;

    {
        #pragma unroll
        for (int s = 0; s < 4; s++) {
            int c  = tid + s * 256;
            int m  = c >> 3, k4 = c & 7;
            cp_async16(As_addr + (m * ASTRIDE + k4 * 4) * 4,
                       &A[(size_t)(block_row + m) * K + k4 * 4]);
        }
        #pragma unroll
        for (int s = 0; s < 4; s++) {
            int c  = tid + s * 256;
            int k  = c >> 5, n4 = c & 31;
            cp_async16(Bs_addr + (k * BSTRIDE + n4 * 4) * 4,
                       &W[(size_t)k * N + block_col + n4 * 4]);
        }
        asm volatile("cp.async.commit_group;\n");
    }

    int buf = 0;
    for (int it = 0; it < NITER; it++) {
        if (it + 1 < NITER) {
            const int k0 = (it + 1) * BK;
            const int nb = buf ^ 1;
            #pragma unroll
            for (int s = 0; s < 4; s++) {
                int c  = tid + s * 256;
                int m  = c >> 3, k4 = c & 7;
                cp_async16(As_addr + (nb * A_STAGE + m * ASTRIDE + k4 * 4) * 4,
                           &A[(size_t)(block_row + m) * K + k0 + k4 * 4]);
            }
            #pragma unroll
            for (int s = 0; s < 4; s++) {
                int c  = tid + s * 256;
                int k  = c >> 5, n4 = c & 31;
                cp_async16(Bs_addr + (nb * B_STAGE + k * BSTRIDE + n4 * 4) * 4,
                           &W[(size_t)(k0 + k) * N + block_col + n4 * 4]);
            }
            asm volatile("cp.async.commit_group;\n");
            asm volatile("cp.async.wait_group 1;\n");
        } else {
            asm volatile("cp.async.wait_group 0;\n");
        }
        __syncthreads();

        const float* Ab = As + buf * A_STAGE;
        const float* Bb = Bs + buf * B_STAGE;

        #pragma unroll
        for (int ks = 0; ks < 4; ks++) {
            const int k0s = ks * 8;
            uint32_t afr[2][4];
            uint32_t bfr[8][2];
            #pragma unroll
            for (int mi = 0; mi < 2; mi++) {
                const int am = warp_m + mi * 16;
                afr[mi][0] = f2tf32(Ab[(am + gid)     * ASTRIDE + k0s + tig]);
                afr[mi][1] = f2tf32(Ab[(am + gid + 8) * ASTRIDE + k0s + tig]);
                afr[mi][2] = f2tf32(Ab[(am + gid)     * ASTRIDE + k0s + tig + 4]);
                afr[mi][3] = f2tf32(Ab[(am + gid + 8) * ASTRIDE + k0s + tig + 4]);
            }
            #pragma unroll
            for (int ni = 0; ni < 8; ni++) {
                const int bn = warp_n + ni * 8 + gid;
                bfr[ni][0] = __float_as_uint(Bb[(k0s + tig)     * BSTRIDE + bn]);
                bfr[ni][1] = __float_as_uint(Bb[(k0s + tig + 4) * BSTRIDE + bn]);
            }
            #pragma unroll
            for (int mi = 0; mi < 2; mi++)
                #pragma unroll
                for (int ni = 0; ni < 8; ni++)
                    mma_tf32(d[mi][ni], afr[mi][0], afr[mi][1], afr[mi][2],
                             afr[mi][3], bfr[ni][0], bfr[ni][1]);
        }
        __syncthreads();
        buf ^= 1;
    }

    #pragma unroll
    for (int mi = 0; mi < 2; mi++) {
        const int r0 = block_row + warp_m + mi * 16 + gid;
        const int r1 = r0 + 8;
        const bool z0 = (zero_period > 0) && ((r0 % zero_period) == 0);
        const bool z1 = (zero_period > 0) && ((r1 % zero_period) == 0);
        #pragma unroll
        for (int ni = 0; ni < 8; ni++) {
            const int cg = block_col + warp_n + ni * 8 + 2 * tig;
            const int cl = out_col_base + warp_n + ni * 8 + 2 * tig;
            const float b0 = bias[cg], b1 = bias[cg + 1];
            float v00 = d[mi][ni][0] + b0, v01 = d[mi][ni][1] + b1;
            float v10 = d[mi][ni][2] + b0, v11 = d[mi][ni][3] + b1;
            if (z0) { v00 = 0.0f; v01 = 0.0f; }
            if (z1) { v10 = 0.0f; v11 = 0.0f; }
            Cout[(size_t)r0 * D_DIM + cl]     = v00;
            Cout[(size_t)r0 * D_DIM + cl + 1] = v01;
            Cout[(size_t)r1 * D_DIM + cl]     = v10;
            Cout[(size_t)r1 * D_DIM + cl + 1] = v11;
        }
    }
}

// ---------------------------------------------------------------------------
// MMA flash-attention: one CTA per (b,h), 512 threads = 16 warps.
// Warp w owns queries [16w, 16w+16). K/V/Q staged in smem (tf32-rounded,
// Q pre-scaled by 1/8). S = Q K^T and ctx += P V via m16n8k8 tf32.
// Online softmax on register tiles; causal chunk-skip per warp.
// smem strides chosen for conflict-free fragment loads:
//   Qs,Ks stride 68  (bank = 4*gid + tig, all distinct)
//   Vs stride 72     (bank = 8*tig + gid, all distinct)
// ---------------------------------------------------------------------------
#define QSTRIDE 68
#define KSTRIDE 68
#define VSTRIDE 72
#define ATT_SMEM_FLOATS (T_DIM * (QSTRIDE + KSTRIDE + VSTRIDE))
#define ATT_SMEM_BYTES  (ATT_SMEM_FLOATS * 4)   // 212992

__global__ __launch_bounds__(512)
void flash_attn_kernel(const float* __restrict__ Q,
                       const float* __restrict__ K,
                       const float* __restrict__ V,
                       const int*   __restrict__ num_turns,
                       float*       __restrict__ CTX)
{
    const int b = blockIdx.x / NH_DIM;
    const int h = blockIdx.x % NH_DIM;

    extern __shared__ float sm[];
    float* Qs = sm;
    float* Ks = Qs + T_DIM * QSTRIDE;
    float* Vs = Ks + T_DIM * KSTRIDE;

    const size_t base = ((size_t)b * T_DIM * NH_DIM + h) * DH_DIM;
    const int tid = threadIdx.x;

    // ---- stage Q (scaled), K, V; cvt to tf32
    for (int idx = tid; idx < T_DIM * (DH_DIM / 4); idx += 512) {
        const int t  = idx >> 4;
        const int c4 = (idx & 15) * 4;
        const size_t g = base + (size_t)t * D_DIM + c4;
        float4 q4 = *(const float4*)&Q[g];
        float4 k4 = *(const float4*)&K[g];
        float4 v4 = *(const float4*)&V[g];
        q4.x = tf32_round(q4.x * 0.125f); q4.y = tf32_round(q4.y * 0.125f);
        q4.z = tf32_round(q4.z * 0.125f); q4.w = tf32_round(q4.w * 0.125f);
        k4.x = tf32_round(k4.x); k4.y = tf32_round(k4.y);
        k4.z = tf32_round(k4.z); k4.w = tf32_round(k4.w);
        v4.x = tf32_round(v4.x); v4.y = tf32_round(v4.y);
        v4.z = tf32_round(v4.z); v4.w = tf32_round(v4.w);
        *(float4*)&Qs[t * QSTRIDE + c4] = q4;
        *(float4*)&Ks[t * KSTRIDE + c4] = k4;
        *(float4*)&Vs[t * VSTRIDE + c4] = v4;
    }
    __syncthreads();

    const int warp = tid >> 5;
    const int lane = tid & 31;
    const int gid  = lane >> 2;
    const int tig  = lane & 3;

    const int q0 = warp * 16 + gid;     // rows for c0/c1
    const int q1 = q0 + 8;              // rows for c2/c3
    const int ntv  = num_turns[b];
    const int lim0 = min(q0, ntv);
    const int lim1 = min(q1, ntv);

    // causal chunk skip: max key index needed in this warp
    const int lim_max = min(warp * 16 + 15, ntv);
    const int nch = (lim_max + 63) >> 6;   // >= 1

    float octx[8][4];
    #pragma unroll
    for (int i = 0; i < 8; i++)
        #pragma unroll
        for (int j = 0; j < 4; j++) octx[i][j] = 0.0f;
    float m0 = -1e30f, m1 = -1e30f, l0 = 0.0f, l1 = 0.0f;

    for (int ch = 0; ch < nch; ch++) {
        const int kbase = ch * 64;

        // ---- S = Q Kchunk^T
        float s[8][4];
        #pragma unroll
        for (int i = 0; i < 8; i++)
            #pragma unroll
            for (int j = 0; j < 4; j++) s[i][j] = 0.0f;

        #pragma unroll
        for (int kt = 0; kt < 8; kt++) {
            const int dh = kt * 8;
            const uint32_t a0 = __float_as_uint(Qs[q0 * QSTRIDE + dh + tig]);
            const uint32_t a1 = __float_as_uint(Qs[q1 * QSTRIDE + dh + tig]);
            const uint32_t a2 = __float_as_uint(Qs[q0 * QSTRIDE + dh + tig + 4]);
            const uint32_t a3 = __float_as_uint(Qs[q1 * QSTRIDE + dh + tig + 4]);
            #pragma unroll
            for (int nt8 = 0; nt8 < 8; nt8++) {
                const int krow = kbase + nt8 * 8 + gid;
                const uint32_t b0 = __float_as_uint(Ks[krow * KSTRIDE + dh + tig]);
                const uint32_t b1 = __float_as_uint(Ks[krow * KSTRIDE + dh + tig + 4]);
                mma_tf32(s[nt8], a0, a1, a2, a3, b0, b1);
            }
        }

        // ---- mask + row max
        float mx0 = -1e30f, mx1 = -1e30f;
        #pragma unroll
        for (int i = 0; i < 8; i++) {
            const int kc = kbase + i * 8 + 2 * tig;
            s[i][0] = (kc     < lim0) ? s[i][0] : -1e30f;
            s[i][1] = (kc + 1 < lim0) ? s[i][1] : -1e30f;
            s[i][2] = (kc     < lim1) ? s[i][2] : -1e30f;
            s[i][3] = (kc + 1 < lim1) ? s[i][3] : -1e30f;
            mx0 = fmaxf(mx0, fmaxf(s[i][0], s[i][1]));
            mx1 = fmaxf(mx1, fmaxf(s[i][2], s[i][3]));
        }
        mx0 = fmaxf(mx0, __shfl_xor_sync(0xFFFFFFFFu, mx0, 1));
        mx0 = fmaxf(mx0, __shfl_xor_sync(0xFFFFFFFFu, mx0, 2));
        mx1 = fmaxf(mx1, __shfl_xor_sync(0xFFFFFFFFu, mx1, 1));
        mx1 = fmaxf(mx1, __shfl_xor_sync(0xFFFFFFFFu, mx1, 2));

        const float nm0 = fmaxf(m0, mx0);
        const float nm1 = fmaxf(m1, mx1);
        const float corr0 = __expf(m0 - nm0);
        const float corr1 = __expf(m1 - nm1);
        m0 = nm0; m1 = nm1;
        l0 *= corr0; l1 *= corr1;
        #pragma unroll
        for (int i = 0; i < 8; i++) {
            octx[i][0] *= corr0; octx[i][1] *= corr0;
            octx[i][2] *= corr1; octx[i][3] *= corr1;
        }

        // ---- P = exp(S - m), accumulate l, round to tf32
        #pragma unroll
        for (int i = 0; i < 8; i++) {
            const float p0 = __expf(s[i][0] - m0);
            const float p1 = __expf(s[i][1] - m0);
            const float p2 = __expf(s[i][2] - m1);
            const float p3 = __expf(s[i][3] - m1);
            l0 += p0 + p1;  l1 += p2 + p3;
            s[i][0] = tf32_round(p0); s[i][1] = tf32_round(p1);
            s[i][2] = tf32_round(p2); s[i][3] = tf32_round(p3);
        }

        // ---- ctx += P @ Vchunk
        const int qb = lane & ~3;             // quad base lane
        const int src  = qb | (tig >> 1);
        const int src2 = src + 2;
        const bool par = (tig & 1) != 0;
        #pragma unroll
        for (int kt = 0; kt < 8; kt++) {
            // permute accum layout (cols 2t,2t+1) -> A layout (cols t, t+4)
            const float v00 = __shfl_sync(0xFFFFFFFFu, s[kt][0], src);
            const float v01 = __shfl_sync(0xFFFFFFFFu, s[kt][1], src);
            const float v10 = __shfl_sync(0xFFFFFFFFu, s[kt][2], src);
            const float v11 = __shfl_sync(0xFFFFFFFFu, s[kt][3], src);
            const float w00 = __shfl_sync(0xFFFFFFFFu, s[kt][0], src2);
            const float w01 = __shfl_sync(0xFFFFFFFFu, s[kt][1], src2);
            const float w10 = __shfl_sync(0xFFFFFFFFu, s[kt][2], src2);
            const float w11 = __shfl_sync(0xFFFFFFFFu, s[kt][3], src2);
            const uint32_t a0 = __float_as_uint(par ? v01 : v00);
            const uint32_t a1 = __float_as_uint(par ? v11 : v10);
            const uint32_t a2 = __float_as_uint(par ? w01 : w00);
            const uint32_t a3 = __float_as_uint(par ? w11 : w10);
            const int vr0 = kbase + kt * 8 + tig;
            #pragma unroll
            for (int ndh = 0; ndh < 8; ndh++) {
                const uint32_t b0 = __float_as_uint(Vs[vr0 * VSTRIDE + ndh * 8 + gid]);
                const uint32_t b1 = __float_as_uint(Vs[(vr0 + 4) * VSTRIDE + ndh * 8 + gid]);
                mma_tf32(octx[ndh], a0, a1, a2, a3, b0, b1);
            }
        }
    }

    // ---- finalize: reduce l across quad, normalize, store
    l0 += __shfl_xor_sync(0xFFFFFFFFu, l0, 1);
    l0 += __shfl_xor_sync(0xFFFFFFFFu, l0, 2);
    l1 += __shfl_xor_sync(0xFFFFFFFFu, l1, 1);
    l1 += __shfl_xor_sync(0xFFFFFFFFu, l1, 2);
    const float inv0 = (lim0 > 0) ? 1.0f / l0 : 0.0f;
    const float inv1 = (lim1 > 0) ? 1.0f / l1 : 0.0f;

    float* o0 = &CTX[base + (size_t)q0 * D_DIM];
    float* o1 = &CTX[base + (size_t)q1 * D_DIM];
    #pragma unroll
    for (int ndh = 0; ndh < 8; ndh++) {
        const int c = ndh * 8 + 2 * tig;
        float2 r0 = make_float2(octx[ndh][0] * inv0, octx[ndh][1] * inv0);
        float2 r1 = make_float2(octx[ndh][2] * inv1, octx[ndh][3] * inv1);
        *(float2*)&o0[c] = r0;
        *(float2*)&o1[c] = r1;
    }
}

// ---------------------------------------------------------------------------
// Classifier
// ---------------------------------------------------------------------------
__global__ __launch_bounds__(256)
void classifier_kernel(const float* __restrict__ H,
                       const float* __restrict__ Cc,
                       const float* __restrict__ Wc,
                       const float* __restrict__ bc,
                       float* __restrict__ out_all)
{
    __shared__ float Wcs[2 * D_DIM * C_DIM];
    const int b = blockIdx.x;

    for (int i = threadIdx.x; i < 2 * D_DIM * C_DIM; i += blockDim.x)
        Wcs[i] = Wc[i];
    __syncthreads();

    const int t = threadIdx.x;
    const float* hrow = &H [((size_t)b * T_DIM + t) * D_DIM];
    const float* crow = &Cc[((size_t)b * T_DIM + t) * D_DIM];

    float acc[C_DIM];
    #pragma unroll
    for (int c = 0; c < C_DIM; c++) acc[c] = bc[c];

    for (int i = 0; i < D_DIM; i += 4) {
        float4 h4 = *(const float4*)&hrow[i];
        const float hv[4] = {h4.x, h4.y, h4.z, h4.w};
        #pragma unroll
        for (int e = 0; e < 4; e++)
            #pragma unroll
            for (int c = 0; c < C_DIM; c++)
                acc[c] += hv[e] * Wcs[(i + e) * C_DIM + c];
    }
    for (int i = 0; i < D_DIM; i += 4) {
        float4 c4 = *(const float4*)&crow[i];
        const float cv[4] = {c4.x, c4.y, c4.z, c4.w};
        #pragma unroll
        for (int e = 0; e < 4; e++)
            #pragma unroll
            for (int c = 0; c < C_DIM; c++)
                acc[c] += cv[e] * Wcs[(D_DIM + i + e) * C_DIM + c];
    }

    float* o = &out_all[((size_t)b * T_DIM + t) * C_DIM];
    #pragma unroll
    for (int c = 0; c < C_DIM; c++) o[c] = acc[c];
}

// ---------------------------------------------------------------------------
__global__ void gather_final_kernel(const float* __restrict__ all_logits,
                                    const int*   __restrict__ num_turns,
                                    float*       __restrict__ out_final)
{
    const int b = blockIdx.x;
    const int c = threadIdx.x;
    const int t = num_turns[b] - 1;
    out_final[(size_t)b * C_DIM + c] =
        all_logits[((size_t)b * T_DIM + t) * C_DIM + c];
}

// ---------------------------------------------------------------------------
// Launch
// ---------------------------------------------------------------------------
extern "C" void kernel_launch(void* const* d_in, const int* in_sizes, int n_in,
                              void* d_out, int out_size)
{
    const float* H  = (const float*)d_in[0];
    const float* Wq = (const float*)d_in[1];
    const float* bq = (const float*)d_in[2];
    const float* Wk = (const float*)d_in[3];
    const float* bk = (const float*)d_in[4];
    const float* Wv = (const float*)d_in[5];
    const float* bv = (const float*)d_in[6];
    const float* Wo = (const float*)d_in[7];
    const float* bo = (const float*)d_in[8];
    const float* Wc = (const float*)d_in[9];
    const float* bc = (const float*)d_in[10];
    const int*   nt = (const int*)  d_in[11];

    float* out_all   = (float*)d_out;
    float* out_final = (float*)d_out + (size_t)B_DIM * T_DIM * C_DIM;

    float *Qb, *Kb, *Vb, *CTXb, *Wp, *bp;
    cudaGetSymbolAddress((void**)&Qb,   g_Q);
    cudaGetSymbolAddress((void**)&Kb,   g_K);
    cudaGetSymbolAddress((void**)&Vb,   g_V);
    cudaGetSymbolAddress((void**)&CTXb, g_CTX);
    cudaGetSymbolAddress((void**)&Wp,   g_Wpack);
    cudaGetSymbolAddress((void**)&bp,   g_bpack);

    // 1) pack + tf32-round weights
    pack_weights_kernel<<<2304, 256>>>(Wq, Wk, Wv, Wo, bq, bk, bv, Wp, bp);

    cudaFuncSetAttribute(tf32_gemm_kernel,
                         cudaFuncAttributeMaxDynamicSharedMemorySize, GEMM_SMEM_BYTES);

    // 2) fused QKV projection: [16384,768] @ Wqkv[768,2304]
    {
        dim3 grid(NQKV / BN, M_ROWS / BM);
        tf32_gemm_kernel<<<grid, 256, GEMM_SMEM_BYTES>>>(
            H, Wp, bp, Qb, Kb, Vb, M_ROWS, NQKV, D_DIM, 0);
    }

    // 3) MMA flash attention
    cudaFuncSetAttribute(flash_attn_kernel,
                         cudaFuncAttributeMaxDynamicSharedMemorySize, ATT_SMEM_BYTES);
    flash_attn_kernel<<<B_DIM * NH_DIM, 512, ATT_SMEM_BYTES>>>(Qb, Kb, Vb, nt, CTXb);

    // 4) output projection c = ctx @ Wo[768,768], t==0 rows zeroed -> g_Q
    {
        dim3 grid(D_DIM / BN, M_ROWS / BM);
        tf32_gemm_kernel<<<grid, 256, GEMM_SMEM_BYTES>>>(
            CTXb, Wp + (size_t)D_DIM * NQKV, bo, Qb, Qb, Qb,
            M_ROWS, D_DIM, D_DIM, T_DIM);
    }

    // 5) classifier + gather
    classifier_kernel<<<B_DIM, T_DIM>>>(H, Qb, Wc, bc, out_all);
    gather_final_kernel<<<B_DIM, C_DIM>>>(out_all, nt, out_final);
}

// round 6
// speedup vs baseline: 3.8960x; 1.2304x over previous
#include <cuda_runtime.h>
#include <math.h>
#include <stdint.h>

// Problem constants
#define B_DIM  64
#define T_DIM  256
#define D_DIM  768
#define NH_DIM 12
#define DH_DIM 64
#define C_DIM  7
#define M_ROWS (B_DIM * T_DIM)   // 16384
#define NQKV   (3 * D_DIM)       // 2304

// ---------------------------------------------------------------------------
// Scratch (device globals; no runtime allocation allowed)
// ---------------------------------------------------------------------------
__device__ float g_Q[(size_t)M_ROWS * D_DIM];
__device__ float g_K[(size_t)M_ROWS * D_DIM];
__device__ float g_V[(size_t)M_ROWS * D_DIM];
__device__ float g_CTX[(size_t)M_ROWS * D_DIM];  // attention output (pre-Wo)
__device__ float g_Wpack[(size_t)D_DIM * NQKV];  // tf32-rounded Wqkv [768][2304]
__device__ float g_bpack[NQKV];                  // bq|bk|bv
__device__ float g_WoWc[D_DIM * C_DIM];          // Wo @ Wc_bot  [768][7]
__device__ float g_boWc[C_DIM];                  // bo @ Wc_bot  [7]

// ---------------------------------------------------------------------------
__device__ __forceinline__ float tf32_round(float f) {
    uint32_t u;
    asm volatile("cvt.rna.tf32.f32 %0, %1;" : "=r"(u) : "f"(f));
    return __uint_as_float(u);
}

__global__ __launch_bounds__(256)
void pack_weights_kernel(const float* __restrict__ Wq, const float* __restrict__ Wk,
                         const float* __restrict__ Wv,
                         const float* __restrict__ bq, const float* __restrict__ bk,
                         const float* __restrict__ bv,
                         float* __restrict__ Wp, float* __restrict__ bp)
{
    const int total_qkv = D_DIM * NQKV;
    for (int idx = blockIdx.x * blockDim.x + threadIdx.x;
         idx < total_qkv; idx += gridDim.x * blockDim.x) {
        const int k = idx / NQKV;
        const int j = idx % NQKV;
        float v;
        if (j < D_DIM)          v = Wq[k * D_DIM + j];
        else if (j < 2 * D_DIM) v = Wk[k * D_DIM + (j - D_DIM)];
        else                    v = Wv[k * D_DIM + (j - 2 * D_DIM)];
        Wp[idx] = tf32_round(v);
        if (idx < NQKV) {
            float bv_;
            if (idx < D_DIM)            bv_ = bq[idx];
            else if (idx < 2 * D_DIM)   bv_ = bk[idx - D_DIM];
            else                        bv_ = bv[idx - 2 * D_DIM];
            bp[idx] = bv_;
        }
    }
}

// ---------------------------------------------------------------------------
// WoWc[d][c] = sum_n Wo[d][n] * Wc[(D+n)][c];  boWc[c] = sum_n bo[n]*Wc[(D+n)][c]
// One warp per d-row; lanes split n (coalesced Wo reads), shfl reduction.
// ---------------------------------------------------------------------------
__global__ __launch_bounds__(256)
void wowc_kernel(const float* __restrict__ Wo, const float* __restrict__ Wc,
                 const float* __restrict__ bo,
                 float* __restrict__ WoWc, float* __restrict__ boWc)
{
    const int gwarp  = (blockIdx.x * blockDim.x + threadIdx.x) >> 5;
    const int nwarps = (gridDim.x * blockDim.x) >> 5;
    const int lane   = threadIdx.x & 31;

    for (int d = gwarp; d < D_DIM; d += nwarps) {
        float acc[C_DIM];
        #pragma unroll
        for (int c = 0; c < C_DIM; c++) acc[c] = 0.0f;
        for (int n = lane; n < D_DIM; n += 32) {
            const float w = Wo[(size_t)d * D_DIM + n];
            const float* wcr = &Wc[(size_t)(D_DIM + n) * C_DIM];
            #pragma unroll
            for (int c = 0; c < C_DIM; c++) acc[c] += w * wcr[c];
        }
        #pragma unroll
        for (int c = 0; c < C_DIM; c++) {
            acc[c] += __shfl_xor_sync(0xFFFFFFFFu, acc[c], 16);
            acc[c] += __shfl_xor_sync(0xFFFFFFFFu, acc[c], 8);
            acc[c] += __shfl_xor_sync(0xFFFFFFFFu, acc[c], 4);
            acc[c] += __shfl_xor_sync(0xFFFFFFFFu, acc[c], 2);
            acc[c] += __shfl_xor_sync(0xFFFFFFFFu, acc[c], 1);
        }
        if (lane == 0) {
            #pragma unroll
            for (int c = 0; c < C_DIM; c++) WoWc[d * C_DIM + c] = acc[c];
        }
    }

    const int g = blockIdx.x * blockDim.x + threadIdx.x;
    if (g < C_DIM) {
        float a = 0.0f;
        for (int n = 0; n < D_DIM; n++)
            a += bo[n] * Wc[(size_t)(D_DIM + n) * C_DIM + g];
        boWc[g] = a;
    }
}

// ---------------------------------------------------------------------------
// TF32 tensor-core GEMM (proven) — unchanged.
// ---------------------------------------------------------------------------
#define BM 128
#define BN 128
#define BK 32
#define ASTRIDE 36
#define BSTRIDE 136
#define A_STAGE (BM * ASTRIDE)
#define B_STAGE (BK * BSTRIDE)
#define GEMM_SMEM_BYTES ((2 * A_STAGE + 2 * B_STAGE) * 4)  // 71680

__device__ __forceinline__ uint32_t f2tf32(float f) {
    uint32_t u;
    asm volatile("cvt.rna.tf32.f32 %0, %1;" : "=r"(u) : "f"(f));
    return u;
}

__device__ __forceinline__ void cp_async16(uint32_t smem_addr, const void* gptr) {
    asm volatile("cp.async.cg.shared.global [%0], [%1], 16;\n"
                 :: "r"(smem_addr), "l"(gptr));
}

__device__ __forceinline__ void mma_tf32(float* d, uint32_t a0, uint32_t a1,
                                         uint32_t a2, uint32_t a3,
                                         uint32_t b0, uint32_t b1)
{
    asm volatile(
        "mma.sync.aligned.m16n8k8.row.col.f32.tf32.tf32.f32 "
        "{%0,%1,%2,%3}, {%4,%5,%6,%7}, {%8,%9}, {%0,%1,%2,%3};\n"
        : "+f"(d[0]), "+f"(d[1]), "+f"(d[2]), "+f"(d[3])
        : "r"(a0), "r"(a1), "r"(a2), "r"(a3), "r"(b0), "r"(b1));
}

__global__ __launch_bounds__(256)
void tf32_gemm_kernel(const float* __restrict__ A,
                      const float* __restrict__ W,
                      const float* __restrict__ bias,
                      float* __restrict__ C0, float* __restrict__ C1,
                      float* __restrict__ C2,
                      int M, int N, int K, int zero_period)
{
    extern __shared__ float smem[];
    float* As = smem;
    float* Bs = smem + 2 * A_STAGE;

    const int tid  = threadIdx.x;
    const int lane = tid & 31;
    const int warp = tid >> 5;
    const int gid  = lane >> 2;
    const int tig  = lane & 3;
    const int warp_m = (warp & 3) * 32;
    const int warp_n = (warp >> 2) * 64;

    const int block_row = blockIdx.y * BM;
    const int block_col = blockIdx.x * BN;

    const int seg = block_col / D_DIM;
    float* Cout = (seg == 0) ? C0 : (seg == 1 ? C1 : C2);
    const int out_col_base = block_col - seg * D_DIM;

    const uint32_t smem_base = (uint32_t)__cvta_generic_to_shared(smem);
    const uint32_t As_addr = smem_base;
    const uint32_t Bs_addr = smem_base + 2 * A_STAGE * 4;

    float d[2][8][4];
    #pragma unroll
    for (int mi = 0; mi < 2; mi++)
        #pragma unroll
        for (int ni = 0; ni < 8; ni++)
            #pragma unroll
            for (int e = 0; e < 4; e++)
                d[mi][ni][e] = 0.0f;

    const int NITER = K / BK;

    {
        #pragma unroll
        for (int s = 0; s < 4; s++) {
            int c  = tid + s * 256;
            int m  = c >> 3, k4 = c & 7;
            cp_async16(As_addr + (m * ASTRIDE + k4 * 4) * 4,
                       &A[(size_t)(block_row + m) * K + k4 * 4]);
        }
        #pragma unroll
        for (int s = 0; s < 4; s++) {
            int c  = tid + s * 256;
            int k  = c >> 5, n4 = c & 31;
            cp_async16(Bs_addr + (k * BSTRIDE + n4 * 4) * 4,
                       &W[(size_t)k * N + block_col + n4 * 4]);
        }
        asm volatile("cp.async.commit_group;\n");
    }

    int buf = 0;
    for (int it = 0; it < NITER; it++) {
        if (it + 1 < NITER) {
            const int k0 = (it + 1) * BK;
            const int nb = buf ^ 1;
            #pragma unroll
            for (int s = 0; s < 4; s++) {
                int c  = tid + s * 256;
                int m  = c >> 3, k4 = c & 7;
                cp_async16(As_addr + (nb * A_STAGE + m * ASTRIDE + k4 * 4) * 4,
                           &A[(size_t)(block_row + m) * K + k0 + k4 * 4]);
            }
            #pragma unroll
            for (int s = 0; s < 4; s++) {
                int c  = tid + s * 256;
                int k  = c >> 5, n4 = c & 31;
                cp_async16(Bs_addr + (nb * B_STAGE + k * BSTRIDE + n4 * 4) * 4,
                           &W[(size_t)(k0 + k) * N + block_col + n4 * 4]);
            }
            asm volatile("cp.async.commit_group;\n");
            asm volatile("cp.async.wait_group 1;\n");
        } else {
            asm volatile("cp.async.wait_group 0;\n");
        }
        __syncthreads();

        const float* Ab = As + buf * A_STAGE;
        const float* Bb = Bs + buf * B_STAGE;

        #pragma unroll
        for (int ks = 0; ks < 4; ks++) {
            const int k0s = ks * 8;
            uint32_t afr[2][4];
            uint32_t bfr[8][2];
            #pragma unroll
            for (int mi = 0; mi < 2; mi++) {
                const int am = warp_m + mi * 16;
                afr[mi][0] = f2tf32(Ab[(am + gid)     * ASTRIDE + k0s + tig]);
                afr[mi][1] = f2tf32(Ab[(am + gid + 8) * ASTRIDE + k0s + tig]);
                afr[mi][2] = f2tf32(Ab[(am + gid)     * ASTRIDE + k0s + tig + 4]);
                afr[mi][3] = f2tf32(Ab[(am + gid + 8) * ASTRIDE + k0s + tig + 4]);
            }
            #pragma unroll
            for (int ni = 0; ni < 8; ni++) {
                const int bn = warp_n + ni * 8 + gid;
                bfr[ni][0] = __float_as_uint(Bb[(k0s + tig)     * BSTRIDE + bn]);
                bfr[ni][1] = __float_as_uint(Bb[(k0s + tig + 4) * BSTRIDE + bn]);
            }
            #pragma unroll
            for (int mi = 0; mi < 2; mi++)
                #pragma unroll
                for (int ni = 0; ni < 8; ni++)
                    mma_tf32(d[mi][ni], afr[mi][0], afr[mi][1], afr[mi][2],
                             afr[mi][3], bfr[ni][0], bfr[ni][1]);
        }
        __syncthreads();
        buf ^= 1;
    }

    #pragma unroll
    for (int mi = 0; mi < 2; mi++) {
        const int r0 = block_row + warp_m + mi * 16 + gid;
        const int r1 = r0 + 8;
        const bool z0 = (zero_period > 0) && ((r0 % zero_period) == 0);
        const bool z1 = (zero_period > 0) && ((r1 % zero_period) == 0);
        #pragma unroll
        for (int ni = 0; ni < 8; ni++) {
            const int cg = block_col + warp_n + ni * 8 + 2 * tig;
            const int cl = out_col_base + warp_n + ni * 8 + 2 * tig;
            const float b0 = bias[cg], b1 = bias[cg + 1];
            float v00 = d[mi][ni][0] + b0, v01 = d[mi][ni][1] + b1;
            float v10 = d[mi][ni][2] + b0, v11 = d[mi][ni][3] + b1;
            if (z0) { v00 = 0.0f; v01 = 0.0f; }
            if (z1) { v10 = 0.0f; v11 = 0.0f; }
            Cout[(size_t)r0 * D_DIM + cl]     = v00;
            Cout[(size_t)r0 * D_DIM + cl + 1] = v01;
            Cout[(size_t)r1 * D_DIM + cl]     = v10;
            Cout[(size_t)r1 * D_DIM + cl + 1] = v11;
        }
    }
}

// ---------------------------------------------------------------------------
// MMA flash-attention (proven in round 5) — unchanged.
// ---------------------------------------------------------------------------
#define QSTRIDE 68
#define KSTRIDE 68
#define VSTRIDE 72
#define ATT_SMEM_FLOATS (T_DIM * (QSTRIDE + KSTRIDE + VSTRIDE))
#define ATT_SMEM_BYTES  (ATT_SMEM_FLOATS * 4)   // 212992

__global__ __launch_bounds__(512)
void flash_attn_kernel(const float* __restrict__ Q,
                       const float* __restrict__ K,
                       const float* __restrict__ V,
                       const int*   __restrict__ num_turns,
                       float*       __restrict__ CTX)
{
    const int b = blockIdx.x / NH_DIM;
    const int h = blockIdx.x % NH_DIM;

    extern __shared__ float sm[];
    float* Qs = sm;
    float* Ks = Qs + T_DIM * QSTRIDE;
    float* Vs = Ks + T_DIM * KSTRIDE;

    const size_t base = ((size_t)b * T_DIM * NH_DIM + h) * DH_DIM;
    const int tid = threadIdx.x;

    for (int idx = tid; idx < T_DIM * (DH_DIM / 4); idx += 512) {
        const int t  = idx >> 4;
        const int c4 = (idx & 15) * 4;
        const size_t g = base + (size_t)t * D_DIM + c4;
        float4 q4 = *(const float4*)&Q[g];
        float4 k4 = *(const float4*)&K[g];
        float4 v4 = *(const float4*)&V[g];
        q4.x = tf32_round(q4.x * 0.125f); q4.y = tf32_round(q4.y * 0.125f);
        q4.z = tf32_round(q4.z * 0.125f); q4.w = tf32_round(q4.w * 0.125f);
        k4.x = tf32_round(k4.x); k4.y = tf32_round(k4.y);
        k4.z = tf32_round(k4.z); k4.w = tf32_round(k4.w);
        v4.x = tf32_round(v4.x); v4.y = tf32_round(v4.y);
        v4.z = tf32_round(v4.z); v4.w = tf32_round(v4.w);
        *(float4*)&Qs[t * QSTRIDE + c4] = q4;
        *(float4*)&Ks[t * KSTRIDE + c4] = k4;
        *(float4*)&Vs[t * VSTRIDE + c4] = v4;
    }
    __syncthreads();

    const int warp = tid >> 5;
    const int lane = tid & 31;
    const int gid  = lane >> 2;
    const int tig  = lane & 3;

    const int q0 = warp * 16 + gid;
    const int q1 = q0 + 8;
    const int ntv  = num_turns[b];
    const int lim0 = min(q0, ntv);
    const int lim1 = min(q1, ntv);

    const int lim_max = min(warp * 16 + 15, ntv);
    const int nch = (lim_max + 63) >> 6;

    float octx[8][4];
    #pragma unroll
    for (int i = 0; i < 8; i++)
        #pragma unroll
        for (int j = 0; j < 4; j++) octx[i][j] = 0.0f;
    float m0 = -1e30f, m1 = -1e30f, l0 = 0.0f, l1 = 0.0f;

    for (int ch = 0; ch < nch; ch++) {
        const int kbase = ch * 64;

        float s[8][4];
        #pragma unroll
        for (int i = 0; i < 8; i++)
            #pragma unroll
            for (int j = 0; j < 4; j++) s[i][j] = 0.0f;

        #pragma unroll
        for (int kt = 0; kt < 8; kt++) {
            const int dh = kt * 8;
            const uint32_t a0 = __float_as_uint(Qs[q0 * QSTRIDE + dh + tig]);
            const uint32_t a1 = __float_as_uint(Qs[q1 * QSTRIDE + dh + tig]);
            const uint32_t a2 = __float_as_uint(Qs[q0 * QSTRIDE + dh + tig + 4]);
            const uint32_t a3 = __float_as_uint(Qs[q1 * QSTRIDE + dh + tig + 4]);
            #pragma unroll
            for (int nt8 = 0; nt8 < 8; nt8++) {
                const int krow = kbase + nt8 * 8 + gid;
                const uint32_t b0 = __float_as_uint(Ks[krow * KSTRIDE + dh + tig]);
                const uint32_t b1 = __float_as_uint(Ks[krow * KSTRIDE + dh + tig + 4]);
                mma_tf32(s[nt8], a0, a1, a2, a3, b0, b1);
            }
        }

        float mx0 = -1e30f, mx1 = -1e30f;
        #pragma unroll
        for (int i = 0; i < 8; i++) {
            const int kc = kbase + i * 8 + 2 * tig;
            s[i][0] = (kc     < lim0) ? s[i][0] : -1e30f;
            s[i][1] = (kc + 1 < lim0) ? s[i][1] : -1e30f;
            s[i][2] = (kc     < lim1) ? s[i][2] : -1e30f;
            s[i][3] = (kc + 1 < lim1) ? s[i][3] : -1e30f;
            mx0 = fmaxf(mx0, fmaxf(s[i][0], s[i][1]));
            mx1 = fmaxf(mx1, fmaxf(s[i][2], s[i][3]));
        }
        mx0 = fmaxf(mx0, __shfl_xor_sync(0xFFFFFFFFu, mx0, 1));
        mx0 = fmaxf(mx0, __shfl_xor_sync(0xFFFFFFFFu, mx0, 2));
        mx1 = fmaxf(mx1, __shfl_xor_sync(0xFFFFFFFFu, mx1, 1));
        mx1 = fmaxf(mx1, __shfl_xor_sync(0xFFFFFFFFu, mx1, 2));

        const float nm0 = fmaxf(m0, mx0);
        const float nm1 = fmaxf(m1, mx1);
        const float corr0 = __expf(m0 - nm0);
        const float corr1 = __expf(m1 - nm1);
        m0 = nm0; m1 = nm1;
        l0 *= corr0; l1 *= corr1;
        #pragma unroll
        for (int i = 0; i < 8; i++) {
            octx[i][0] *= corr0; octx[i][1] *= corr0;
            octx[i][2] *= corr1; octx[i][3] *= corr1;
        }

        #pragma unroll
        for (int i = 0; i < 8; i++) {
            const float p0 = __expf(s[i][0] - m0);
            const float p1 = __expf(s[i][1] - m0);
            const float p2 = __expf(s[i][2] - m1);
            const float p3 = __expf(s[i][3] - m1);
            l0 += p0 + p1;  l1 += p2 + p3;
            s[i][0] = tf32_round(p0); s[i][1] = tf32_round(p1);
            s[i][2] = tf32_round(p2); s[i][3] = tf32_round(p3);
        }

        const int qb = lane & ~3;
        const int src  = qb | (tig >> 1);
        const int src2 = src + 2;
        const bool par = (tig & 1) != 0;
        #pragma unroll
        for (int kt = 0; kt < 8; kt++) {
            const float v00 = __shfl_sync(0xFFFFFFFFu, s[kt][0], src);
            const float v01 = __shfl_sync(0xFFFFFFFFu, s[kt][1], src);
            const float v10 = __shfl_sync(0xFFFFFFFFu, s[kt][2], src);
            const float v11 = __shfl_sync(0xFFFFFFFFu, s[kt][3], src);
            const float w00 = __shfl_sync(0xFFFFFFFFu, s[kt][0], src2);
            const float w01 = __shfl_sync(0xFFFFFFFFu, s[kt][1], src2);
            const float w10 = __shfl_sync(0xFFFFFFFFu, s[kt][2], src2);
            const float w11 = __shfl_sync(0xFFFFFFFFu, s[kt][3], src2);
            const uint32_t a0 = __float_as_uint(par ? v01 : v00);
            const uint32_t a1 = __float_as_uint(par ? v11 : v10);
            const uint32_t a2 = __float_as_uint(par ? w01 : w00);
            const uint32_t a3 = __float_as_uint(par ? w11 : w10);
            const int vr0 = kbase + kt * 8 + tig;
            #pragma unroll
            for (int ndh = 0; ndh < 8; ndh++) {
                const uint32_t b0 = __float_as_uint(Vs[vr0 * VSTRIDE + ndh * 8 + gid]);
                const uint32_t b1 = __float_as_uint(Vs[(vr0 + 4) * VSTRIDE + ndh * 8 + gid]);
                mma_tf32(octx[ndh], a0, a1, a2, a3, b0, b1);
            }
        }
    }

    l0 += __shfl_xor_sync(0xFFFFFFFFu, l0, 1);
    l0 += __shfl_xor_sync(0xFFFFFFFFu, l0, 2);
    l1 += __shfl_xor_sync(0xFFFFFFFFu, l1, 1);
    l1 += __shfl_xor_sync(0xFFFFFFFFu, l1, 2);
    const float inv0 = (lim0 > 0) ? 1.0f / l0 : 0.0f;
    const float inv1 = (lim1 > 0) ? 1.0f / l1 : 0.0f;

    float* o0 = &CTX[base + (size_t)q0 * D_DIM];
    float* o1 = &CTX[base + (size_t)q1 * D_DIM];
    #pragma unroll
    for (int ndh = 0; ndh < 8; ndh++) {
        const int c = ndh * 8 + 2 * tig;
        float2 r0 = make_float2(octx[ndh][0] * inv0, octx[ndh][1] * inv0);
        float2 r1 = make_float2(octx[ndh][2] * inv1, octx[ndh][3] * inv1);
        *(float2*)&o0[c] = r0;
        *(float2*)&o1[c] = r1;
    }
}

// ---------------------------------------------------------------------------
// Fused classifier: all_logits[b,t] = bc + [t>0]*boWc
//                                    + H[b,t] @ Wc_top + CTX[b,t] @ WoWc
// (CTX t==0 rows are exact zeros, matching the reference's c-zeroing.)
// ---------------------------------------------------------------------------
__global__ __launch_bounds__(128)
void classifier_kernel(const float* __restrict__ H,
                       const float* __restrict__ CTX,
                       const float* __restrict__ Wc,
                       const float* __restrict__ bc,
                       const float* __restrict__ WoWc,
                       const float* __restrict__ boWc,
                       float* __restrict__ out_all)
{
    __shared__ float Wtop[D_DIM * C_DIM];   // first 768 rows of Wc
    __shared__ float Wbot[D_DIM * C_DIM];   // Wo @ Wc_bot

    for (int i = threadIdx.x; i < D_DIM * C_DIM; i += 128) {
        Wtop[i] = Wc[i];
        Wbot[i] = WoWc[i];
    }
    __syncthreads();

    const int row = blockIdx.x * 128 + threadIdx.x;   // 0..16383
    const int t   = row & (T_DIM - 1);
    const float* hrow = &H  [(size_t)row * D_DIM];
    const float* crow = &CTX[(size_t)row * D_DIM];

    float acc[C_DIM];
    #pragma unroll
    for (int c = 0; c < C_DIM; c++)
        acc[c] = bc[c] + ((t > 0) ? boWc[c] : 0.0f);

    for (int i = 0; i < D_DIM; i += 4) {
        float4 h4 = *(const float4*)&hrow[i];
        const float hv[4] = {h4.x, h4.y, h4.z, h4.w};
        #pragma unroll
        for (int e = 0; e < 4; e++)
            #pragma unroll
            for (int c = 0; c < C_DIM; c++)
                acc[c] += hv[e] * Wtop[(i + e) * C_DIM + c];
    }
    for (int i = 0; i < D_DIM; i += 4) {
        float4 c4 = *(const float4*)&crow[i];
        const float cv[4] = {c4.x, c4.y, c4.z, c4.w};
        #pragma unroll
        for (int e = 0; e < 4; e++)
            #pragma unroll
            for (int c = 0; c < C_DIM; c++)
                acc[c] += cv[e] * Wbot[(i + e) * C_DIM + c];
    }

    float* o = &out_all[(size_t)row * C_DIM];
    #pragma unroll
    for (int c = 0; c < C_DIM; c++) o[c] = acc[c];
}

// ---------------------------------------------------------------------------
__global__ void gather_final_kernel(const float* __restrict__ all_logits,
                                    const int*   __restrict__ num_turns,
                                    float*       __restrict__ out_final)
{
    const int b = blockIdx.x;
    const int c = threadIdx.x;
    const int t = num_turns[b] - 1;
    out_final[(size_t)b * C_DIM + c] =
        all_logits[((size_t)b * T_DIM + t) * C_DIM + c];
}

// ---------------------------------------------------------------------------
// Launch
// ---------------------------------------------------------------------------
extern "C" void kernel_launch(void* const* d_in, const int* in_sizes, int n_in,
                              void* d_out, int out_size)
{
    const float* H  = (const float*)d_in[0];
    const float* Wq = (const float*)d_in[1];
    const float* bq = (const float*)d_in[2];
    const float* Wk = (const float*)d_in[3];
    const float* bk = (const float*)d_in[4];
    const float* Wv = (const float*)d_in[5];
    const float* bv = (const float*)d_in[6];
    const float* Wo = (const float*)d_in[7];
    const float* bo = (const float*)d_in[8];
    const float* Wc = (const float*)d_in[9];
    const float* bc = (const float*)d_in[10];
    const int*   nt = (const int*)  d_in[11];

    float* out_all   = (float*)d_out;
    float* out_final = (float*)d_out + (size_t)B_DIM * T_DIM * C_DIM;

    float *Qb, *Kb, *Vb, *CTXb, *Wp, *bp, *WoWcb, *boWcb;
    cudaGetSymbolAddress((void**)&Qb,    g_Q);
    cudaGetSymbolAddress((void**)&Kb,    g_K);
    cudaGetSymbolAddress((void**)&Vb,    g_V);
    cudaGetSymbolAddress((void**)&CTXb,  g_CTX);
    cudaGetSymbolAddress((void**)&Wp,    g_Wpack);
    cudaGetSymbolAddress((void**)&bp,    g_bpack);
    cudaGetSymbolAddress((void**)&WoWcb, g_WoWc);
    cudaGetSymbolAddress((void**)&boWcb, g_boWc);

    // 1) pack Wqkv (tf32) + fold Wo into the classifier weights
    pack_weights_kernel<<<1728, 256>>>(Wq, Wk, Wv, bq, bk, bv, Wp, bp);
    wowc_kernel<<<24, 256>>>(Wo, Wc, bo, WoWcb, boWcb);

    cudaFuncSetAttribute(tf32_gemm_kernel,
                         cudaFuncAttributeMaxDynamicSharedMemorySize, GEMM_SMEM_BYTES);

    // 2) fused QKV projection: [16384,768] @ Wqkv[768,2304]
    {
        dim3 grid(NQKV / BN, M_ROWS / BM);
        tf32_gemm_kernel<<<grid, 256, GEMM_SMEM_BYTES>>>(
            H, Wp, bp, Qb, Kb, Vb, M_ROWS, NQKV, D_DIM, 0);
    }

    // 3) MMA flash attention
    cudaFuncSetAttribute(flash_attn_kernel,
                         cudaFuncAttributeMaxDynamicSharedMemorySize, ATT_SMEM_BYTES);
    flash_attn_kernel<<<B_DIM * NH_DIM, 512, ATT_SMEM_BYTES>>>(Qb, Kb, Vb, nt, CTXb);

    // 4) fused classifier (Wo folded in) + gather
    classifier_kernel<<<M_ROWS / 128, 128>>>(H, CTXb, Wc, bc, WoWcb, boWcb, out_all);
    gather_final_kernel<<<B_DIM, C_DIM>>>(out_all, nt, out_final);
}

// round 7
// speedup vs baseline: 5.5091x; 1.4140x over previous
#include <cuda_runtime.h>
#include <cuda_bf16.h>
#include <math.h>
#include <stdint.h>

// Problem constants
#define B_DIM  64
#define T_DIM  256
#define D_DIM  768
#define NH_DIM 12
#define DH_DIM 64
#define C_DIM  7
#define M_ROWS (B_DIM * T_DIM)   // 16384
#define NQKV   (3 * D_DIM)       // 2304
#define KB16   (D_DIM / 16)      // 48  (k in 16-blocks)
#define MB16   (M_ROWS / 16)     // 1024
#define NB8    (NQKV / 8)        // 288

// ---------------------------------------------------------------------------
// Scratch (device globals; no runtime allocation allowed)
// ---------------------------------------------------------------------------
__device__ float g_Q[(size_t)M_ROWS * D_DIM];
__device__ float g_K[(size_t)M_ROWS * D_DIM];
__device__ float g_V[(size_t)M_ROWS * D_DIM];
__device__ float g_CTX[(size_t)M_ROWS * D_DIM];
// Fragment-packed bf16 operands:
//   g_Abf: [MB16][KB16][32 lanes][8 halves]  (A fragment per lane, m16k16 tile)
//   g_Wbf: [NB8 ][KB16][32 lanes][4 halves]  (B fragment per lane, k16n8 tile)
__device__ __nv_bfloat16 g_Abf[(size_t)MB16 * KB16 * 256];
__device__ __nv_bfloat16 g_Wbf[(size_t)NB8  * KB16 * 128];
__device__ float g_bpack[NQKV];                  // bq|bk|bv
__device__ float g_WoWc[D_DIM * C_DIM];          // Wo @ Wc_bot  [768][7]
__device__ float g_boWc[C_DIM];                  // bo @ Wc_bot  [7]

// ---------------------------------------------------------------------------
__device__ __forceinline__ float tf32_round(float f) {
    uint32_t u;
    asm volatile("cvt.rna.tf32.f32 %0, %1;" : "=r"(u) : "f"(f));
    return __uint_as_float(u);
}

__device__ __forceinline__ uint32_t pack_bf2(float lo, float hi) {
    __nv_bfloat162 t = __floats2bfloat162_rn(lo, hi);   // .x = lo (low 16 bits)
    return *reinterpret_cast<uint32_t*>(&t);
}

// ---------------------------------------------------------------------------
// Pack A: H [16384][768] fp32 -> g_Abf fragment-packed bf16.
// Thread per (mblk, kblk, lane): 4x LDG.64 gather, 1x STG.128.
// Fragment order per lane (gid=lane>>2, tig=lane&3, m0=16mblk+gid, k0=16kblk+2tig):
//   h0,h1=(m0,k0..k0+1) h2,h3=(m0+8,...) h4,h5=(m0,k0+8..) h6,h7=(m0+8,k0+8..)
// ---------------------------------------------------------------------------
__global__ __launch_bounds__(256)
void pack_a_kernel(const float* __restrict__ H, __nv_bfloat16* __restrict__ Abf)
{
    const int idx  = blockIdx.x * 256 + threadIdx.x;   // < MB16*KB16*32
    const int lane = idx & 31;
    const int kblk = (idx >> 5) % KB16;
    const int mblk = idx / (KB16 * 32);
    const int gid  = lane >> 2;
    const int tig  = lane & 3;
    const int m0 = mblk * 16 + gid;
    const int k0 = kblk * 16 + 2 * tig;

    float2 p00 = *(const float2*)&H[(size_t)m0 * D_DIM + k0];
    float2 p10 = *(const float2*)&H[(size_t)(m0 + 8) * D_DIM + k0];
    float2 p01 = *(const float2*)&H[(size_t)m0 * D_DIM + k0 + 8];
    float2 p11 = *(const float2*)&H[(size_t)(m0 + 8) * D_DIM + k0 + 8];

    uint4 out;
    out.x = pack_bf2(p00.x, p00.y);
    out.y = pack_bf2(p10.x, p10.y);
    out.z = pack_bf2(p01.x, p01.y);
    out.w = pack_bf2(p11.x, p11.y);
    *(uint4*)&Abf[(size_t)idx * 8] = out;
}

// ---------------------------------------------------------------------------
// Pack W: Wq|Wk|Wv [768][768] fp32 -> g_Wbf fragment-packed bf16; pack biases.
// B fragment per lane (n=8nblk+gid, k0=16kblk+2tig):
//   h0,h1=(k0..k0+1, n)  h2,h3=(k0+8..k0+9, n)
// ---------------------------------------------------------------------------
__global__ __launch_bounds__(256)
void pack_w_kernel(const float* __restrict__ Wq, const float* __restrict__ Wk,
                   const float* __restrict__ Wv,
                   const float* __restrict__ bq, const float* __restrict__ bk,
                   const float* __restrict__ bv,
                   __nv_bfloat16* __restrict__ Wbf, float* __restrict__ bp)
{
    const int idx  = blockIdx.x * 256 + threadIdx.x;   // < NB8*KB16*32
    const int lane = idx & 31;
    const int kblk = (idx >> 5) % KB16;
    const int nblk = idx / (KB16 * 32);
    const int gid  = lane >> 2;
    const int tig  = lane & 3;
    const int n  = nblk * 8 + gid;                     // 0..2303
    const int k0 = kblk * 16 + 2 * tig;

    const float* W = (n < D_DIM) ? Wq : ((n < 2 * D_DIM) ? Wk : Wv);
    const int j = (n >= 2 * D_DIM) ? (n - 2 * D_DIM)
                 : ((n >= D_DIM) ? (n - D_DIM) : n);

    const float w0 = W[(size_t)k0 * D_DIM + j];
    const float w1 = W[(size_t)(k0 + 1) * D_DIM + j];
    const float w2 = W[(size_t)(k0 + 8) * D_DIM + j];
    const float w3 = W[(size_t)(k0 + 9) * D_DIM + j];

    uint2 out;
    out.x = pack_bf2(w0, w1);
    out.y = pack_bf2(w2, w3);
    *(uint2*)&Wbf[(size_t)idx * 4] = out;

    if (idx < NQKV) {
        float bv_;
        if (idx < D_DIM)            bv_ = bq[idx];
        else if (idx < 2 * D_DIM)   bv_ = bk[idx - D_DIM];
        else                        bv_ = bv[idx - 2 * D_DIM];
        bp[idx] = bv_;
    }
}

// ---------------------------------------------------------------------------
// WoWc[d][c] = sum_n Wo[d][n] * Wc[(D+n)][c];  boWc[c] = sum_n bo[n]*Wc[(D+n)][c]
// ---------------------------------------------------------------------------
__global__ __launch_bounds__(256)
void wowc_kernel(const float* __restrict__ Wo, const float* __restrict__ Wc,
                 const float* __restrict__ bo,
                 float* __restrict__ WoWc, float* __restrict__ boWc)
{
    const int gwarp  = (blockIdx.x * blockDim.x + threadIdx.x) >> 5;
    const int nwarps = (gridDim.x * blockDim.x) >> 5;
    const int lane   = threadIdx.x & 31;

    for (int d = gwarp; d < D_DIM; d += nwarps) {
        float acc[C_DIM];
        #pragma unroll
        for (int c = 0; c < C_DIM; c++) acc[c] = 0.0f;
        for (int n = lane; n < D_DIM; n += 32) {
            const float w = Wo[(size_t)d * D_DIM + n];
            const float* wcr = &Wc[(size_t)(D_DIM + n) * C_DIM];
            #pragma unroll
            for (int c = 0; c < C_DIM; c++) acc[c] += w * wcr[c];
        }
        #pragma unroll
        for (int c = 0; c < C_DIM; c++) {
            acc[c] += __shfl_xor_sync(0xFFFFFFFFu, acc[c], 16);
            acc[c] += __shfl_xor_sync(0xFFFFFFFFu, acc[c], 8);
            acc[c] += __shfl_xor_sync(0xFFFFFFFFu, acc[c], 4);
            acc[c] += __shfl_xor_sync(0xFFFFFFFFu, acc[c], 2);
            acc[c] += __shfl_xor_sync(0xFFFFFFFFu, acc[c], 1);
        }
        if (lane == 0) {
            #pragma unroll
            for (int c = 0; c < C_DIM; c++) WoWc[d * C_DIM + c] = acc[c];
        }
    }

    const int g = blockIdx.x * blockDim.x + threadIdx.x;
    if (g < C_DIM) {
        float a = 0.0f;
        for (int n = 0; n < D_DIM; n++)
            a += bo[n] * Wc[(size_t)(D_DIM + n) * C_DIM + g];
        boWc[g] = a;
    }
}

// ---------------------------------------------------------------------------
// BF16 tensor-core GEMM on fragment-packed operands.
// BM=BN=128, BK=32 (2 k16-blocks), 8 warps (4x2), warp tile 32x64.
// mma.m16n8k16.bf16; all fragment loads are LDS.128 (A) / LDS.64 (B).
// Output routed by 768-col segment -> C0/C1/C2 (row stride 768), + bias.
// ---------------------------------------------------------------------------
#define A_STAGE_H 4096   // halves per stage: 8 mb * 2 kb * 32 * 8
#define B_STAGE_H 4096   // halves per stage: 16 nb * 2 kb * 32 * 4

__device__ __forceinline__ void cp_async16(uint32_t smem_addr, const void* gptr) {
    asm volatile("cp.async.cg.shared.global [%0], [%1], 16;\n"
                 :: "r"(smem_addr), "l"(gptr));
}

__device__ __forceinline__ void mma_bf16(float* d, uint4 a, uint2 b) {
    asm volatile(
        "mma.sync.aligned.m16n8k16.row.col.f32.bf16.bf16.f32 "
        "{%0,%1,%2,%3}, {%4,%5,%6,%7}, {%8,%9}, {%0,%1,%2,%3};\n"
        : "+f"(d[0]), "+f"(d[1]), "+f"(d[2]), "+f"(d[3])
        : "r"(a.x), "r"(a.y), "r"(a.z), "r"(a.w), "r"(b.x), "r"(b.y));
}

__global__ __launch_bounds__(256)
void bf16_gemm_kernel(const __nv_bfloat16* __restrict__ Abf,
                      const __nv_bfloat16* __restrict__ Wbf,
                      const float* __restrict__ bias,
                      float* __restrict__ C0, float* __restrict__ C1,
                      float* __restrict__ C2)
{
    __shared__ __nv_bfloat16 As[2 * A_STAGE_H];   // [buf][mb(8)][kb(2)][lane][8]
    __shared__ __nv_bfloat16 Bs[2 * B_STAGE_H];   // [buf][nb(16)][kb(2)][lane][4]

    const int tid  = threadIdx.x;
    const int lane = tid & 31;
    const int warp = tid >> 5;
    const int gid  = lane >> 2;
    const int tig  = lane & 3;

    const int mrow0 = blockIdx.y * 8;     // first 16-row block of this CTA
    const int nb0   = blockIdx.x * 16;    // first 8-col block of this CTA
    const int block_row = blockIdx.y * 128;
    const int block_col = blockIdx.x * 128;

    const int seg = block_col / D_DIM;
    float* Cout = (seg == 0) ? C0 : (seg == 1 ? C1 : C2);
    const int out_col_base = block_col - seg * D_DIM;

    const uint32_t As_u32 = (uint32_t)__cvta_generic_to_shared(As);
    const uint32_t Bs_u32 = (uint32_t)__cvta_generic_to_shared(Bs);

    float d[2][8][4];
    #pragma unroll
    for (int mi = 0; mi < 2; mi++)
        #pragma unroll
        for (int ni = 0; ni < 8; ni++)
            #pragma unroll
            for (int e = 0; e < 4; e++)
                d[mi][ni][e] = 0.0f;

    const int NITER = KB16 / 2;   // 24 (BK=32 = 2 k16-blocks)

    // stage copy: 512 16B-chunks for A, 512 for B; 2 each per thread
    auto do_stage = [&](int kb0, int sbuf) {
        #pragma unroll
        for (int s = 0; s < 2; s++) {
            const int c  = tid + s * 256;
            const int mb = c >> 6, ch = c & 63;
            cp_async16(As_u32 + (sbuf * A_STAGE_H + c * 8) * 2,
                       Abf + ((((size_t)(mrow0 + mb)) * KB16 + kb0) << 8) + ch * 8);
        }
        #pragma unroll
        for (int s = 0; s < 2; s++) {
            const int c  = tid + s * 256;
            const int nb = c >> 5, ch = c & 31;
            cp_async16(Bs_u32 + (sbuf * B_STAGE_H + c * 8) * 2,
                       Wbf + ((((size_t)(nb0 + nb)) * KB16 + kb0) << 7) + ch * 8);
        }
        asm volatile("cp.async.commit_group;\n");
    };

    do_stage(0, 0);

    const int warp_mb = (warp & 3) * 2;   // 2 m16-blocks per warp
    const int warp_nb = (warp >> 2) * 8;  // 8 n8-blocks per warp

    int buf = 0;
    for (int it = 0; it < NITER; it++) {
        if (it + 1 < NITER) {
            do_stage((it + 1) * 2, buf ^ 1);
            asm volatile("cp.async.wait_group 1;\n");
        } else {
            asm volatile("cp.async.wait_group 0;\n");
        }
        __syncthreads();

        const uint4* As4 = (const uint4*)As + buf * (A_STAGE_H / 8);
        const uint2* Bs2 = (const uint2*)Bs + buf * (B_STAGE_H / 4);

        #pragma unroll
        for (int kb = 0; kb < 2; kb++) {
            uint4 afr[2];
            #pragma unroll
            for (int mi = 0; mi < 2; mi++)
                afr[mi] = As4[((warp_mb + mi) * 2 + kb) * 32 + lane];
            uint2 bfr[8];
            #pragma unroll
            for (int ni = 0; ni < 8; ni++)
                bfr[ni] = Bs2[((warp_nb + ni) * 2 + kb) * 32 + lane];
            #pragma unroll
            for (int mi = 0; mi < 2; mi++)
                #pragma unroll
                for (int ni = 0; ni < 8; ni++)
                    mma_bf16(d[mi][ni], afr[mi], bfr[ni]);
        }
        __syncthreads();
        buf ^= 1;
    }

    // epilogue: bias + segmented store (row stride 768)
    #pragma unroll
    for (int mi = 0; mi < 2; mi++) {
        const int r0 = block_row + (warp & 3) * 32 + mi * 16 + gid;
        const int r1 = r0 + 8;
        #pragma unroll
        for (int ni = 0; ni < 8; ni++) {
            const int cg = block_col + (warp >> 2) * 64 + ni * 8 + 2 * tig;
            const int cl = out_col_base + (warp >> 2) * 64 + ni * 8 + 2 * tig;
            const float b0 = bias[cg], b1 = bias[cg + 1];
            Cout[(size_t)r0 * D_DIM + cl]     = d[mi][ni][0] + b0;
            Cout[(size_t)r0 * D_DIM + cl + 1] = d[mi][ni][1] + b1;
            Cout[(size_t)r1 * D_DIM + cl]     = d[mi][ni][2] + b0;
            Cout[(size_t)r1 * D_DIM + cl + 1] = d[mi][ni][3] + b1;
        }
    }
}

// ---------------------------------------------------------------------------
// MMA flash-attention (proven in round 5) — unchanged.
// ---------------------------------------------------------------------------
#define QSTRIDE 68
#define KSTRIDE 68
#define VSTRIDE 72
#define ATT_SMEM_FLOATS (T_DIM * (QSTRIDE + KSTRIDE + VSTRIDE))
#define ATT_SMEM_BYTES  (ATT_SMEM_FLOATS * 4)   // 212992

__device__ __forceinline__ void mma_tf32(float* d, uint32_t a0, uint32_t a1,
                                         uint32_t a2, uint32_t a3,
                                         uint32_t b0, uint32_t b1)
{
    asm volatile(
        "mma.sync.aligned.m16n8k8.row.col.f32.tf32.tf32.f32 "
        "{%0,%1,%2,%3}, {%4,%5,%6,%7}, {%8,%9}, {%0,%1,%2,%3};\n"
        : "+f"(d[0]), "+f"(d[1]), "+f"(d[2]), "+f"(d[3])
        : "r"(a0), "r"(a1), "r"(a2), "r"(a3), "r"(b0), "r"(b1));
}

__global__ __launch_bounds__(512)
void flash_attn_kernel(const float* __restrict__ Q,
                       const float* __restrict__ K,
                       const float* __restrict__ V,
                       const int*   __restrict__ num_turns,
                       float*       __restrict__ CTX)
{
    const int b = blockIdx.x / NH_DIM;
    const int h = blockIdx.x % NH_DIM;

    extern __shared__ float sm[];
    float* Qs = sm;
    float* Ks = Qs + T_DIM * QSTRIDE;
    float* Vs = Ks + T_DIM * KSTRIDE;

    const size_t base = ((size_t)b * T_DIM * NH_DIM + h) * DH_DIM;
    const int tid = threadIdx.x;

    for (int idx = tid; idx < T_DIM * (DH_DIM / 4); idx += 512) {
        const int t  = idx >> 4;
        const int c4 = (idx & 15) * 4;
        const size_t g = base + (size_t)t * D_DIM + c4;
        float4 q4 = *(const float4*)&Q[g];
        float4 k4 = *(const float4*)&K[g];
        float4 v4 = *(const float4*)&V[g];
        q4.x = tf32_round(q4.x * 0.125f); q4.y = tf32_round(q4.y * 0.125f);
        q4.z = tf32_round(q4.z * 0.125f); q4.w = tf32_round(q4.w * 0.125f);
        k4.x = tf32_round(k4.x); k4.y = tf32_round(k4.y);
        k4.z = tf32_round(k4.z); k4.w = tf32_round(k4.w);
        v4.x = tf32_round(v4.x); v4.y = tf32_round(v4.y);
        v4.z = tf32_round(v4.z); v4.w = tf32_round(v4.w);
        *(float4*)&Qs[t * QSTRIDE + c4] = q4;
        *(float4*)&Ks[t * KSTRIDE + c4] = k4;
        *(float4*)&Vs[t * VSTRIDE + c4] = v4;
    }
    __syncthreads();

    const int warp = tid >> 5;
    const int lane = tid & 31;
    const int gid  = lane >> 2;
    const int tig  = lane & 3;

    const int q0 = warp * 16 + gid;
    const int q1 = q0 + 8;
    const int ntv  = num_turns[b];
    const int lim0 = min(q0, ntv);
    const int lim1 = min(q1, ntv);

    const int lim_max = min(warp * 16 + 15, ntv);
    const int nch = (lim_max + 63) >> 6;

    float octx[8][4];
    #pragma unroll
    for (int i = 0; i < 8; i++)
        #pragma unroll
        for (int j = 0; j < 4; j++) octx[i][j] = 0.0f;
    float m0 = -1e30f, m1 = -1e30f, l0 = 0.0f, l1 = 0.0f;

    for (int ch = 0; ch < nch; ch++) {
        const int kbase = ch * 64;

        float s[8][4];
        #pragma unroll
        for (int i = 0; i < 8; i++)
            #pragma unroll
            for (int j = 0; j < 4; j++) s[i][j] = 0.0f;

        #pragma unroll
        for (int kt = 0; kt < 8; kt++) {
            const int dh = kt * 8;
            const uint32_t a0 = __float_as_uint(Qs[q0 * QSTRIDE + dh + tig]);
            const uint32_t a1 = __float_as_uint(Qs[q1 * QSTRIDE + dh + tig]);
            const uint32_t a2 = __float_as_uint(Qs[q0 * QSTRIDE + dh + tig + 4]);
            const uint32_t a3 = __float_as_uint(Qs[q1 * QSTRIDE + dh + tig + 4]);
            #pragma unroll
            for (int nt8 = 0; nt8 < 8; nt8++) {
                const int krow = kbase + nt8 * 8 + gid;
                const uint32_t b0 = __float_as_uint(Ks[krow * KSTRIDE + dh + tig]);
                const uint32_t b1 = __float_as_uint(Ks[krow * KSTRIDE + dh + tig + 4]);
                mma_tf32(s[nt8], a0, a1, a2, a3, b0, b1);
            }
        }

        float mx0 = -1e30f, mx1 = -1e30f;
        #pragma unroll
        for (int i = 0; i < 8; i++) {
            const int kc = kbase + i * 8 + 2 * tig;
            s[i][0] = (kc     < lim0) ? s[i][0] : -1e30f;
            s[i][1] = (kc + 1 < lim0) ? s[i][1] : -1e30f;
            s[i][2] = (kc     < lim1) ? s[i][2] : -1e30f;
            s[i][3] = (kc + 1 < lim1) ? s[i][3] : -1e30f;
            mx0 = fmaxf(mx0, fmaxf(s[i][0], s[i][1]));
            mx1 = fmaxf(mx1, fmaxf(s[i][2], s[i][3]));
        }
        mx0 = fmaxf(mx0, __shfl_xor_sync(0xFFFFFFFFu, mx0, 1));
        mx0 = fmaxf(mx0, __shfl_xor_sync(0xFFFFFFFFu, mx0, 2));
        mx1 = fmaxf(mx1, __shfl_xor_sync(0xFFFFFFFFu, mx1, 1));
        mx1 = fmaxf(mx1, __shfl_xor_sync(0xFFFFFFFFu, mx1, 2));

        const float nm0 = fmaxf(m0, mx0);
        const float nm1 = fmaxf(m1, mx1);
        const float corr0 = __expf(m0 - nm0);
        const float corr1 = __expf(m1 - nm1);
        m0 = nm0; m1 = nm1;
        l0 *= corr0; l1 *= corr1;
        #pragma unroll
        for (int i = 0; i < 8; i++) {
            octx[i][0] *= corr0; octx[i][1] *= corr0;
            octx[i][2] *= corr1; octx[i][3] *= corr1;
        }

        #pragma unroll
        for (int i = 0; i < 8; i++) {
            const float p0 = __expf(s[i][0] - m0);
            const float p1 = __expf(s[i][1] - m0);
            const float p2 = __expf(s[i][2] - m1);
            const float p3 = __expf(s[i][3] - m1);
            l0 += p0 + p1;  l1 += p2 + p3;
            s[i][0] = tf32_round(p0); s[i][1] = tf32_round(p1);
            s[i][2] = tf32_round(p2); s[i][3] = tf32_round(p3);
        }

        const int qb = lane & ~3;
        const int src  = qb | (tig >> 1);
        const int src2 = src + 2;
        const bool par = (tig & 1) != 0;
        #pragma unroll
        for (int kt = 0; kt < 8; kt++) {
            const float v00 = __shfl_sync(0xFFFFFFFFu, s[kt][0], src);
            const float v01 = __shfl_sync(0xFFFFFFFFu, s[kt][1], src);
            const float v10 = __shfl_sync(0xFFFFFFFFu, s[kt][2], src);
            const float v11 = __shfl_sync(0xFFFFFFFFu, s[kt][3], src);
            const float w00 = __shfl_sync(0xFFFFFFFFu, s[kt][0], src2);
            const float w01 = __shfl_sync(0xFFFFFFFFu, s[kt][1], src2);
            const float w10 = __shfl_sync(0xFFFFFFFFu, s[kt][2], src2);
            const float w11 = __shfl_sync(0xFFFFFFFFu, s[kt][3], src2);
            const uint32_t a0 = __float_as_uint(par ? v01 : v00);
            const uint32_t a1 = __float_as_uint(par ? v11 : v10);
            const uint32_t a2 = __float_as_uint(par ? w01 : w00);
            const uint32_t a3 = __float_as_uint(par ? w11 : w10);
            const int vr0 = kbase + kt * 8 + tig;
            #pragma unroll
            for (int ndh = 0; ndh < 8; ndh++) {
                const uint32_t b0 = __float_as_uint(Vs[vr0 * VSTRIDE + ndh * 8 + gid]);
                const uint32_t b1 = __float_as_uint(Vs[(vr0 + 4) * VSTRIDE + ndh * 8 + gid]);
                mma_tf32(octx[ndh], a0, a1, a2, a3, b0, b1);
            }
        }
    }

    l0 += __shfl_xor_sync(0xFFFFFFFFu, l0, 1);
    l0 += __shfl_xor_sync(0xFFFFFFFFu, l0, 2);
    l1 += __shfl_xor_sync(0xFFFFFFFFu, l1, 1);
    l1 += __shfl_xor_sync(0xFFFFFFFFu, l1, 2);
    const float inv0 = (lim0 > 0) ? 1.0f / l0 : 0.0f;
    const float inv1 = (lim1 > 0) ? 1.0f / l1 : 0.0f;

    float* o0 = &CTX[base + (size_t)q0 * D_DIM];
    float* o1 = &CTX[base + (size_t)q1 * D_DIM];
    #pragma unroll
    for (int ndh = 0; ndh < 8; ndh++) {
        const int c = ndh * 8 + 2 * tig;
        float2 r0 = make_float2(octx[ndh][0] * inv0, octx[ndh][1] * inv0);
        float2 r1 = make_float2(octx[ndh][2] * inv1, octx[ndh][3] * inv1);
        *(float2*)&o0[c] = r0;
        *(float2*)&o1[c] = r1;
    }
}

// ---------------------------------------------------------------------------
// Fused classifier: all_logits[b,t] = bc + [t>0]*boWc
//                                    + H[b,t] @ Wc_top + CTX[b,t] @ WoWc
// ---------------------------------------------------------------------------
__global__ __launch_bounds__(128)
void classifier_kernel(const float* __restrict__ H,
                       const float* __restrict__ CTX,
                       const float* __restrict__ Wc,
                       const float* __restrict__ bc,
                       const float* __restrict__ WoWc,
                       const float* __restrict__ boWc,
                       float* __restrict__ out_all)
{
    __shared__ float Wtop[D_DIM * C_DIM];
    __shared__ float Wbot[D_DIM * C_DIM];

    for (int i = threadIdx.x; i < D_DIM * C_DIM; i += 128) {
        Wtop[i] = Wc[i];
        Wbot[i] = WoWc[i];
    }
    __syncthreads();

    const int row = blockIdx.x * 128 + threadIdx.x;
    const int t   = row & (T_DIM - 1);
    const float* hrow = &H  [(size_t)row * D_DIM];
    const float* crow = &CTX[(size_t)row * D_DIM];

    float acc[C_DIM];
    #pragma unroll
    for (int c = 0; c < C_DIM; c++)
        acc[c] = bc[c] + ((t > 0) ? boWc[c] : 0.0f);

    for (int i = 0; i < D_DIM; i += 4) {
        float4 h4 = *(const float4*)&hrow[i];
        const float hv[4] = {h4.x, h4.y, h4.z, h4.w};
        #pragma unroll
        for (int e = 0; e < 4; e++)
            #pragma unroll
            for (int c = 0; c < C_DIM; c++)
                acc[c] += hv[e] * Wtop[(i + e) * C_DIM + c];
    }
    for (int i = 0; i < D_DIM; i += 4) {
        float4 c4 = *(const float4*)&crow[i];
        const float cv[4] = {c4.x, c4.y, c4.z, c4.w};
        #pragma unroll
        for (int e = 0; e < 4; e++)
            #pragma unroll
            for (int c = 0; c < C_DIM; c++)
                acc[c] += cv[e] * Wbot[(i + e) * C_DIM + c];
    }

    float* o = &out_all[(size_t)row * C_DIM];
    #pragma unroll
    for (int c = 0; c < C_DIM; c++) o[c] = acc[c];
}

// ---------------------------------------------------------------------------
__global__ void gather_final_kernel(const float* __restrict__ all_logits,
                                    const int*   __restrict__ num_turns,
                                    float*       __restrict__ out_final)
{
    const int b = blockIdx.x;
    const int c = threadIdx.x;
    const int t = num_turns[b] - 1;
    out_final[(size_t)b * C_DIM + c] =
        all_logits[((size_t)b * T_DIM + t) * C_DIM + c];
}

// ---------------------------------------------------------------------------
// Launch
// ---------------------------------------------------------------------------
extern "C" void kernel_launch(void* const* d_in, const int* in_sizes, int n_in,
                              void* d_out, int out_size)
{
    const float* H  = (const float*)d_in[0];
    const float* Wq = (const float*)d_in[1];
    const float* bq = (const float*)d_in[2];
    const float* Wk = (const float*)d_in[3];
    const float* bk = (const float*)d_in[4];
    const float* Wv = (const float*)d_in[5];
    const float* bv = (const float*)d_in[6];
    const float* Wo = (const float*)d_in[7];
    const float* bo = (const float*)d_in[8];
    const float* Wc = (const float*)d_in[9];
    const float* bc = (const float*)d_in[10];
    const int*   nt = (const int*)  d_in[11];

    float* out_all   = (float*)d_out;
    float* out_final = (float*)d_out + (size_t)B_DIM * T_DIM * C_DIM;

    float *Qb, *Kb, *Vb, *CTXb, *bp, *WoWcb, *boWcb;
    __nv_bfloat16 *Abf, *Wbf;
    cudaGetSymbolAddress((void**)&Qb,    g_Q);
    cudaGetSymbolAddress((void**)&Kb,    g_K);
    cudaGetSymbolAddress((void**)&Vb,    g_V);
    cudaGetSymbolAddress((void**)&CTXb,  g_CTX);
    cudaGetSymbolAddress((void**)&Abf,   g_Abf);
    cudaGetSymbolAddress((void**)&Wbf,   g_Wbf);
    cudaGetSymbolAddress((void**)&bp,    g_bpack);
    cudaGetSymbolAddress((void**)&WoWcb, g_WoWc);
    cudaGetSymbolAddress((void**)&boWcb, g_boWc);

    // 1) fragment-pack operands (bf16) + fold Wo into classifier weights
    pack_a_kernel<<<MB16 * KB16 * 32 / 256, 256>>>(H, Abf);
    pack_w_kernel<<<NB8 * KB16 * 32 / 256, 256>>>(Wq, Wk, Wv, bq, bk, bv, Wbf, bp);
    wowc_kernel<<<24, 256>>>(Wo, Wc, bo, WoWcb, boWcb);

    // 2) fused QKV projection (bf16 tensor cores)
    {
        dim3 grid(NQKV / 128, M_ROWS / 128);   // (18, 128)
        bf16_gemm_kernel<<<grid, 256>>>(Abf, Wbf, bp, Qb, Kb, Vb);
    }

    // 3) MMA flash attention
    cudaFuncSetAttribute(flash_attn_kernel,
                         cudaFuncAttributeMaxDynamicSharedMemorySize, ATT_SMEM_BYTES);
    flash_attn_kernel<<<B_DIM * NH_DIM, 512, ATT_SMEM_BYTES>>>(Qb, Kb, Vb, nt, CTXb);

    // 4) fused classifier (Wo folded) + gather
    classifier_kernel<<<M_ROWS / 128, 128>>>(H, CTXb, Wc, bc, WoWcb, boWcb, out_all);
    gather_final_kernel<<<B_DIM, C_DIM>>>(out_all, nt, out_final);
}

// round 8
// speedup vs baseline: 6.0925x; 1.1059x over previous
#include <cuda_runtime.h>
#include <cuda_bf16.h>
#include <math.h>
#include <stdint.h>

// Problem constants
#define B_DIM  64
#define T_DIM  256
#define D_DIM  768
#define NH_DIM 12
#define DH_DIM 64
#define C_DIM  7
#define M_ROWS (B_DIM * T_DIM)   // 16384
#define NQKV   (3 * D_DIM)       // 2304
#define KB16   (D_DIM / 16)      // 48
#define MB16   (M_ROWS / 16)     // 1024
#define NB8    (NQKV / 8)        // 288

// Prep-kernel block ranges
#define PA_BLOCKS  (MB16 * KB16 * 32 / 256)   // 6144
#define PW_BLOCKS  (NB8  * KB16 * 32 / 256)   // 1728
#define WC_BLOCKS  24
#define PREP_BLOCKS (PA_BLOCKS + PW_BLOCKS + WC_BLOCKS)

// ---------------------------------------------------------------------------
// Scratch (device globals; no runtime allocation allowed)
// ---------------------------------------------------------------------------
__device__ __nv_bfloat16 g_Q[(size_t)M_ROWS * D_DIM];
__device__ __nv_bfloat16 g_K[(size_t)M_ROWS * D_DIM];
__device__ __nv_bfloat16 g_V[(size_t)M_ROWS * D_DIM];
__device__ float g_CTX[(size_t)M_ROWS * D_DIM];
__device__ __nv_bfloat16 g_Abf[(size_t)MB16 * KB16 * 256];
__device__ __nv_bfloat16 g_Wbf[(size_t)NB8  * KB16 * 128];
__device__ float g_bpack[NQKV];
__device__ float g_WoWc[D_DIM * C_DIM];
__device__ float g_boWc[C_DIM];

// ---------------------------------------------------------------------------
__device__ __forceinline__ uint32_t pack_bf2(float lo, float hi) {
    __nv_bfloat162 t = __floats2bfloat162_rn(lo, hi);
    return *reinterpret_cast<uint32_t*>(&t);
}

// ---------------------------------------------------------------------------
// Fused prep: pack A fragments | pack W fragments + biases | WoWc fold.
// ---------------------------------------------------------------------------
__global__ __launch_bounds__(256)
void prep_kernel(const float* __restrict__ H,
                 const float* __restrict__ Wq, const float* __restrict__ Wk,
                 const float* __restrict__ Wv,
                 const float* __restrict__ bq, const float* __restrict__ bk,
                 const float* __restrict__ bv,
                 const float* __restrict__ Wo, const float* __restrict__ Wc,
                 const float* __restrict__ bo,
                 __nv_bfloat16* __restrict__ Abf,
                 __nv_bfloat16* __restrict__ Wbf,
                 float* __restrict__ bp,
                 float* __restrict__ WoWc, float* __restrict__ boWc)
{
    const int blk = blockIdx.x;

    if (blk < PA_BLOCKS) {
        // ---- pack A: H -> fragment-packed bf16
        const int idx  = blk * 256 + threadIdx.x;
        const int lane = idx & 31;
        const int kblk = (idx >> 5) % KB16;
        const int mblk = idx / (KB16 * 32);
        const int gid  = lane >> 2;
        const int tig  = lane & 3;
        const int m0 = mblk * 16 + gid;
        const int k0 = kblk * 16 + 2 * tig;

        float2 p00 = *(const float2*)&H[(size_t)m0 * D_DIM + k0];
        float2 p10 = *(const float2*)&H[(size_t)(m0 + 8) * D_DIM + k0];
        float2 p01 = *(const float2*)&H[(size_t)m0 * D_DIM + k0 + 8];
        float2 p11 = *(const float2*)&H[(size_t)(m0 + 8) * D_DIM + k0 + 8];

        uint4 out;
        out.x = pack_bf2(p00.x, p00.y);
        out.y = pack_bf2(p10.x, p10.y);
        out.z = pack_bf2(p01.x, p01.y);
        out.w = pack_bf2(p11.x, p11.y);
        *(uint4*)&Abf[(size_t)idx * 8] = out;

    } else if (blk < PA_BLOCKS + PW_BLOCKS) {
        // ---- pack W: Wq|Wk|Wv -> fragment-packed bf16; biases
        const int idx  = (blk - PA_BLOCKS) * 256 + threadIdx.x;
        const int lane = idx & 31;
        const int kblk = (idx >> 5) % KB16;
        const int nblk = idx / (KB16 * 32);
        const int gid  = lane >> 2;
        const int tig  = lane & 3;
        const int n  = nblk * 8 + gid;
        const int k0 = kblk * 16 + 2 * tig;

        const float* W = (n < D_DIM) ? Wq : ((n < 2 * D_DIM) ? Wk : Wv);
        const int j = (n >= 2 * D_DIM) ? (n - 2 * D_DIM)
                     : ((n >= D_DIM) ? (n - D_DIM) : n);

        const float w0 = W[(size_t)k0 * D_DIM + j];
        const float w1 = W[(size_t)(k0 + 1) * D_DIM + j];
        const float w2 = W[(size_t)(k0 + 8) * D_DIM + j];
        const float w3 = W[(size_t)(k0 + 9) * D_DIM + j];

        uint2 out;
        out.x = pack_bf2(w0, w1);
        out.y = pack_bf2(w2, w3);
        *(uint2*)&Wbf[(size_t)idx * 4] = out;

        if (idx < NQKV) {
            float bv_;
            if (idx < D_DIM)            bv_ = bq[idx];
            else if (idx < 2 * D_DIM)   bv_ = bk[idx - D_DIM];
            else                        bv_ = bv[idx - 2 * D_DIM];
            bp[idx] = bv_;
        }

    } else {
        // ---- WoWc fold: one warp per d-row
        const int wblk   = blk - PA_BLOCKS - PW_BLOCKS;   // 0..23
        const int gwarp  = (wblk * 256 + threadIdx.x) >> 5;
        const int nwarps = (WC_BLOCKS * 256) >> 5;        // 192
        const int lane   = threadIdx.x & 31;

        for (int d = gwarp; d < D_DIM; d += nwarps) {
            float acc[C_DIM];
            #pragma unroll
            for (int c = 0; c < C_DIM; c++) acc[c] = 0.0f;
            for (int n = lane; n < D_DIM; n += 32) {
                const float w = Wo[(size_t)d * D_DIM + n];
                const float* wcr = &Wc[(size_t)(D_DIM + n) * C_DIM];
                #pragma unroll
                for (int c = 0; c < C_DIM; c++) acc[c] += w * wcr[c];
            }
            #pragma unroll
            for (int c = 0; c < C_DIM; c++) {
                acc[c] += __shfl_xor_sync(0xFFFFFFFFu, acc[c], 16);
                acc[c] += __shfl_xor_sync(0xFFFFFFFFu, acc[c], 8);
                acc[c] += __shfl_xor_sync(0xFFFFFFFFu, acc[c], 4);
                acc[c] += __shfl_xor_sync(0xFFFFFFFFu, acc[c], 2);
                acc[c] += __shfl_xor_sync(0xFFFFFFFFu, acc[c], 1);
            }
            if (lane == 0) {
                #pragma unroll
                for (int c = 0; c < C_DIM; c++) WoWc[d * C_DIM + c] = acc[c];
            }
        }

        const int g = wblk * 256 + threadIdx.x;
        if (g < C_DIM) {
            float a = 0.0f;
            for (int n = 0; n < D_DIM; n++)
                a += bo[n] * Wc[(size_t)(D_DIM + n) * C_DIM + g];
            boWc[g] = a;
        }
    }
}

// ---------------------------------------------------------------------------
// BF16 tensor-core GEMM on fragment-packed operands (round 7, proven).
// Epilogue now stores bf16 Q/K/V (bias added in fp32 first).
// ---------------------------------------------------------------------------
#define A_STAGE_H 4096
#define B_STAGE_H 4096

__device__ __forceinline__ void cp_async16(uint32_t smem_addr, const void* gptr) {
    asm volatile("cp.async.cg.shared.global [%0], [%1], 16;\n"
                 :: "r"(smem_addr), "l"(gptr));
}

__device__ __forceinline__ void mma_bf16(float* d, uint4 a, uint2 b) {
    asm volatile(
        "mma.sync.aligned.m16n8k16.row.col.f32.bf16.bf16.f32 "
        "{%0,%1,%2,%3}, {%4,%5,%6,%7}, {%8,%9}, {%0,%1,%2,%3};\n"
        : "+f"(d[0]), "+f"(d[1]), "+f"(d[2]), "+f"(d[3])
        : "r"(a.x), "r"(a.y), "r"(a.z), "r"(a.w), "r"(b.x), "r"(b.y));
}

__global__ __launch_bounds__(256)
void bf16_gemm_kernel(const __nv_bfloat16* __restrict__ Abf,
                      const __nv_bfloat16* __restrict__ Wbf,
                      const float* __restrict__ bias,
                      __nv_bfloat16* __restrict__ C0,
                      __nv_bfloat16* __restrict__ C1,
                      __nv_bfloat16* __restrict__ C2)
{
    __shared__ __nv_bfloat16 As[2 * A_STAGE_H];
    __shared__ __nv_bfloat16 Bs[2 * B_STAGE_H];

    const int tid  = threadIdx.x;
    const int lane = tid & 31;
    const int warp = tid >> 5;
    const int gid  = lane >> 2;
    const int tig  = lane & 3;

    const int mrow0 = blockIdx.y * 8;
    const int nb0   = blockIdx.x * 16;
    const int block_row = blockIdx.y * 128;
    const int block_col = blockIdx.x * 128;

    const int seg = block_col / D_DIM;
    __nv_bfloat16* Cout = (seg == 0) ? C0 : (seg == 1 ? C1 : C2);
    const int out_col_base = block_col - seg * D_DIM;

    const uint32_t As_u32 = (uint32_t)__cvta_generic_to_shared(As);
    const uint32_t Bs_u32 = (uint32_t)__cvta_generic_to_shared(Bs);

    float d[2][8][4];
    #pragma unroll
    for (int mi = 0; mi < 2; mi++)
        #pragma unroll
        for (int ni = 0; ni < 8; ni++)
            #pragma unroll
            for (int e = 0; e < 4; e++)
                d[mi][ni][e] = 0.0f;

    const int NITER = KB16 / 2;   // 24

    auto do_stage = [&](int kb0, int sbuf) {
        #pragma unroll
        for (int s = 0; s < 2; s++) {
            const int c  = tid + s * 256;
            const int mb = c >> 6, ch = c & 63;
            cp_async16(As_u32 + (sbuf * A_STAGE_H + c * 8) * 2,
                       Abf + ((((size_t)(mrow0 + mb)) * KB16 + kb0) << 8) + ch * 8);
        }
        #pragma unroll
        for (int s = 0; s < 2; s++) {
            const int c  = tid + s * 256;
            const int nb = c >> 5, ch = c & 31;
            cp_async16(Bs_u32 + (sbuf * B_STAGE_H + c * 8) * 2,
                       Wbf + ((((size_t)(nb0 + nb)) * KB16 + kb0) << 7) + ch * 8);
        }
        asm volatile("cp.async.commit_group;\n");
    };

    do_stage(0, 0);

    const int warp_mb = (warp & 3) * 2;
    const int warp_nb = (warp >> 2) * 8;

    int buf = 0;
    for (int it = 0; it < NITER; it++) {
        if (it + 1 < NITER) {
            do_stage((it + 1) * 2, buf ^ 1);
            asm volatile("cp.async.wait_group 1;\n");
        } else {
            asm volatile("cp.async.wait_group 0;\n");
        }
        __syncthreads();

        const uint4* As4 = (const uint4*)As + buf * (A_STAGE_H / 8);
        const uint2* Bs2 = (const uint2*)Bs + buf * (B_STAGE_H / 4);

        #pragma unroll
        for (int kb = 0; kb < 2; kb++) {
            uint4 afr[2];
            #pragma unroll
            for (int mi = 0; mi < 2; mi++)
                afr[mi] = As4[((warp_mb + mi) * 2 + kb) * 32 + lane];
            uint2 bfr[8];
            #pragma unroll
            for (int ni = 0; ni < 8; ni++)
                bfr[ni] = Bs2[((warp_nb + ni) * 2 + kb) * 32 + lane];
            #pragma unroll
            for (int mi = 0; mi < 2; mi++)
                #pragma unroll
                for (int ni = 0; ni < 8; ni++)
                    mma_bf16(d[mi][ni], afr[mi], bfr[ni]);
        }
        __syncthreads();
        buf ^= 1;
    }

    // epilogue: bias (fp32) -> bf16 store, segmented (row stride 768)
    #pragma unroll
    for (int mi = 0; mi < 2; mi++) {
        const int r0 = block_row + (warp & 3) * 32 + mi * 16 + gid;
        const int r1 = r0 + 8;
        #pragma unroll
        for (int ni = 0; ni < 8; ni++) {
            const int cg = block_col + (warp >> 2) * 64 + ni * 8 + 2 * tig;
            const int cl = out_col_base + (warp >> 2) * 64 + ni * 8 + 2 * tig;
            const float b0 = bias[cg], b1 = bias[cg + 1];
            *(uint32_t*)&Cout[(size_t)r0 * D_DIM + cl] =
                pack_bf2(d[mi][ni][0] + b0, d[mi][ni][1] + b1);
            *(uint32_t*)&Cout[(size_t)r1 * D_DIM + cl] =
                pack_bf2(d[mi][ni][2] + b0, d[mi][ni][3] + b1);
        }
    }
}

// ---------------------------------------------------------------------------
// MMA flash-attention (round 5 core, proven) — inputs now bf16 in global.
// bf16 -> fp32 conversion in staging is exact; bf16 ⊂ tf32 so no re-round
// is needed (0.125 scale is a power of two, also exact).
// ---------------------------------------------------------------------------
#define QSTRIDE 68
#define KSTRIDE 68
#define VSTRIDE 72
#define ATT_SMEM_FLOATS (T_DIM * (QSTRIDE + KSTRIDE + VSTRIDE))
#define ATT_SMEM_BYTES  (ATT_SMEM_FLOATS * 4)   // 212992

__device__ __forceinline__ void mma_tf32(float* d, uint32_t a0, uint32_t a1,
                                         uint32_t a2, uint32_t a3,
                                         uint32_t b0, uint32_t b1)
{
    asm volatile(
        "mma.sync.aligned.m16n8k8.row.col.f32.tf32.tf32.f32 "
        "{%0,%1,%2,%3}, {%4,%5,%6,%7}, {%8,%9}, {%0,%1,%2,%3};\n"
        : "+f"(d[0]), "+f"(d[1]), "+f"(d[2]), "+f"(d[3])
        : "r"(a0), "r"(a1), "r"(a2), "r"(a3), "r"(b0), "r"(b1));
}

__device__ __forceinline__ void bf8_to_f8(uint4 u, float* f, float scale) {
    const __nv_bfloat162* h = reinterpret_cast<const __nv_bfloat162*>(&u);
    #pragma unroll
    for (int i = 0; i < 4; i++) {
        float2 p = __bfloat1622float2(h[i]);
        f[2*i]   = p.x * scale;
        f[2*i+1] = p.y * scale;
    }
}

__global__ __launch_bounds__(512)
void flash_attn_kernel(const __nv_bfloat16* __restrict__ Q,
                       const __nv_bfloat16* __restrict__ K,
                       const __nv_bfloat16* __restrict__ V,
                       const int*   __restrict__ num_turns,
                       float*       __restrict__ CTX)
{
    const int b = blockIdx.x / NH_DIM;
    const int h = blockIdx.x % NH_DIM;

    extern __shared__ float sm[];
    float* Qs = sm;
    float* Ks = Qs + T_DIM * QSTRIDE;
    float* Vs = Ks + T_DIM * KSTRIDE;

    const size_t base = ((size_t)b * T_DIM * NH_DIM + h) * DH_DIM;
    const int tid = threadIdx.x;

    // stage: each iter handles 8 contiguous head-dims of one row
    for (int idx = tid; idx < T_DIM * (DH_DIM / 8); idx += 512) {
        const int t  = idx >> 3;
        const int c8 = (idx & 7) * 8;
        const size_t g = base + (size_t)t * D_DIM + c8;
        float qf[8], kf[8], vf[8];
        bf8_to_f8(*(const uint4*)&Q[g], qf, 0.125f);
        bf8_to_f8(*(const uint4*)&K[g], kf, 1.0f);
        bf8_to_f8(*(const uint4*)&V[g], vf, 1.0f);
        *(float4*)&Qs[t * QSTRIDE + c8]     = make_float4(qf[0], qf[1], qf[2], qf[3]);
        *(float4*)&Qs[t * QSTRIDE + c8 + 4] = make_float4(qf[4], qf[5], qf[6], qf[7]);
        *(float4*)&Ks[t * KSTRIDE + c8]     = make_float4(kf[0], kf[1], kf[2], kf[3]);
        *(float4*)&Ks[t * KSTRIDE + c8 + 4] = make_float4(kf[4], kf[5], kf[6], kf[7]);
        *(float4*)&Vs[t * VSTRIDE + c8]     = make_float4(vf[0], vf[1], vf[2], vf[3]);
        *(float4*)&Vs[t * VSTRIDE + c8 + 4] = make_float4(vf[4], vf[5], vf[6], vf[7]);
    }
    __syncthreads();

    const int warp = tid >> 5;
    const int lane = tid & 31;
    const int gid  = lane >> 2;
    const int tig  = lane & 3;

    const int q0 = warp * 16 + gid;
    const int q1 = q0 + 8;
    const int ntv  = num_turns[b];
    const int lim0 = min(q0, ntv);
    const int lim1 = min(q1, ntv);

    const int lim_max = min(warp * 16 + 15, ntv);
    const int nch = (lim_max + 63) >> 6;

    float octx[8][4];
    #pragma unroll
    for (int i = 0; i < 8; i++)
        #pragma unroll
        for (int j = 0; j < 4; j++) octx[i][j] = 0.0f;
    float m0 = -1e30f, m1 = -1e30f, l0 = 0.0f, l1 = 0.0f;

    for (int ch = 0; ch < nch; ch++) {
        const int kbase = ch * 64;

        float s[8][4];
        #pragma unroll
        for (int i = 0; i < 8; i++)
            #pragma unroll
            for (int j = 0; j < 4; j++) s[i][j] = 0.0f;

        #pragma unroll
        for (int kt = 0; kt < 8; kt++) {
            const int dh = kt * 8;
            const uint32_t a0 = __float_as_uint(Qs[q0 * QSTRIDE + dh + tig]);
            const uint32_t a1 = __float_as_uint(Qs[q1 * QSTRIDE + dh + tig]);
            const uint32_t a2 = __float_as_uint(Qs[q0 * QSTRIDE + dh + tig + 4]);
            const uint32_t a3 = __float_as_uint(Qs[q1 * QSTRIDE + dh + tig + 4]);
            #pragma unroll
            for (int nt8 = 0; nt8 < 8; nt8++) {
                const int krow = kbase + nt8 * 8 + gid;
                const uint32_t b0 = __float_as_uint(Ks[krow * KSTRIDE + dh + tig]);
                const uint32_t b1 = __float_as_uint(Ks[krow * KSTRIDE + dh + tig + 4]);
                mma_tf32(s[nt8], a0, a1, a2, a3, b0, b1);
            }
        }

        float mx0 = -1e30f, mx1 = -1e30f;
        #pragma unroll
        for (int i = 0; i < 8; i++) {
            const int kc = kbase + i * 8 + 2 * tig;
            s[i][0] = (kc     < lim0) ? s[i][0] : -1e30f;
            s[i][1] = (kc + 1 < lim0) ? s[i][1] : -1e30f;
            s[i][2] = (kc     < lim1) ? s[i][2] : -1e30f;
            s[i][3] = (kc + 1 < lim1) ? s[i][3] : -1e30f;
            mx0 = fmaxf(mx0, fmaxf(s[i][0], s[i][1]));
            mx1 = fmaxf(mx1, fmaxf(s[i][2], s[i][3]));
        }
        mx0 = fmaxf(mx0, __shfl_xor_sync(0xFFFFFFFFu, mx0, 1));
        mx0 = fmaxf(mx0, __shfl_xor_sync(0xFFFFFFFFu, mx0, 2));
        mx1 = fmaxf(mx1, __shfl_xor_sync(0xFFFFFFFFu, mx1, 1));
        mx1 = fmaxf(mx1, __shfl_xor_sync(0xFFFFFFFFu, mx1, 2));

        const float nm0 = fmaxf(m0, mx0);
        const float nm1 = fmaxf(m1, mx1);
        const float corr0 = __expf(m0 - nm0);
        const float corr1 = __expf(m1 - nm1);
        m0 = nm0; m1 = nm1;
        l0 *= corr0; l1 *= corr1;
        #pragma unroll
        for (int i = 0; i < 8; i++) {
            octx[i][0] *= corr0; octx[i][1] *= corr0;
            octx[i][2] *= corr1; octx[i][3] *= corr1;
        }

        #pragma unroll
        for (int i = 0; i < 8; i++) {
            const float p0 = __expf(s[i][0] - m0);
            const float p1 = __expf(s[i][1] - m0);
            const float p2 = __expf(s[i][2] - m1);
            const float p3 = __expf(s[i][3] - m1);
            l0 += p0 + p1;  l1 += p2 + p3;
            s[i][0] = p0; s[i][1] = p1; s[i][2] = p2; s[i][3] = p3;
        }

        const int qb = lane & ~3;
        const int src  = qb | (tig >> 1);
        const int src2 = src + 2;
        const bool par = (tig & 1) != 0;
        #pragma unroll
        for (int kt = 0; kt < 8; kt++) {
            const float v00 = __shfl_sync(0xFFFFFFFFu, s[kt][0], src);
            const float v01 = __shfl_sync(0xFFFFFFFFu, s[kt][1], src);
            const float v10 = __shfl_sync(0xFFFFFFFFu, s[kt][2], src);
            const float v11 = __shfl_sync(0xFFFFFFFFu, s[kt][3], src);
            const float w00 = __shfl_sync(0xFFFFFFFFu, s[kt][0], src2);
            const float w01 = __shfl_sync(0xFFFFFFFFu, s[kt][1], src2);
            const float w10 = __shfl_sync(0xFFFFFFFFu, s[kt][2], src2);
            const float w11 = __shfl_sync(0xFFFFFFFFu, s[kt][3], src2);
            uint32_t a0 = __float_as_uint(par ? v01 : v00);
            uint32_t a1 = __float_as_uint(par ? v11 : v10);
            uint32_t a2 = __float_as_uint(par ? w01 : w00);
            uint32_t a3 = __float_as_uint(par ? w11 : w10);
            // round P to tf32 (mma operand semantics)
            asm volatile("cvt.rna.tf32.f32 %0, %0;" : "+r"(a0));
            asm volatile("cvt.rna.tf32.f32 %0, %0;" : "+r"(a1));
            asm volatile("cvt.rna.tf32.f32 %0, %0;" : "+r"(a2));
            asm volatile("cvt.rna.tf32.f32 %0, %0;" : "+r"(a3));
            const int vr0 = kbase + kt * 8 + tig;
            #pragma unroll
            for (int ndh = 0; ndh < 8; ndh++) {
                const uint32_t b0 = __float_as_uint(Vs[vr0 * VSTRIDE + ndh * 8 + gid]);
                const uint32_t b1 = __float_as_uint(Vs[(vr0 + 4) * VSTRIDE + ndh * 8 + gid]);
                mma_tf32(octx[ndh], a0, a1, a2, a3, b0, b1);
            }
        }
    }

    l0 += __shfl_xor_sync(0xFFFFFFFFu, l0, 1);
    l0 += __shfl_xor_sync(0xFFFFFFFFu, l0, 2);
    l1 += __shfl_xor_sync(0xFFFFFFFFu, l1, 1);
    l1 += __shfl_xor_sync(0xFFFFFFFFu, l1, 2);
    const float inv0 = (lim0 > 0) ? 1.0f / l0 : 0.0f;
    const float inv1 = (lim1 > 0) ? 1.0f / l1 : 0.0f;

    float* o0 = &CTX[base + (size_t)q0 * D_DIM];
    float* o1 = &CTX[base + (size_t)q1 * D_DIM];
    #pragma unroll
    for (int ndh = 0; ndh < 8; ndh++) {
        const int c = ndh * 8 + 2 * tig;
        float2 r0 = make_float2(octx[ndh][0] * inv0, octx[ndh][1] * inv0);
        float2 r1 = make_float2(octx[ndh][2] * inv1, octx[ndh][3] * inv1);
        *(float2*)&o0[c] = r0;
        *(float2*)&o1[c] = r1;
    }
}

// ---------------------------------------------------------------------------
// Fused classifier + final gather.
// ---------------------------------------------------------------------------
__global__ __launch_bounds__(128)
void classifier_kernel(const float* __restrict__ H,
                       const float* __restrict__ CTX,
                       const float* __restrict__ Wc,
                       const float* __restrict__ bc,
                       const float* __restrict__ WoWc,
                       const float* __restrict__ boWc,
                       const int*   __restrict__ num_turns,
                       float* __restrict__ out_all,
                       float* __restrict__ out_final)
{
    __shared__ float Wtop[D_DIM * C_DIM];
    __shared__ float Wbot[D_DIM * C_DIM];

    for (int i = threadIdx.x; i < D_DIM * C_DIM; i += 128) {
        Wtop[i] = Wc[i];
        Wbot[i] = WoWc[i];
    }
    __syncthreads();

    const int row = blockIdx.x * 128 + threadIdx.x;
    const int t   = row & (T_DIM - 1);
    const int b   = row >> 8;
    const float* hrow = &H  [(size_t)row * D_DIM];
    const float* crow = &CTX[(size_t)row * D_DIM];

    float acc[C_DIM];
    #pragma unroll
    for (int c = 0; c < C_DIM; c++)
        acc[c] = bc[c] + ((t > 0) ? boWc[c] : 0.0f);

    for (int i = 0; i < D_DIM; i += 4) {
        float4 h4 = *(const float4*)&hrow[i];
        const float hv[4] = {h4.x, h4.y, h4.z, h4.w};
        #pragma unroll
        for (int e = 0; e < 4; e++)
            #pragma unroll
            for (int c = 0; c < C_DIM; c++)
                acc[c] += hv[e] * Wtop[(i + e) * C_DIM + c];
    }
    for (int i = 0; i < D_DIM; i += 4) {
        float4 c4 = *(const float4*)&crow[i];
        const float cv[4] = {c4.x, c4.y, c4.z, c4.w};
        #pragma unroll
        for (int e = 0; e < 4; e++)
            #pragma unroll
            for (int c = 0; c < C_DIM; c++)
                acc[c] += cv[e] * Wbot[(i + e) * C_DIM + c];
    }

    float* o = &out_all[(size_t)row * C_DIM];
    #pragma unroll
    for (int c = 0; c < C_DIM; c++) o[c] = acc[c];

    if (t == num_turns[b] - 1) {
        float* f = &out_final[(size_t)b * C_DIM];
        #pragma unroll
        for (int c = 0; c < C_DIM; c++) f[c] = acc[c];
    }
}

// ---------------------------------------------------------------------------
// Launch
// ---------------------------------------------------------------------------
extern "C" void kernel_launch(void* const* d_in, const int* in_sizes, int n_in,
                              void* d_out, int out_size)
{
    const float* H  = (const float*)d_in[0];
    const float* Wq = (const float*)d_in[1];
    const float* bq = (const float*)d_in[2];
    const float* Wk = (const float*)d_in[3];
    const float* bk = (const float*)d_in[4];
    const float* Wv = (const float*)d_in[5];
    const float* bv = (const float*)d_in[6];
    const float* Wo = (const float*)d_in[7];
    const float* bo = (const float*)d_in[8];
    const float* Wc = (const float*)d_in[9];
    const float* bc = (const float*)d_in[10];
    const int*   nt = (const int*)  d_in[11];

    float* out_all   = (float*)d_out;
    float* out_final = (float*)d_out + (size_t)B_DIM * T_DIM * C_DIM;

    float *CTXb, *bp, *WoWcb, *boWcb;
    __nv_bfloat16 *Qb, *Kb, *Vb, *Abf, *Wbf;
    cudaGetSymbolAddress((void**)&Qb,    g_Q);
    cudaGetSymbolAddress((void**)&Kb,    g_K);
    cudaGetSymbolAddress((void**)&Vb,    g_V);
    cudaGetSymbolAddress((void**)&CTXb,  g_CTX);
    cudaGetSymbolAddress((void**)&Abf,   g_Abf);
    cudaGetSymbolAddress((void**)&Wbf,   g_Wbf);
    cudaGetSymbolAddress((void**)&bp,    g_bpack);
    cudaGetSymbolAddress((void**)&WoWcb, g_WoWc);
    cudaGetSymbolAddress((void**)&boWcb, g_boWc);

    // 1) fused prep: fragment packs + WoWc fold (single launch)
    prep_kernel<<<PREP_BLOCKS, 256>>>(H, Wq, Wk, Wv, bq, bk, bv, Wo, Wc, bo,
                                      Abf, Wbf, bp, WoWcb, boWcb);

    // 2) fused QKV projection (bf16 tensor cores, bf16 outputs)
    {
        dim3 grid(NQKV / 128, M_ROWS / 128);   // (18, 128)
        bf16_gemm_kernel<<<grid, 256>>>(Abf, Wbf, bp, Qb, Kb, Vb);
    }

    // 3) MMA flash attention (bf16 inputs)
    cudaFuncSetAttribute(flash_attn_kernel,
                         cudaFuncAttributeMaxDynamicSharedMemorySize, ATT_SMEM_BYTES);
    flash_attn_kernel<<<B_DIM * NH_DIM, 512, ATT_SMEM_BYTES>>>(Qb, Kb, Vb, nt, CTXb);

    // 4) fused classifier + final gather
    classifier_kernel<<<M_ROWS / 128, 128>>>(H, CTXb, Wc, bc, WoWcb, boWcb,
                                             nt, out_all, out_final);
}

// round 9
// speedup vs baseline: 7.1827x; 1.1789x over previous
#include <cuda_runtime.h>
#include <cuda_bf16.h>
#include <math.h>
#include <stdint.h>

// Problem constants
#define B_DIM  64
#define T_DIM  256
#define D_DIM  768
#define NH_DIM 12
#define DH_DIM 64
#define C_DIM  7
#define M_ROWS (B_DIM * T_DIM)   // 16384
#define NQKV   (3 * D_DIM)       // 2304
#define KB16   (D_DIM / 16)      // 48
#define MB16   (M_ROWS / 16)     // 1024
#define NB8    (NQKV / 8)        // 288

// Prep-kernel block ranges
#define PA_BLOCKS  (MB16 * KB16 * 32 / 256)   // 6144
#define PW_BLOCKS  (NB8  * KB16 * 32 / 256)   // 1728
#define WC_BLOCKS  24
#define PREP_BLOCKS (PA_BLOCKS + PW_BLOCKS + WC_BLOCKS)

// ---------------------------------------------------------------------------
// Scratch (device globals; no runtime allocation allowed)
// ---------------------------------------------------------------------------
__device__ __nv_bfloat16 g_Q[(size_t)M_ROWS * D_DIM];
__device__ __nv_bfloat16 g_K[(size_t)M_ROWS * D_DIM];
__device__ __nv_bfloat16 g_V[(size_t)M_ROWS * D_DIM];
__device__ __nv_bfloat16 g_CTX[(size_t)M_ROWS * D_DIM];   // bf16 now
__device__ __nv_bfloat16 g_Abf[(size_t)MB16 * KB16 * 256];
__device__ __nv_bfloat16 g_Wbf[(size_t)NB8  * KB16 * 128];
__device__ float g_bpack[NQKV];
__device__ float g_WoWc[D_DIM * C_DIM];
__device__ float g_boWc[C_DIM];

// ---------------------------------------------------------------------------
__device__ __forceinline__ uint32_t pack_bf2(float lo, float hi) {
    __nv_bfloat162 t = __floats2bfloat162_rn(lo, hi);
    return *reinterpret_cast<uint32_t*>(&t);
}

// ---------------------------------------------------------------------------
// Fused prep: pack A fragments | pack W fragments + biases | WoWc fold.
// ---------------------------------------------------------------------------
__global__ __launch_bounds__(256)
void prep_kernel(const float* __restrict__ H,
                 const float* __restrict__ Wq, const float* __restrict__ Wk,
                 const float* __restrict__ Wv,
                 const float* __restrict__ bq, const float* __restrict__ bk,
                 const float* __restrict__ bv,
                 const float* __restrict__ Wo, const float* __restrict__ Wc,
                 const float* __restrict__ bo,
                 __nv_bfloat16* __restrict__ Abf,
                 __nv_bfloat16* __restrict__ Wbf,
                 float* __restrict__ bp,
                 float* __restrict__ WoWc, float* __restrict__ boWc)
{
    const int blk = blockIdx.x;

    if (blk < PA_BLOCKS) {
        const int idx  = blk * 256 + threadIdx.x;
        const int lane = idx & 31;
        const int kblk = (idx >> 5) % KB16;
        const int mblk = idx / (KB16 * 32);
        const int gid  = lane >> 2;
        const int tig  = lane & 3;
        const int m0 = mblk * 16 + gid;
        const int k0 = kblk * 16 + 2 * tig;

        float2 p00 = *(const float2*)&H[(size_t)m0 * D_DIM + k0];
        float2 p10 = *(const float2*)&H[(size_t)(m0 + 8) * D_DIM + k0];
        float2 p01 = *(const float2*)&H[(size_t)m0 * D_DIM + k0 + 8];
        float2 p11 = *(const float2*)&H[(size_t)(m0 + 8) * D_DIM + k0 + 8];

        uint4 out;
        out.x = pack_bf2(p00.x, p00.y);
        out.y = pack_bf2(p10.x, p10.y);
        out.z = pack_bf2(p01.x, p01.y);
        out.w = pack_bf2(p11.x, p11.y);
        *(uint4*)&Abf[(size_t)idx * 8] = out;

    } else if (blk < PA_BLOCKS + PW_BLOCKS) {
        const int idx  = (blk - PA_BLOCKS) * 256 + threadIdx.x;
        const int lane = idx & 31;
        const int kblk = (idx >> 5) % KB16;
        const int nblk = idx / (KB16 * 32);
        const int gid  = lane >> 2;
        const int tig  = lane & 3;
        const int n  = nblk * 8 + gid;
        const int k0 = kblk * 16 + 2 * tig;

        const float* W = (n < D_DIM) ? Wq : ((n < 2 * D_DIM) ? Wk : Wv);
        const int j = (n >= 2 * D_DIM) ? (n - 2 * D_DIM)
                     : ((n >= D_DIM) ? (n - D_DIM) : n);

        const float w0 = W[(size_t)k0 * D_DIM + j];
        const float w1 = W[(size_t)(k0 + 1) * D_DIM + j];
        const float w2 = W[(size_t)(k0 + 8) * D_DIM + j];
        const float w3 = W[(size_t)(k0 + 9) * D_DIM + j];

        uint2 out;
        out.x = pack_bf2(w0, w1);
        out.y = pack_bf2(w2, w3);
        *(uint2*)&Wbf[(size_t)idx * 4] = out;

        if (idx < NQKV) {
            float bv_;
            if (idx < D_DIM)            bv_ = bq[idx];
            else if (idx < 2 * D_DIM)   bv_ = bk[idx - D_DIM];
            else                        bv_ = bv[idx - 2 * D_DIM];
            bp[idx] = bv_;
        }

    } else {
        const int wblk   = blk - PA_BLOCKS - PW_BLOCKS;
        const int gwarp  = (wblk * 256 + threadIdx.x) >> 5;
        const int nwarps = (WC_BLOCKS * 256) >> 5;
        const int lane   = threadIdx.x & 31;

        for (int d = gwarp; d < D_DIM; d += nwarps) {
            float acc[C_DIM];
            #pragma unroll
            for (int c = 0; c < C_DIM; c++) acc[c] = 0.0f;
            for (int n = lane; n < D_DIM; n += 32) {
                const float w = Wo[(size_t)d * D_DIM + n];
                const float* wcr = &Wc[(size_t)(D_DIM + n) * C_DIM];
                #pragma unroll
                for (int c = 0; c < C_DIM; c++) acc[c] += w * wcr[c];
            }
            #pragma unroll
            for (int c = 0; c < C_DIM; c++) {
                acc[c] += __shfl_xor_sync(0xFFFFFFFFu, acc[c], 16);
                acc[c] += __shfl_xor_sync(0xFFFFFFFFu, acc[c], 8);
                acc[c] += __shfl_xor_sync(0xFFFFFFFFu, acc[c], 4);
                acc[c] += __shfl_xor_sync(0xFFFFFFFFu, acc[c], 2);
                acc[c] += __shfl_xor_sync(0xFFFFFFFFu, acc[c], 1);
            }
            if (lane == 0) {
                #pragma unroll
                for (int c = 0; c < C_DIM; c++) WoWc[d * C_DIM + c] = acc[c];
            }
        }

        const int g = wblk * 256 + threadIdx.x;
        if (g < C_DIM) {
            float a = 0.0f;
            for (int n = 0; n < D_DIM; n++)
                a += bo[n] * Wc[(size_t)(D_DIM + n) * C_DIM + g];
            boWc[g] = a;
        }
    }
}

// ---------------------------------------------------------------------------
// BF16 tensor-core GEMM on fragment-packed operands (proven).
// ---------------------------------------------------------------------------
#define A_STAGE_H 4096
#define B_STAGE_H 4096

__device__ __forceinline__ void cp_async16(uint32_t smem_addr, const void* gptr) {
    asm volatile("cp.async.cg.shared.global [%0], [%1], 16;\n"
                 :: "r"(smem_addr), "l"(gptr));
}

__device__ __forceinline__ void mma_bf16(float* d, uint4 a, uint2 b) {
    asm volatile(
        "mma.sync.aligned.m16n8k16.row.col.f32.bf16.bf16.f32 "
        "{%0,%1,%2,%3}, {%4,%5,%6,%7}, {%8,%9}, {%0,%1,%2,%3};\n"
        : "+f"(d[0]), "+f"(d[1]), "+f"(d[2]), "+f"(d[3])
        : "r"(a.x), "r"(a.y), "r"(a.z), "r"(a.w), "r"(b.x), "r"(b.y));
}

__global__ __launch_bounds__(256)
void bf16_gemm_kernel(const __nv_bfloat16* __restrict__ Abf,
                      const __nv_bfloat16* __restrict__ Wbf,
                      const float* __restrict__ bias,
                      __nv_bfloat16* __restrict__ C0,
                      __nv_bfloat16* __restrict__ C1,
                      __nv_bfloat16* __restrict__ C2)
{
    __shared__ __nv_bfloat16 As[2 * A_STAGE_H];
    __shared__ __nv_bfloat16 Bs[2 * B_STAGE_H];

    const int tid  = threadIdx.x;
    const int lane = tid & 31;
    const int warp = tid >> 5;
    const int gid  = lane >> 2;
    const int tig  = lane & 3;

    const int mrow0 = blockIdx.y * 8;
    const int nb0   = blockIdx.x * 16;
    const int block_row = blockIdx.y * 128;
    const int block_col = blockIdx.x * 128;

    const int seg = block_col / D_DIM;
    __nv_bfloat16* Cout = (seg == 0) ? C0 : (seg == 1 ? C1 : C2);
    const int out_col_base = block_col - seg * D_DIM;

    const uint32_t As_u32 = (uint32_t)__cvta_generic_to_shared(As);
    const uint32_t Bs_u32 = (uint32_t)__cvta_generic_to_shared(Bs);

    float d[2][8][4];
    #pragma unroll
    for (int mi = 0; mi < 2; mi++)
        #pragma unroll
        for (int ni = 0; ni < 8; ni++)
            #pragma unroll
            for (int e = 0; e < 4; e++)
                d[mi][ni][e] = 0.0f;

    const int NITER = KB16 / 2;

    auto do_stage = [&](int kb0, int sbuf) {
        #pragma unroll
        for (int s = 0; s < 2; s++) {
            const int c  = tid + s * 256;
            const int mb = c >> 6, ch = c & 63;
            cp_async16(As_u32 + (sbuf * A_STAGE_H + c * 8) * 2,
                       Abf + ((((size_t)(mrow0 + mb)) * KB16 + kb0) << 8) + ch * 8);
        }
        #pragma unroll
        for (int s = 0; s < 2; s++) {
            const int c  = tid + s * 256;
            const int nb = c >> 5, ch = c & 31;
            cp_async16(Bs_u32 + (sbuf * B_STAGE_H + c * 8) * 2,
                       Wbf + ((((size_t)(nb0 + nb)) * KB16 + kb0) << 7) + ch * 8);
        }
        asm volatile("cp.async.commit_group;\n");
    };

    do_stage(0, 0);

    const int warp_mb = (warp & 3) * 2;
    const int warp_nb = (warp >> 2) * 8;

    int buf = 0;
    for (int it = 0; it < NITER; it++) {
        if (it + 1 < NITER) {
            do_stage((it + 1) * 2, buf ^ 1);
            asm volatile("cp.async.wait_group 1;\n");
        } else {
            asm volatile("cp.async.wait_group 0;\n");
        }
        __syncthreads();

        const uint4* As4 = (const uint4*)As + buf * (A_STAGE_H / 8);
        const uint2* Bs2 = (const uint2*)Bs + buf * (B_STAGE_H / 4);

        #pragma unroll
        for (int kb = 0; kb < 2; kb++) {
            uint4 afr[2];
            #pragma unroll
            for (int mi = 0; mi < 2; mi++)
                afr[mi] = As4[((warp_mb + mi) * 2 + kb) * 32 + lane];
            uint2 bfr[8];
            #pragma unroll
            for (int ni = 0; ni < 8; ni++)
                bfr[ni] = Bs2[((warp_nb + ni) * 2 + kb) * 32 + lane];
            #pragma unroll
            for (int mi = 0; mi < 2; mi++)
                #pragma unroll
                for (int ni = 0; ni < 8; ni++)
                    mma_bf16(d[mi][ni], afr[mi], bfr[ni]);
        }
        __syncthreads();
        buf ^= 1;
    }

    #pragma unroll
    for (int mi = 0; mi < 2; mi++) {
        const int r0 = block_row + (warp & 3) * 32 + mi * 16 + gid;
        const int r1 = r0 + 8;
        #pragma unroll
        for (int ni = 0; ni < 8; ni++) {
            const int cg = block_col + (warp >> 2) * 64 + ni * 8 + 2 * tig;
            const int cl = out_col_base + (warp >> 2) * 64 + ni * 8 + 2 * tig;
            const float b0 = bias[cg], b1 = bias[cg + 1];
            *(uint32_t*)&Cout[(size_t)r0 * D_DIM + cl] =
                pack_bf2(d[mi][ni][0] + b0, d[mi][ni][1] + b1);
            *(uint32_t*)&Cout[(size_t)r1 * D_DIM + cl] =
                pack_bf2(d[mi][ni][2] + b0, d[mi][ni][3] + b1);
        }
    }
}

// ---------------------------------------------------------------------------
// MMA flash-attention (proven) — bf16 in, bf16 CTX out.
// ---------------------------------------------------------------------------
#define QSTRIDE 68
#define KSTRIDE 68
#define VSTRIDE 72
#define ATT_SMEM_FLOATS (T_DIM * (QSTRIDE + KSTRIDE + VSTRIDE))
#define ATT_SMEM_BYTES  (ATT_SMEM_FLOATS * 4)   // 212992

__device__ __forceinline__ void mma_tf32(float* d, uint32_t a0, uint32_t a1,
                                         uint32_t a2, uint32_t a3,
                                         uint32_t b0, uint32_t b1)
{
    asm volatile(
        "mma.sync.aligned.m16n8k8.row.col.f32.tf32.tf32.f32 "
        "{%0,%1,%2,%3}, {%4,%5,%6,%7}, {%8,%9}, {%0,%1,%2,%3};\n"
        : "+f"(d[0]), "+f"(d[1]), "+f"(d[2]), "+f"(d[3])
        : "r"(a0), "r"(a1), "r"(a2), "r"(a3), "r"(b0), "r"(b1));
}

__device__ __forceinline__ void bf8_to_f8(uint4 u, float* f, float scale) {
    const __nv_bfloat162* h = reinterpret_cast<const __nv_bfloat162*>(&u);
    #pragma unroll
    for (int i = 0; i < 4; i++) {
        float2 p = __bfloat1622float2(h[i]);
        f[2*i]   = p.x * scale;
        f[2*i+1] = p.y * scale;
    }
}

__global__ __launch_bounds__(512)
void flash_attn_kernel(const __nv_bfloat16* __restrict__ Q,
                       const __nv_bfloat16* __restrict__ K,
                       const __nv_bfloat16* __restrict__ V,
                       const int*   __restrict__ num_turns,
                       __nv_bfloat16* __restrict__ CTX)
{
    const int b = blockIdx.x / NH_DIM;
    const int h = blockIdx.x % NH_DIM;

    extern __shared__ float sm[];
    float* Qs = sm;
    float* Ks = Qs + T_DIM * QSTRIDE;
    float* Vs = Ks + T_DIM * KSTRIDE;

    const size_t base = ((size_t)b * T_DIM * NH_DIM + h) * DH_DIM;
    const int tid = threadIdx.x;

    for (int idx = tid; idx < T_DIM * (DH_DIM / 8); idx += 512) {
        const int t  = idx >> 3;
        const int c8 = (idx & 7) * 8;
        const size_t g = base + (size_t)t * D_DIM + c8;
        float qf[8], kf[8], vf[8];
        bf8_to_f8(*(const uint4*)&Q[g], qf, 0.125f);
        bf8_to_f8(*(const uint4*)&K[g], kf, 1.0f);
        bf8_to_f8(*(const uint4*)&V[g], vf, 1.0f);
        *(float4*)&Qs[t * QSTRIDE + c8]     = make_float4(qf[0], qf[1], qf[2], qf[3]);
        *(float4*)&Qs[t * QSTRIDE + c8 + 4] = make_float4(qf[4], qf[5], qf[6], qf[7]);
        *(float4*)&Ks[t * KSTRIDE + c8]     = make_float4(kf[0], kf[1], kf[2], kf[3]);
        *(float4*)&Ks[t * KSTRIDE + c8 + 4] = make_float4(kf[4], kf[5], kf[6], kf[7]);
        *(float4*)&Vs[t * VSTRIDE + c8]     = make_float4(vf[0], vf[1], vf[2], vf[3]);
        *(float4*)&Vs[t * VSTRIDE + c8 + 4] = make_float4(vf[4], vf[5], vf[6], vf[7]);
    }
    __syncthreads();

    const int warp = tid >> 5;
    const int lane = tid & 31;
    const int gid  = lane >> 2;
    const int tig  = lane & 3;

    const int q0 = warp * 16 + gid;
    const int q1 = q0 + 8;
    const int ntv  = num_turns[b];
    const int lim0 = min(q0, ntv);
    const int lim1 = min(q1, ntv);

    const int lim_max = min(warp * 16 + 15, ntv);
    const int nch = (lim_max + 63) >> 6;

    float octx[8][4];
    #pragma unroll
    for (int i = 0; i < 8; i++)
        #pragma unroll
        for (int j = 0; j < 4; j++) octx[i][j] = 0.0f;
    float m0 = -1e30f, m1 = -1e30f, l0 = 0.0f, l1 = 0.0f;

    for (int ch = 0; ch < nch; ch++) {
        const int kbase = ch * 64;

        float s[8][4];
        #pragma unroll
        for (int i = 0; i < 8; i++)
            #pragma unroll
            for (int j = 0; j < 4; j++) s[i][j] = 0.0f;

        #pragma unroll
        for (int kt = 0; kt < 8; kt++) {
            const int dh = kt * 8;
            const uint32_t a0 = __float_as_uint(Qs[q0 * QSTRIDE + dh + tig]);
            const uint32_t a1 = __float_as_uint(Qs[q1 * QSTRIDE + dh + tig]);
            const uint32_t a2 = __float_as_uint(Qs[q0 * QSTRIDE + dh + tig + 4]);
            const uint32_t a3 = __float_as_uint(Qs[q1 * QSTRIDE + dh + tig + 4]);
            #pragma unroll
            for (int nt8 = 0; nt8 < 8; nt8++) {
                const int krow = kbase + nt8 * 8 + gid;
                const uint32_t b0 = __float_as_uint(Ks[krow * KSTRIDE + dh + tig]);
                const uint32_t b1 = __float_as_uint(Ks[krow * KSTRIDE + dh + tig + 4]);
                mma_tf32(s[nt8], a0, a1, a2, a3, b0, b1);
            }
        }

        float mx0 = -1e30f, mx1 = -1e30f;
        #pragma unroll
        for (int i = 0; i < 8; i++) {
            const int kc = kbase + i * 8 + 2 * tig;
            s[i][0] = (kc     < lim0) ? s[i][0] : -1e30f;
            s[i][1] = (kc + 1 < lim0) ? s[i][1] : -1e30f;
            s[i][2] = (kc     < lim1) ? s[i][2] : -1e30f;
            s[i][3] = (kc + 1 < lim1) ? s[i][3] : -1e30f;
            mx0 = fmaxf(mx0, fmaxf(s[i][0], s[i][1]));
            mx1 = fmaxf(mx1, fmaxf(s[i][2], s[i][3]));
        }
        mx0 = fmaxf(mx0, __shfl_xor_sync(0xFFFFFFFFu, mx0, 1));
        mx0 = fmaxf(mx0, __shfl_xor_sync(0xFFFFFFFFu, mx0, 2));
        mx1 = fmaxf(mx1, __shfl_xor_sync(0xFFFFFFFFu, mx1, 1));
        mx1 = fmaxf(mx1, __shfl_xor_sync(0xFFFFFFFFu, mx1, 2));

        const float nm0 = fmaxf(m0, mx0);
        const float nm1 = fmaxf(m1, mx1);
        const float corr0 = __expf(m0 - nm0);
        const float corr1 = __expf(m1 - nm1);
        m0 = nm0; m1 = nm1;
        l0 *= corr0; l1 *= corr1;
        #pragma unroll
        for (int i = 0; i < 8; i++) {
            octx[i][0] *= corr0; octx[i][1] *= corr0;
            octx[i][2] *= corr1; octx[i][3] *= corr1;
        }

        #pragma unroll
        for (int i = 0; i < 8; i++) {
            const float p0 = __expf(s[i][0] - m0);
            const float p1 = __expf(s[i][1] - m0);
            const float p2 = __expf(s[i][2] - m1);
            const float p3 = __expf(s[i][3] - m1);
            l0 += p0 + p1;  l1 += p2 + p3;
            s[i][0] = p0; s[i][1] = p1; s[i][2] = p2; s[i][3] = p3;
        }

        const int qb = lane & ~3;
        const int src  = qb | (tig >> 1);
        const int src2 = src + 2;
        const bool par = (tig & 1) != 0;
        #pragma unroll
        for (int kt = 0; kt < 8; kt++) {
            const float v00 = __shfl_sync(0xFFFFFFFFu, s[kt][0], src);
            const float v01 = __shfl_sync(0xFFFFFFFFu, s[kt][1], src);
            const float v10 = __shfl_sync(0xFFFFFFFFu, s[kt][2], src);
            const float v11 = __shfl_sync(0xFFFFFFFFu, s[kt][3], src);
            const float w00 = __shfl_sync(0xFFFFFFFFu, s[kt][0], src2);
            const float w01 = __shfl_sync(0xFFFFFFFFu, s[kt][1], src2);
            const float w10 = __shfl_sync(0xFFFFFFFFu, s[kt][2], src2);
            const float w11 = __shfl_sync(0xFFFFFFFFu, s[kt][3], src2);
            uint32_t a0 = __float_as_uint(par ? v01 : v00);
            uint32_t a1 = __float_as_uint(par ? v11 : v10);
            uint32_t a2 = __float_as_uint(par ? w01 : w00);
            uint32_t a3 = __float_as_uint(par ? w11 : w10);
            asm volatile("cvt.rna.tf32.f32 %0, %0;" : "+r"(a0));
            asm volatile("cvt.rna.tf32.f32 %0, %0;" : "+r"(a1));
            asm volatile("cvt.rna.tf32.f32 %0, %0;" : "+r"(a2));
            asm volatile("cvt.rna.tf32.f32 %0, %0;" : "+r"(a3));
            const int vr0 = kbase + kt * 8 + tig;
            #pragma unroll
            for (int ndh = 0; ndh < 8; ndh++) {
                const uint32_t b0 = __float_as_uint(Vs[vr0 * VSTRIDE + ndh * 8 + gid]);
                const uint32_t b1 = __float_as_uint(Vs[(vr0 + 4) * VSTRIDE + ndh * 8 + gid]);
                mma_tf32(octx[ndh], a0, a1, a2, a3, b0, b1);
            }
        }
    }

    l0 += __shfl_xor_sync(0xFFFFFFFFu, l0, 1);
    l0 += __shfl_xor_sync(0xFFFFFFFFu, l0, 2);
    l1 += __shfl_xor_sync(0xFFFFFFFFu, l1, 1);
    l1 += __shfl_xor_sync(0xFFFFFFFFu, l1, 2);
    const float inv0 = (lim0 > 0) ? 1.0f / l0 : 0.0f;
    const float inv1 = (lim1 > 0) ? 1.0f / l1 : 0.0f;

    __nv_bfloat16* o0 = &CTX[base + (size_t)q0 * D_DIM];
    __nv_bfloat16* o1 = &CTX[base + (size_t)q1 * D_DIM];
    #pragma unroll
    for (int ndh = 0; ndh < 8; ndh++) {
        const int c = ndh * 8 + 2 * tig;
        *(uint32_t*)&o0[c] = pack_bf2(octx[ndh][0] * inv0, octx[ndh][1] * inv0);
        *(uint32_t*)&o1[c] = pack_bf2(octx[ndh][2] * inv1, octx[ndh][3] * inv1);
    }
}

// ---------------------------------------------------------------------------
// Warp-per-row classifier + final gather.
// Lane splits the 768-dim dots: 6 float4 of H, 3 uint4 (8 bf16) of CTX.
// 7-way shfl reduction; lane 0 writes logits (+ final row if t==nt[b]-1).
// ---------------------------------------------------------------------------
__global__ __launch_bounds__(512)
void classifier_kernel(const float* __restrict__ H,
                       const __nv_bfloat16* __restrict__ CTX,
                       const float* __restrict__ Wc,
                       const float* __restrict__ bc,
                       const float* __restrict__ WoWc,
                       const float* __restrict__ boWc,
                       const int*   __restrict__ num_turns,
                       float* __restrict__ out_all,
                       float* __restrict__ out_final)
{
    __shared__ float Wtop[D_DIM * C_DIM];
    __shared__ float Wbot[D_DIM * C_DIM];

    for (int i = threadIdx.x; i < D_DIM * C_DIM; i += 512) {
        Wtop[i] = Wc[i];
        Wbot[i] = WoWc[i];
    }
    __syncthreads();

    const int warp = threadIdx.x >> 5;
    const int lane = threadIdx.x & 31;
    const int row  = blockIdx.x * 16 + warp;    // 16 warps/block
    const int t = row & (T_DIM - 1);
    const int b = row >> 8;

    const float* hrow = &H[(size_t)row * D_DIM];
    const __nv_bfloat16* crow = &CTX[(size_t)row * D_DIM];

    float acc[C_DIM];
    #pragma unroll
    for (int c = 0; c < C_DIM; c++) acc[c] = 0.0f;

    // H term: 192 float4 per row; 6 per lane
    #pragma unroll
    for (int i = 0; i < 6; i++) {
        const int c4 = i * 32 + lane;           // float4 index
        float4 h4 = *(const float4*)&hrow[c4 * 4];
        const float hv[4] = {h4.x, h4.y, h4.z, h4.w};
        #pragma unroll
        for (int e = 0; e < 4; e++) {
            const float* w = &Wtop[(c4 * 4 + e) * C_DIM];
            #pragma unroll
            for (int c = 0; c < C_DIM; c++) acc[c] += hv[e] * w[c];
        }
    }
    // CTX term: 96 uint4 (8 bf16 each) per row; 3 per lane
    #pragma unroll
    for (int i = 0; i < 3; i++) {
        const int c8 = i * 32 + lane;           // uint4 index
        uint4 u = *(const uint4*)&crow[c8 * 8];
        const __nv_bfloat162* hh = reinterpret_cast<const __nv_bfloat162*>(&u);
        #pragma unroll
        for (int p = 0; p < 4; p++) {
            float2 cv = __bfloat1622float2(hh[p]);
            const float* w0 = &Wbot[(c8 * 8 + 2 * p) * C_DIM];
            #pragma unroll
            for (int c = 0; c < C_DIM; c++)
                acc[c] += cv.x * w0[c] + cv.y * w0[C_DIM + c];
        }
    }

    #pragma unroll
    for (int c = 0; c < C_DIM; c++) {
        acc[c] += __shfl_xor_sync(0xFFFFFFFFu, acc[c], 16);
        acc[c] += __shfl_xor_sync(0xFFFFFFFFu, acc[c], 8);
        acc[c] += __shfl_xor_sync(0xFFFFFFFFu, acc[c], 4);
        acc[c] += __shfl_xor_sync(0xFFFFFFFFu, acc[c], 2);
        acc[c] += __shfl_xor_sync(0xFFFFFFFFu, acc[c], 1);
    }

    if (lane < C_DIM) {
        const float v = acc[0] * 0.0f +  // (placeholder avoided below)
                        0.0f;
    }

    if (lane == 0) {
        float* o = &out_all[(size_t)row * C_DIM];
        const bool fin = (t == num_turns[b] - 1);
        float* f = &out_final[(size_t)b * C_DIM];
        #pragma unroll
        for (int c = 0; c < C_DIM; c++) {
            const float v = acc[c] + bc[c] + ((t > 0) ? boWc[c] : 0.0f);
            o[c] = v;
            if (fin) f[c] = v;
        }
    }
}

// ---------------------------------------------------------------------------
// Launch
// ---------------------------------------------------------------------------
extern "C" void kernel_launch(void* const* d_in, const int* in_sizes, int n_in,
                              void* d_out, int out_size)
{
    const float* H  = (const float*)d_in[0];
    const float* Wq = (const float*)d_in[1];
    const float* bq = (const float*)d_in[2];
    const float* Wk = (const float*)d_in[3];
    const float* bk = (const float*)d_in[4];
    const float* Wv = (const float*)d_in[5];
    const float* bv = (const float*)d_in[6];
    const float* Wo = (const float*)d_in[7];
    const float* bo = (const float*)d_in[8];
    const float* Wc = (const float*)d_in[9];
    const float* bc = (const float*)d_in[10];
    const int*   nt = (const int*)  d_in[11];

    float* out_all   = (float*)d_out;
    float* out_final = (float*)d_out + (size_t)B_DIM * T_DIM * C_DIM;

    float *bp, *WoWcb, *boWcb;
    __nv_bfloat16 *Qb, *Kb, *Vb, *CTXb, *Abf, *Wbf;
    cudaGetSymbolAddress((void**)&Qb,    g_Q);
    cudaGetSymbolAddress((void**)&Kb,    g_K);
    cudaGetSymbolAddress((void**)&Vb,    g_V);
    cudaGetSymbolAddress((void**)&CTXb,  g_CTX);
    cudaGetSymbolAddress((void**)&Abf,   g_Abf);
    cudaGetSymbolAddress((void**)&Wbf,   g_Wbf);
    cudaGetSymbolAddress((void**)&bp,    g_bpack);
    cudaGetSymbolAddress((void**)&WoWcb, g_WoWc);
    cudaGetSymbolAddress((void**)&boWcb, g_boWc);

    // 1) fused prep
    prep_kernel<<<PREP_BLOCKS, 256>>>(H, Wq, Wk, Wv, bq, bk, bv, Wo, Wc, bo,
                                      Abf, Wbf, bp, WoWcb, boWcb);

    // 2) fused QKV projection (bf16 tensor cores, bf16 outputs)
    {
        dim3 grid(NQKV / 128, M_ROWS / 128);
        bf16_gemm_kernel<<<grid, 256>>>(Abf, Wbf, bp, Qb, Kb, Vb);
    }

    // 3) MMA flash attention (bf16 in, bf16 CTX out)
    cudaFuncSetAttribute(flash_attn_kernel,
                         cudaFuncAttributeMaxDynamicSharedMemorySize, ATT_SMEM_BYTES);
    flash_attn_kernel<<<B_DIM * NH_DIM, 512, ATT_SMEM_BYTES>>>(Qb, Kb, Vb, nt, CTXb);

    // 4) warp-per-row classifier + final gather
    classifier_kernel<<<M_ROWS / 16, 512>>>(H, CTXb, Wc, bc, WoWcb, boWcb,
                                            nt, out_all, out_final);
}

// round 10
// speedup vs baseline: 7.8017x; 1.0862x over previous
#include <cuda_runtime.h>
#include <cuda_bf16.h>
#include <math.h>
#include <stdint.h>

// Problem constants
#define B_DIM  64
#define T_DIM  256
#define D_DIM  768
#define NH_DIM 12
#define DH_DIM 64
#define C_DIM  7
#define M_ROWS (B_DIM * T_DIM)   // 16384
#define NQKV   (3 * D_DIM)       // 2304
#define KB16   (D_DIM / 16)      // 48
#define MB16   (M_ROWS / 16)     // 1024
#define NB8    (NQKV / 8)        // 288

// Prep-kernel block ranges
#define PA_BLOCKS  (MB16 * KB16 * 32 / 256)   // 6144
#define PW_BLOCKS  (NB8  * KB16 * 32 / 256)   // 1728
#define WC_BLOCKS  24
#define PREP_BLOCKS (PA_BLOCKS + PW_BLOCKS + WC_BLOCKS)

// ---------------------------------------------------------------------------
// Scratch (device globals; no runtime allocation allowed)
// ---------------------------------------------------------------------------
__device__ __nv_bfloat16 g_Q[(size_t)M_ROWS * D_DIM];
__device__ __nv_bfloat16 g_K[(size_t)M_ROWS * D_DIM];
__device__ __nv_bfloat16 g_V[(size_t)M_ROWS * D_DIM];
__device__ __nv_bfloat16 g_CTX[(size_t)M_ROWS * D_DIM];
__device__ __nv_bfloat16 g_Abf[(size_t)MB16 * KB16 * 256];
__device__ __nv_bfloat16 g_Wbf[(size_t)NB8  * KB16 * 128];
__device__ float g_bpack[NQKV];
__device__ float g_WoWc[D_DIM * C_DIM];
__device__ float g_boWc[C_DIM];

// ---------------------------------------------------------------------------
__device__ __forceinline__ uint32_t pack_bf2(float lo, float hi) {
    __nv_bfloat162 t = __floats2bfloat162_rn(lo, hi);
    return *reinterpret_cast<uint32_t*>(&t);
}

// ---------------------------------------------------------------------------
// Fused prep: pack A fragments | pack W fragments + biases | WoWc fold.
// ---------------------------------------------------------------------------
__global__ __launch_bounds__(256)
void prep_kernel(const float* __restrict__ H,
                 const float* __restrict__ Wq, const float* __restrict__ Wk,
                 const float* __restrict__ Wv,
                 const float* __restrict__ bq, const float* __restrict__ bk,
                 const float* __restrict__ bv,
                 const float* __restrict__ Wo, const float* __restrict__ Wc,
                 const float* __restrict__ bo,
                 __nv_bfloat16* __restrict__ Abf,
                 __nv_bfloat16* __restrict__ Wbf,
                 float* __restrict__ bp,
                 float* __restrict__ WoWc, float* __restrict__ boWc)
{
    const int blk = blockIdx.x;

    if (blk < PA_BLOCKS) {
        const int idx  = blk * 256 + threadIdx.x;
        const int lane = idx & 31;
        const int kblk = (idx >> 5) % KB16;
        const int mblk = idx / (KB16 * 32);
        const int gid  = lane >> 2;
        const int tig  = lane & 3;
        const int m0 = mblk * 16 + gid;
        const int k0 = kblk * 16 + 2 * tig;

        float2 p00 = *(const float2*)&H[(size_t)m0 * D_DIM + k0];
        float2 p10 = *(const float2*)&H[(size_t)(m0 + 8) * D_DIM + k0];
        float2 p01 = *(const float2*)&H[(size_t)m0 * D_DIM + k0 + 8];
        float2 p11 = *(const float2*)&H[(size_t)(m0 + 8) * D_DIM + k0 + 8];

        uint4 out;
        out.x = pack_bf2(p00.x, p00.y);
        out.y = pack_bf2(p10.x, p10.y);
        out.z = pack_bf2(p01.x, p01.y);
        out.w = pack_bf2(p11.x, p11.y);
        *(uint4*)&Abf[(size_t)idx * 8] = out;

    } else if (blk < PA_BLOCKS + PW_BLOCKS) {
        const int idx  = (blk - PA_BLOCKS) * 256 + threadIdx.x;
        const int lane = idx & 31;
        const int kblk = (idx >> 5) % KB16;
        const int nblk = idx / (KB16 * 32);
        const int gid  = lane >> 2;
        const int tig  = lane & 3;
        const int n  = nblk * 8 + gid;
        const int k0 = kblk * 16 + 2 * tig;

        const float* W = (n < D_DIM) ? Wq : ((n < 2 * D_DIM) ? Wk : Wv);
        const int j = (n >= 2 * D_DIM) ? (n - 2 * D_DIM)
                     : ((n >= D_DIM) ? (n - D_DIM) : n);

        const float w0 = W[(size_t)k0 * D_DIM + j];
        const float w1 = W[(size_t)(k0 + 1) * D_DIM + j];
        const float w2 = W[(size_t)(k0 + 8) * D_DIM + j];
        const float w3 = W[(size_t)(k0 + 9) * D_DIM + j];

        uint2 out;
        out.x = pack_bf2(w0, w1);
        out.y = pack_bf2(w2, w3);
        *(uint2*)&Wbf[(size_t)idx * 4] = out;

        if (idx < NQKV) {
            float bv_;
            if (idx < D_DIM)            bv_ = bq[idx];
            else if (idx < 2 * D_DIM)   bv_ = bk[idx - D_DIM];
            else                        bv_ = bv[idx - 2 * D_DIM];
            bp[idx] = bv_;
        }

    } else {
        const int wblk   = blk - PA_BLOCKS - PW_BLOCKS;
        const int gwarp  = (wblk * 256 + threadIdx.x) >> 5;
        const int nwarps = (WC_BLOCKS * 256) >> 5;
        const int lane   = threadIdx.x & 31;

        for (int d = gwarp; d < D_DIM; d += nwarps) {
            float acc[C_DIM];
            #pragma unroll
            for (int c = 0; c < C_DIM; c++) acc[c] = 0.0f;
            for (int n = lane; n < D_DIM; n += 32) {
                const float w = Wo[(size_t)d * D_DIM + n];
                const float* wcr = &Wc[(size_t)(D_DIM + n) * C_DIM];
                #pragma unroll
                for (int c = 0; c < C_DIM; c++) acc[c] += w * wcr[c];
            }
            #pragma unroll
            for (int c = 0; c < C_DIM; c++) {
                acc[c] += __shfl_xor_sync(0xFFFFFFFFu, acc[c], 16);
                acc[c] += __shfl_xor_sync(0xFFFFFFFFu, acc[c], 8);
                acc[c] += __shfl_xor_sync(0xFFFFFFFFu, acc[c], 4);
                acc[c] += __shfl_xor_sync(0xFFFFFFFFu, acc[c], 2);
                acc[c] += __shfl_xor_sync(0xFFFFFFFFu, acc[c], 1);
            }
            if (lane == 0) {
                #pragma unroll
                for (int c = 0; c < C_DIM; c++) WoWc[d * C_DIM + c] = acc[c];
            }
        }

        const int g = wblk * 256 + threadIdx.x;
        if (g < C_DIM) {
            float a = 0.0f;
            for (int n = 0; n < D_DIM; n++)
                a += bo[n] * Wc[(size_t)(D_DIM + n) * C_DIM + g];
            boWc[g] = a;
        }
    }
}

// ---------------------------------------------------------------------------
// BF16 tensor-core GEMM, BK=64, 3-stage cp.async pipeline.
// Stage: 8 mb x 4 kb A-fragments (16 KB) + 16 nb x 4 kb B-fragments (16 KB).
// 96 KB dynamic smem, 2 CTAs/SM. Syncs: 12 (vs 48 at BK=32).
// ---------------------------------------------------------------------------
#define A_STAGE_H 8192   // halves per A stage
#define B_STAGE_H 8192   // halves per B stage
#define GEMM_SMEM_BYTES (3 * (A_STAGE_H + B_STAGE_H) * 2)  // 98304

__device__ __forceinline__ void cp_async16(uint32_t smem_addr, const void* gptr) {
    asm volatile("cp.async.cg.shared.global [%0], [%1], 16;\n"
                 :: "r"(smem_addr), "l"(gptr));
}

__device__ __forceinline__ void mma_bf16(float* d, uint4 a, uint2 b) {
    asm volatile(
        "mma.sync.aligned.m16n8k16.row.col.f32.bf16.bf16.f32 "
        "{%0,%1,%2,%3}, {%4,%5,%6,%7}, {%8,%9}, {%0,%1,%2,%3};\n"
        : "+f"(d[0]), "+f"(d[1]), "+f"(d[2]), "+f"(d[3])
        : "r"(a.x), "r"(a.y), "r"(a.z), "r"(a.w), "r"(b.x), "r"(b.y));
}

__global__ __launch_bounds__(256)
void bf16_gemm_kernel(const __nv_bfloat16* __restrict__ Abf,
                      const __nv_bfloat16* __restrict__ Wbf,
                      const float* __restrict__ bias,
                      __nv_bfloat16* __restrict__ C0,
                      __nv_bfloat16* __restrict__ C1,
                      __nv_bfloat16* __restrict__ C2)
{
    extern __shared__ __nv_bfloat16 smem[];
    __nv_bfloat16* As = smem;                       // [3][A_STAGE_H]
    __nv_bfloat16* Bs = smem + 3 * A_STAGE_H;       // [3][B_STAGE_H]

    const int tid  = threadIdx.x;
    const int lane = tid & 31;
    const int warp = tid >> 5;
    const int gid  = lane >> 2;
    const int tig  = lane & 3;

    const int mrow0 = blockIdx.y * 8;
    const int nb0   = blockIdx.x * 16;
    const int block_row = blockIdx.y * 128;
    const int block_col = blockIdx.x * 128;

    const int seg = block_col / D_DIM;
    __nv_bfloat16* Cout = (seg == 0) ? C0 : (seg == 1 ? C1 : C2);
    const int out_col_base = block_col - seg * D_DIM;

    const uint32_t As_u32 = (uint32_t)__cvta_generic_to_shared(As);
    const uint32_t Bs_u32 = As_u32 + 3 * A_STAGE_H * 2;

    float d[2][8][4];
    #pragma unroll
    for (int mi = 0; mi < 2; mi++)
        #pragma unroll
        for (int ni = 0; ni < 8; ni++)
            #pragma unroll
            for (int e = 0; e < 4; e++)
                d[mi][ni][e] = 0.0f;

    const int NITER = KB16 / 4;   // 12

    // stage copy: 1024 16B-chunks for A (c = mb*128 + kbl*32 + ch),
    //             1024 for B (c = nb*64 + kbl*16 + ch); 4 each per thread.
    auto do_stage = [&](int kb0, int s) {
        #pragma unroll
        for (int si = 0; si < 4; si++) {
            const int c   = tid + si * 256;
            const int mb  = c >> 7;
            const int kbl = (c >> 5) & 3;
            const int ch  = c & 31;
            cp_async16(As_u32 + (s * A_STAGE_H + c * 8) * 2,
                       Abf + (((size_t)(mrow0 + mb) * KB16 + kb0 + kbl) << 8) + ch * 8);
        }
        #pragma unroll
        for (int si = 0; si < 4; si++) {
            const int c   = tid + si * 256;
            const int nb  = c >> 6;
            const int kbl = (c >> 4) & 3;
            const int ch  = c & 15;
            cp_async16(Bs_u32 + (s * B_STAGE_H + c * 8) * 2,
                       Wbf + (((size_t)(nb0 + nb) * KB16 + kb0 + kbl) << 7) + ch * 8);
        }
        asm volatile("cp.async.commit_group;\n");
    };

    do_stage(0, 0);
    do_stage(4, 1);

    const int warp_mb = (warp & 3) * 2;
    const int warp_nb = (warp >> 2) * 8;

    for (int it = 0; it < NITER; it++) {
        if (it + 1 < NITER) {
            asm volatile("cp.async.wait_group 1;\n");
        } else {
            asm volatile("cp.async.wait_group 0;\n");
        }
        __syncthreads();

        if (it + 2 < NITER) do_stage((it + 2) * 4, (it + 2) % 3);

        const int s = it % 3;
        const uint4* As4 = (const uint4*)As + s * (A_STAGE_H / 8);
        const uint2* Bs2 = (const uint2*)Bs + s * (B_STAGE_H / 4);

        #pragma unroll
        for (int kb = 0; kb < 4; kb++) {
            uint4 afr[2];
            #pragma unroll
            for (int mi = 0; mi < 2; mi++)
                afr[mi] = As4[((warp_mb + mi) * 4 + kb) * 32 + lane];
            uint2 bfr[8];
            #pragma unroll
            for (int ni = 0; ni < 8; ni++)
                bfr[ni] = Bs2[((warp_nb + ni) * 4 + kb) * 32 + lane];
            #pragma unroll
            for (int mi = 0; mi < 2; mi++)
                #pragma unroll
                for (int ni = 0; ni < 8; ni++)
                    mma_bf16(d[mi][ni], afr[mi], bfr[ni]);
        }
    }

    #pragma unroll
    for (int mi = 0; mi < 2; mi++) {
        const int r0 = block_row + (warp & 3) * 32 + mi * 16 + gid;
        const int r1 = r0 + 8;
        #pragma unroll
        for (int ni = 0; ni < 8; ni++) {
            const int cg = block_col + (warp >> 2) * 64 + ni * 8 + 2 * tig;
            const int cl = out_col_base + (warp >> 2) * 64 + ni * 8 + 2 * tig;
            const float b0 = bias[cg], b1 = bias[cg + 1];
            *(uint32_t*)&Cout[(size_t)r0 * D_DIM + cl] =
                pack_bf2(d[mi][ni][0] + b0, d[mi][ni][1] + b1);
            *(uint32_t*)&Cout[(size_t)r1 * D_DIM + cl] =
                pack_bf2(d[mi][ni][2] + b0, d[mi][ni][3] + b1);
        }
    }
}

// ---------------------------------------------------------------------------
// MMA flash-attention (proven) — bf16 in, bf16 CTX out. Unchanged.
// ---------------------------------------------------------------------------
#define QSTRIDE 68
#define KSTRIDE 68
#define VSTRIDE 72
#define ATT_SMEM_FLOATS (T_DIM * (QSTRIDE + KSTRIDE + VSTRIDE))
#define ATT_SMEM_BYTES  (ATT_SMEM_FLOATS * 4)   // 212992

__device__ __forceinline__ void mma_tf32(float* d, uint32_t a0, uint32_t a1,
                                         uint32_t a2, uint32_t a3,
                                         uint32_t b0, uint32_t b1)
{
    asm volatile(
        "mma.sync.aligned.m16n8k8.row.col.f32.tf32.tf32.f32 "
        "{%0,%1,%2,%3}, {%4,%5,%6,%7}, {%8,%9}, {%0,%1,%2,%3};\n"
        : "+f"(d[0]), "+f"(d[1]), "+f"(d[2]), "+f"(d[3])
        : "r"(a0), "r"(a1), "r"(a2), "r"(a3), "r"(b0), "r"(b1));
}

__device__ __forceinline__ void bf8_to_f8(uint4 u, float* f, float scale) {
    const __nv_bfloat162* h = reinterpret_cast<const __nv_bfloat162*>(&u);
    #pragma unroll
    for (int i = 0; i < 4; i++) {
        float2 p = __bfloat1622float2(h[i]);
        f[2*i]   = p.x * scale;
        f[2*i+1] = p.y * scale;
    }
}

__global__ __launch_bounds__(512)
void flash_attn_kernel(const __nv_bfloat16* __restrict__ Q,
                       const __nv_bfloat16* __restrict__ K,
                       const __nv_bfloat16* __restrict__ V,
                       const int*   __restrict__ num_turns,
                       __nv_bfloat16* __restrict__ CTX)
{
    const int b = blockIdx.x / NH_DIM;
    const int h = blockIdx.x % NH_DIM;

    extern __shared__ float sm[];
    float* Qs = sm;
    float* Ks = Qs + T_DIM * QSTRIDE;
    float* Vs = Ks + T_DIM * KSTRIDE;

    const size_t base = ((size_t)b * T_DIM * NH_DIM + h) * DH_DIM;
    const int tid = threadIdx.x;

    for (int idx = tid; idx < T_DIM * (DH_DIM / 8); idx += 512) {
        const int t  = idx >> 3;
        const int c8 = (idx & 7) * 8;
        const size_t g = base + (size_t)t * D_DIM + c8;
        float qf[8], kf[8], vf[8];
        bf8_to_f8(*(const uint4*)&Q[g], qf, 0.125f);
        bf8_to_f8(*(const uint4*)&K[g], kf, 1.0f);
        bf8_to_f8(*(const uint4*)&V[g], vf, 1.0f);
        *(float4*)&Qs[t * QSTRIDE + c8]     = make_float4(qf[0], qf[1], qf[2], qf[3]);
        *(float4*)&Qs[t * QSTRIDE + c8 + 4] = make_float4(qf[4], qf[5], qf[6], qf[7]);
        *(float4*)&Ks[t * KSTRIDE + c8]     = make_float4(kf[0], kf[1], kf[2], kf[3]);
        *(float4*)&Ks[t * KSTRIDE + c8 + 4] = make_float4(kf[4], kf[5], kf[6], kf[7]);
        *(float4*)&Vs[t * VSTRIDE + c8]     = make_float4(vf[0], vf[1], vf[2], vf[3]);
        *(float4*)&Vs[t * VSTRIDE + c8 + 4] = make_float4(vf[4], vf[5], vf[6], vf[7]);
    }
    __syncthreads();

    const int warp = tid >> 5;
    const int lane = tid & 31;
    const int gid  = lane >> 2;
    const int tig  = lane & 3;

    const int q0 = warp * 16 + gid;
    const int q1 = q0 + 8;
    const int ntv  = num_turns[b];
    const int lim0 = min(q0, ntv);
    const int lim1 = min(q1, ntv);

    const int lim_max = min(warp * 16 + 15, ntv);
    const int nch = (lim_max + 63) >> 6;

    float octx[8][4];
    #pragma unroll
    for (int i = 0; i < 8; i++)
        #pragma unroll
        for (int j = 0; j < 4; j++) octx[i][j] = 0.0f;
    float m0 = -1e30f, m1 = -1e30f, l0 = 0.0f, l1 = 0.0f;

    for (int ch = 0; ch < nch; ch++) {
        const int kbase = ch * 64;

        float s[8][4];
        #pragma unroll
        for (int i = 0; i < 8; i++)
            #pragma unroll
            for (int j = 0; j < 4; j++) s[i][j] = 0.0f;

        #pragma unroll
        for (int kt = 0; kt < 8; kt++) {
            const int dh = kt * 8;
            const uint32_t a0 = __float_as_uint(Qs[q0 * QSTRIDE + dh + tig]);
            const uint32_t a1 = __float_as_uint(Qs[q1 * QSTRIDE + dh + tig]);
            const uint32_t a2 = __float_as_uint(Qs[q0 * QSTRIDE + dh + tig + 4]);
            const uint32_t a3 = __float_as_uint(Qs[q1 * QSTRIDE + dh + tig + 4]);
            #pragma unroll
            for (int nt8 = 0; nt8 < 8; nt8++) {
                const int krow = kbase + nt8 * 8 + gid;
                const uint32_t b0 = __float_as_uint(Ks[krow * KSTRIDE + dh + tig]);
                const uint32_t b1 = __float_as_uint(Ks[krow * KSTRIDE + dh + tig + 4]);
                mma_tf32(s[nt8], a0, a1, a2, a3, b0, b1);
            }
        }

        float mx0 = -1e30f, mx1 = -1e30f;
        #pragma unroll
        for (int i = 0; i < 8; i++) {
            const int kc = kbase + i * 8 + 2 * tig;
            s[i][0] = (kc     < lim0) ? s[i][0] : -1e30f;
            s[i][1] = (kc + 1 < lim0) ? s[i][1] : -1e30f;
            s[i][2] = (kc     < lim1) ? s[i][2] : -1e30f;
            s[i][3] = (kc + 1 < lim1) ? s[i][3] : -1e30f;
            mx0 = fmaxf(mx0, fmaxf(s[i][0], s[i][1]));
            mx1 = fmaxf(mx1, fmaxf(s[i][2], s[i][3]));
        }
        mx0 = fmaxf(mx0, __shfl_xor_sync(0xFFFFFFFFu, mx0, 1));
        mx0 = fmaxf(mx0, __shfl_xor_sync(0xFFFFFFFFu, mx0, 2));
        mx1 = fmaxf(mx1, __shfl_xor_sync(0xFFFFFFFFu, mx1, 1));
        mx1 = fmaxf(mx1, __shfl_xor_sync(0xFFFFFFFFu, mx1, 2));

        const float nm0 = fmaxf(m0, mx0);
        const float nm1 = fmaxf(m1, mx1);
        const float corr0 = __expf(m0 - nm0);
        const float corr1 = __expf(m1 - nm1);
        m0 = nm0; m1 = nm1;
        l0 *= corr0; l1 *= corr1;
        #pragma unroll
        for (int i = 0; i < 8; i++) {
            octx[i][0] *= corr0; octx[i][1] *= corr0;
            octx[i][2] *= corr1; octx[i][3] *= corr1;
        }

        #pragma unroll
        for (int i = 0; i < 8; i++) {
            const float p0 = __expf(s[i][0] - m0);
            const float p1 = __expf(s[i][1] - m0);
            const float p2 = __expf(s[i][2] - m1);
            const float p3 = __expf(s[i][3] - m1);
            l0 += p0 + p1;  l1 += p2 + p3;
            s[i][0] = p0; s[i][1] = p1; s[i][2] = p2; s[i][3] = p3;
        }

        const int qb = lane & ~3;
        const int src  = qb | (tig >> 1);
        const int src2 = src + 2;
        const bool par = (tig & 1) != 0;
        #pragma unroll
        for (int kt = 0; kt < 8; kt++) {
            const float v00 = __shfl_sync(0xFFFFFFFFu, s[kt][0], src);
            const float v01 = __shfl_sync(0xFFFFFFFFu, s[kt][1], src);
            const float v10 = __shfl_sync(0xFFFFFFFFu, s[kt][2], src);
            const float v11 = __shfl_sync(0xFFFFFFFFu, s[kt][3], src);
            const float w00 = __shfl_sync(0xFFFFFFFFu, s[kt][0], src2);
            const float w01 = __shfl_sync(0xFFFFFFFFu, s[kt][1], src2);
            const float w10 = __shfl_sync(0xFFFFFFFFu, s[kt][2], src2);
            const float w11 = __shfl_sync(0xFFFFFFFFu, s[kt][3], src2);
            uint32_t a0 = __float_as_uint(par ? v01 : v00);
            uint32_t a1 = __float_as_uint(par ? v11 : v10);
            uint32_t a2 = __float_as_uint(par ? w01 : w00);
            uint32_t a3 = __float_as_uint(par ? w11 : w10);
            asm volatile("cvt.rna.tf32.f32 %0, %0;" : "+r"(a0));
            asm volatile("cvt.rna.tf32.f32 %0, %0;" : "+r"(a1));
            asm volatile("cvt.rna.tf32.f32 %0, %0;" : "+r"(a2));
            asm volatile("cvt.rna.tf32.f32 %0, %0;" : "+r"(a3));
            const int vr0 = kbase + kt * 8 + tig;
            #pragma unroll
            for (int ndh = 0; ndh < 8; ndh++) {
                const uint32_t b0 = __float_as_uint(Vs[vr0 * VSTRIDE + ndh * 8 + gid]);
                const uint32_t b1 = __float_as_uint(Vs[(vr0 + 4) * VSTRIDE + ndh * 8 + gid]);
                mma_tf32(octx[ndh], a0, a1, a2, a3, b0, b1);
            }
        }
    }

    l0 += __shfl_xor_sync(0xFFFFFFFFu, l0, 1);
    l0 += __shfl_xor_sync(0xFFFFFFFFu, l0, 2);
    l1 += __shfl_xor_sync(0xFFFFFFFFu, l1, 1);
    l1 += __shfl_xor_sync(0xFFFFFFFFu, l1, 2);
    const float inv0 = (lim0 > 0) ? 1.0f / l0 : 0.0f;
    const float inv1 = (lim1 > 0) ? 1.0f / l1 : 0.0f;

    __nv_bfloat16* o0 = &CTX[base + (size_t)q0 * D_DIM];
    __nv_bfloat16* o1 = &CTX[base + (size_t)q1 * D_DIM];
    #pragma unroll
    for (int ndh = 0; ndh < 8; ndh++) {
        const int c = ndh * 8 + 2 * tig;
        *(uint32_t*)&o0[c] = pack_bf2(octx[ndh][0] * inv0, octx[ndh][1] * inv0);
        *(uint32_t*)&o1[c] = pack_bf2(octx[ndh][2] * inv1, octx[ndh][3] * inv1);
    }
}

// ---------------------------------------------------------------------------
// Classifier v3: warp per 4 rows, transposed conflict-free smem weights.
// Wtop_t/Wbot_t stored [C][772] so lane float4 loads are conflict-free;
// each weight float4 is reused across 4 rows.
// ---------------------------------------------------------------------------
#define WPAD 772

__global__ __launch_bounds__(512)
void classifier_kernel(const float* __restrict__ H,
                       const __nv_bfloat16* __restrict__ CTX,
                       const float* __restrict__ Wc,
                       const float* __restrict__ bc,
                       const float* __restrict__ WoWc,
                       const float* __restrict__ boWc,
                       const int*   __restrict__ num_turns,
                       float* __restrict__ out_all,
                       float* __restrict__ out_final)
{
    __shared__ float Wtop[C_DIM * WPAD];
    __shared__ float Wbot[C_DIM * WPAD];

    for (int i = threadIdx.x; i < D_DIM * C_DIM; i += 512) {
        const int dd = i / C_DIM, cc = i % C_DIM;
        Wtop[cc * WPAD + dd] = Wc[i];
        Wbot[cc * WPAD + dd] = WoWc[i];
    }
    __syncthreads();

    const int warp = threadIdx.x >> 5;
    const int lane = threadIdx.x & 31;
    const int row0 = (blockIdx.x * 16 + warp) * 4;   // 4 rows per warp

    float acc[4][C_DIM];
    #pragma unroll
    for (int r = 0; r < 4; r++)
        #pragma unroll
        for (int c = 0; c < C_DIM; c++) acc[r][c] = 0.0f;

    // H term: lane owns float4 chunks {i*32+lane}, reused across 4 rows
    #pragma unroll
    for (int i = 0; i < 6; i++) {
        const int off = (i * 32 + lane) * 4;
        float4 h4[4];
        #pragma unroll
        for (int r = 0; r < 4; r++)
            h4[r] = *(const float4*)&H[(size_t)(row0 + r) * D_DIM + off];
        #pragma unroll
        for (int c = 0; c < C_DIM; c++) {
            const float4 w = *(const float4*)&Wtop[c * WPAD + off];
            #pragma unroll
            for (int r = 0; r < 4; r++)
                acc[r][c] += h4[r].x * w.x + h4[r].y * w.y
                           + h4[r].z * w.z + h4[r].w * w.w;
        }
    }

    // CTX term: lane owns 8-bf16 chunks, reused across 4 rows
    #pragma unroll
    for (int i = 0; i < 3; i++) {
        const int off = (i * 32 + lane) * 8;
        float cf[4][8];
        #pragma unroll
        for (int r = 0; r < 4; r++) {
            uint4 u = *(const uint4*)&CTX[(size_t)(row0 + r) * D_DIM + off];
            const __nv_bfloat162* hh = reinterpret_cast<const __nv_bfloat162*>(&u);
            #pragma unroll
            for (int p = 0; p < 4; p++) {
                float2 cv = __bfloat1622float2(hh[p]);
                cf[r][2*p]   = cv.x;
                cf[r][2*p+1] = cv.y;
            }
        }
        #pragma unroll
        for (int c = 0; c < C_DIM; c++) {
            const float4 w0 = *(const float4*)&Wbot[c * WPAD + off];
            const float4 w1 = *(const float4*)&Wbot[c * WPAD + off + 4];
            #pragma unroll
            for (int r = 0; r < 4; r++)
                acc[r][c] += cf[r][0] * w0.x + cf[r][1] * w0.y
                           + cf[r][2] * w0.z + cf[r][3] * w0.w
                           + cf[r][4] * w1.x + cf[r][5] * w1.y
                           + cf[r][6] * w1.z + cf[r][7] * w1.w;
        }
    }

    // reduce across lanes
    #pragma unroll
    for (int r = 0; r < 4; r++)
        #pragma unroll
        for (int c = 0; c < C_DIM; c++) {
            acc[r][c] += __shfl_xor_sync(0xFFFFFFFFu, acc[r][c], 16);
            acc[r][c] += __shfl_xor_sync(0xFFFFFFFFu, acc[r][c], 8);
            acc[r][c] += __shfl_xor_sync(0xFFFFFFFFu, acc[r][c], 4);
            acc[r][c] += __shfl_xor_sync(0xFFFFFFFFu, acc[r][c], 2);
            acc[r][c] += __shfl_xor_sync(0xFFFFFFFFu, acc[r][c], 1);
        }

    if (lane == 0) {
        #pragma unroll
        for (int r = 0; r < 4; r++) {
            const int row = row0 + r;
            const int t = row & (T_DIM - 1);
            const int b = row >> 8;
            float* o = &out_all[(size_t)row * C_DIM];
            const bool fin = (t == num_turns[b] - 1);
            float* f = &out_final[(size_t)b * C_DIM];
            #pragma unroll
            for (int c = 0; c < C_DIM; c++) {
                const float v = acc[r][c] + bc[c] + ((t > 0) ? boWc[c] : 0.0f);
                o[c] = v;
                if (fin) f[c] = v;
            }
        }
    }
}

// ---------------------------------------------------------------------------
// Launch
// ---------------------------------------------------------------------------
extern "C" void kernel_launch(void* const* d_in, const int* in_sizes, int n_in,
                              void* d_out, int out_size)
{
    const float* H  = (const float*)d_in[0];
    const float* Wq = (const float*)d_in[1];
    const float* bq = (const float*)d_in[2];
    const float* Wk = (const float*)d_in[3];
    const float* bk = (const float*)d_in[4];
    const float* Wv = (const float*)d_in[5];
    const float* bv = (const float*)d_in[6];
    const float* Wo = (const float*)d_in[7];
    const float* bo = (const float*)d_in[8];
    const float* Wc = (const float*)d_in[9];
    const float* bc = (const float*)d_in[10];
    const int*   nt = (const int*)  d_in[11];

    float* out_all   = (float*)d_out;
    float* out_final = (float*)d_out + (size_t)B_DIM * T_DIM * C_DIM;

    float *bp, *WoWcb, *boWcb;
    __nv_bfloat16 *Qb, *Kb, *Vb, *CTXb, *Abf, *Wbf;
    cudaGetSymbolAddress((void**)&Qb,    g_Q);
    cudaGetSymbolAddress((void**)&Kb,    g_K);
    cudaGetSymbolAddress((void**)&Vb,    g_V);
    cudaGetSymbolAddress((void**)&CTXb,  g_CTX);
    cudaGetSymbolAddress((void**)&Abf,   g_Abf);
    cudaGetSymbolAddress((void**)&Wbf,   g_Wbf);
    cudaGetSymbolAddress((void**)&bp,    g_bpack);
    cudaGetSymbolAddress((void**)&WoWcb, g_WoWc);
    cudaGetSymbolAddress((void**)&boWcb, g_boWc);

    // 1) fused prep
    prep_kernel<<<PREP_BLOCKS, 256>>>(H, Wq, Wk, Wv, bq, bk, bv, Wo, Wc, bo,
                                      Abf, Wbf, bp, WoWcb, boWcb);

    // 2) fused QKV projection (bf16 tensor cores, 3-stage pipeline)
    cudaFuncSetAttribute(bf16_gemm_kernel,
                         cudaFuncAttributeMaxDynamicSharedMemorySize, GEMM_SMEM_BYTES);
    {
        dim3 grid(NQKV / 128, M_ROWS / 128);
        bf16_gemm_kernel<<<grid, 256, GEMM_SMEM_BYTES>>>(Abf, Wbf, bp, Qb, Kb, Vb);
    }

    // 3) MMA flash attention
    cudaFuncSetAttribute(flash_attn_kernel,
                         cudaFuncAttributeMaxDynamicSharedMemorySize, ATT_SMEM_BYTES);
    flash_attn_kernel<<<B_DIM * NH_DIM, 512, ATT_SMEM_BYTES>>>(Qb, Kb, Vb, nt, CTXb);

    // 4) classifier (4 rows/warp, conflict-free weights) + final gather
    classifier_kernel<<<M_ROWS / 64, 512>>>(H, CTXb, Wc, bc, WoWcb, boWcb,
                                            nt, out_all, out_final);
}